// round 2
// baseline (speedup 1.0000x reference)
#include <cuda_runtime.h>
#include <math.h>

#define NB 16
#define NC 512
#define NHW 1024
#define NHEADS 8
#define HD 64
#define NG 32
#define CPG 16   // channels per group

// ---- scratch (device globals: allocation-free per harness rules) ----
__device__ float g_xgn[(size_t)NB * NC * NHW];                 //  33.5 MB
__device__ float g_qkv[(size_t)NB * 3 * NC * NHW];             // 100.7 MB  [b][o][n]
__device__ float g_qkv2[(size_t)NB * NHEADS * 3 * HD * NHW];   // 100.7 MB  [bh][s][d2][n2] (scrambled layout)
__device__ float g_s[(size_t)NB * NHEADS * NHW * NHW];         // 512   MB  [bh][i][j]
__device__ float g_h[(size_t)NB * NC * NHW];                   //  33.5 MB  [b][c][n]

// ============================================================
// GroupNorm: one block per (b, g). 16 ch x 1024 = 16384 elems.
// ============================================================
__global__ void __launch_bounds__(256) gn_kernel(const float* __restrict__ x,
                                                 const float* __restrict__ w,
                                                 const float* __restrict__ bias)
{
    int b = blockIdx.x >> 5;
    int g = blockIdx.x & 31;
    const float* xp = x + ((size_t)b * NC + g * CPG) * NHW;

    float s = 0.f, s2 = 0.f;
    for (int i = threadIdx.x; i < CPG * NHW; i += 256) {
        float v = xp[i];
        s += v;
        s2 += v * v;
    }
    __shared__ float r0[8], r1[8];
    #pragma unroll
    for (int o = 16; o; o >>= 1) {
        s  += __shfl_xor_sync(~0u, s,  o);
        s2 += __shfl_xor_sync(~0u, s2, o);
    }
    int wid = threadIdx.x >> 5, lid = threadIdx.x & 31;
    if (lid == 0) { r0[wid] = s; r1[wid] = s2; }
    __syncthreads();
    if (threadIdx.x < 32) {
        s  = (lid < 8) ? r0[lid] : 0.f;
        s2 = (lid < 8) ? r1[lid] : 0.f;
        #pragma unroll
        for (int o = 4; o; o >>= 1) {
            s  += __shfl_xor_sync(~0u, s,  o);
            s2 += __shfl_xor_sync(~0u, s2, o);
        }
        if (lid == 0) { r0[0] = s; r1[0] = s2; }
    }
    __syncthreads();
    const float inv_n = 1.f / (CPG * NHW);
    float mean = r0[0] * inv_n;
    float var  = r1[0] * inv_n - mean * mean;
    float rinv = rsqrtf(var + 1e-5f);

    float* op = g_xgn + ((size_t)b * NC + g * CPG) * NHW;
    for (int i = threadIdx.x; i < CPG * NHW; i += 256) {
        int c = g * CPG + (i >> 10);
        op[i] = (xp[i] - mean) * rinv * w[c] + bias[c];
    }
}

// ============================================================
// GEMM NN:  C[b][m][n] = sum_k W[m][k] * X[b][k][n]
// MODE 0: qkv (W=qkv_w, X=g_xgn, C=g_qkv, M=1536)
// MODE 1: proj (W=proj_w, X=g_h, C=out, M=512, + bias + residual g_xgn)
// ============================================================
template <int MODE>
__global__ void __launch_bounds__(256) gemm_nn(const float* __restrict__ W,
                                               const float* __restrict__ pbias,
                                               float* __restrict__ outp)
{
    const int Kd = NC;
    const int M  = MODE ? NC : 3 * NC;
    const float* X = MODE ? g_h : g_xgn;
    float* Cout    = MODE ? outp : g_qkv;

    int b  = blockIdx.z;
    int m0 = blockIdx.y << 7;
    int n0 = blockIdx.x << 7;
    const float* Xb = X + (size_t)b * Kd * NHW;

    __shared__ float As[16][129];   // padded: transposed stores
    __shared__ float Bs[16][128];

    int t = threadIdx.x;
    int tx = t & 15, ty = t >> 4;

    float acc[8][8] = {};

    for (int k0 = 0; k0 < Kd; k0 += 16) {
        #pragma unroll
        for (int i = t; i < 128 * 16; i += 256) {
            int m = i >> 4, k = i & 15;
            As[k][m] = W[(size_t)(m0 + m) * Kd + k0 + k];
        }
        #pragma unroll
        for (int i = t; i < 16 * 128; i += 256) {
            int k = i >> 7, n = i & 127;
            Bs[k][n] = Xb[(size_t)(k0 + k) * NHW + n0 + n];
        }
        __syncthreads();
        #pragma unroll
        for (int k = 0; k < 16; k++) {
            float a[8];
            #pragma unroll
            for (int i = 0; i < 8; i++) a[i] = As[k][ty * 8 + i];
            float4 b0 = *reinterpret_cast<const float4*>(&Bs[k][tx * 8]);
            float4 b1 = *reinterpret_cast<const float4*>(&Bs[k][tx * 8 + 4]);
            float bb[8] = {b0.x, b0.y, b0.z, b0.w, b1.x, b1.y, b1.z, b1.w};
            #pragma unroll
            for (int i = 0; i < 8; i++)
                #pragma unroll
                for (int j = 0; j < 8; j++)
                    acc[i][j] = fmaf(a[i], bb[j], acc[i][j]);
        }
        __syncthreads();
    }

    #pragma unroll
    for (int i = 0; i < 8; i++) {
        int m = m0 + ty * 8 + i;
        float* crow = Cout + ((size_t)b * M + m) * NHW + n0 + tx * 8;
        if (MODE) {
            const float* xg = g_xgn + ((size_t)b * NC + m) * NHW + n0 + tx * 8;
            float pb = pbias[m];
            #pragma unroll
            for (int j = 0; j < 8; j++) crow[j] = acc[i][j] + pb + xg[j];
        } else {
            #pragma unroll
            for (int j = 0; j < 8; j++) crow[j] = acc[i][j];
        }
    }
}

// ============================================================
// Permute qkv -> scrambled attention layout (reference's
// transpose(0,2,3,1).reshape quirk).
// For slice (bh = b*8+r, s, d_lo): out[d2][n2 = d_lo*128+j]
//   = qkv[b][s*512 + (d2&7)*64 + r*8 + d_lo][ j*8 + (d2>>3) ]
// One block per (bh, s, d_lo): 128*3*8 = 3072 blocks.
// ============================================================
__global__ void __launch_bounds__(256) permute_kernel()
{
    int blk  = blockIdx.x;
    int d_lo = blk & 7;
    int s    = (blk >> 3) % 3;
    int bh   = blk / 24;
    int b = bh >> 3, r = bh & 7;

    __shared__ float sm[8][1024];
    const float* src = g_qkv + ((size_t)b * 3 * NC + s * NC + r * 8 + d_lo) * NHW;
    for (int i = threadIdx.x; i < 8 * 1024; i += 256) {
        int h = i >> 10, n = i & 1023;
        sm[h][n] = src[(size_t)h * HD * NHW + n];
    }
    __syncthreads();

    float* dst = g_qkv2 + (((size_t)bh * 3 + s) * HD) * NHW + (size_t)d_lo * 128;
    for (int i = threadIdx.x; i < 64 * 128; i += 256) {
        int d2 = i >> 7, j = i & 127;
        dst[(size_t)d2 * NHW + j] = sm[d2 & 7][j * 8 + (d2 >> 3)];
    }
}

// ============================================================
// S = scale * Q2^T K2  (per bh).  Q2T,K2T stored [d2][n2], TN GEMM.
// ============================================================
__global__ void __launch_bounds__(256) gemm_s_kernel()
{
    int bh = blockIdx.z;
    const float* Q  = g_qkv2 + ((size_t)bh * 3 + 0) * HD * NHW;
    const float* Kp = g_qkv2 + ((size_t)bh * 3 + 1) * HD * NHW;
    float* S = g_s + (size_t)bh * NHW * NHW;

    int m0 = blockIdx.y << 7;
    int n0 = blockIdx.x << 7;

    __shared__ float As[16][128];
    __shared__ float Bs[16][128];

    int t = threadIdx.x;
    int tx = t & 15, ty = t >> 4;

    float acc[8][8] = {};

    for (int k0 = 0; k0 < HD; k0 += 16) {
        #pragma unroll
        for (int i = t; i < 16 * 128; i += 256) {
            int k = i >> 7, m = i & 127;
            As[k][m] = Q [(size_t)(k0 + k) * NHW + m0 + m];
            Bs[k][m] = Kp[(size_t)(k0 + k) * NHW + n0 + m];
        }
        __syncthreads();
        #pragma unroll
        for (int k = 0; k < 16; k++) {
            float4 a0 = *reinterpret_cast<const float4*>(&As[k][ty * 8]);
            float4 a1 = *reinterpret_cast<const float4*>(&As[k][ty * 8 + 4]);
            float4 b0 = *reinterpret_cast<const float4*>(&Bs[k][tx * 8]);
            float4 b1 = *reinterpret_cast<const float4*>(&Bs[k][tx * 8 + 4]);
            float a[8]  = {a0.x, a0.y, a0.z, a0.w, a1.x, a1.y, a1.z, a1.w};
            float bb[8] = {b0.x, b0.y, b0.z, b0.w, b1.x, b1.y, b1.z, b1.w};
            #pragma unroll
            for (int i = 0; i < 8; i++)
                #pragma unroll
                for (int j = 0; j < 8; j++)
                    acc[i][j] = fmaf(a[i], bb[j], acc[i][j]);
        }
        __syncthreads();
    }

    const float scale = 0.125f;  // 1/sqrt(64)
    #pragma unroll
    for (int i = 0; i < 8; i++) {
        float* srow = S + (size_t)(m0 + ty * 8 + i) * NHW + n0 + tx * 8;
        #pragma unroll
        for (int j = 0; j < 8; j++) srow[j] = acc[i][j] * scale;
    }
}

// ============================================================
// Row softmax over g_s: one block (128 thr) per row of 1024.
// ============================================================
__global__ void __launch_bounds__(128) softmax_kernel()
{
    float* r = g_s + (size_t)blockIdx.x * NHW;
    int t = threadIdx.x;
    float v[8];
    float mx = -3.4e38f;
    #pragma unroll
    for (int i = 0; i < 8; i++) {
        v[i] = r[t + (i << 7)];
        mx = fmaxf(mx, v[i]);
    }
    __shared__ float redm[4], reds[4];
    #pragma unroll
    for (int o = 16; o; o >>= 1) mx = fmaxf(mx, __shfl_xor_sync(~0u, mx, o));
    int wid = t >> 5, lid = t & 31;
    if (lid == 0) redm[wid] = mx;
    __syncthreads();
    mx = fmaxf(fmaxf(redm[0], redm[1]), fmaxf(redm[2], redm[3]));

    float sum = 0.f;
    #pragma unroll
    for (int i = 0; i < 8; i++) {
        v[i] = __expf(v[i] - mx);
        sum += v[i];
    }
    #pragma unroll
    for (int o = 16; o; o >>= 1) sum += __shfl_xor_sync(~0u, sum, o);
    if (lid == 0) reds[wid] = sum;
    __syncthreads();
    sum = reds[0] + reds[1] + reds[2] + reds[3];
    float inv = 1.f / sum;
    #pragma unroll
    for (int i = 0; i < 8; i++) r[t + (i << 7)] = v[i] * inv;
}

// ============================================================
// O[d2][i] = sum_j V2T[d2][j] * P[i][j]   (per bh), NT GEMM.
// Output straight into g_h[b][r*64+d2][i] — proj-ready layout.
// ============================================================
__global__ void __launch_bounds__(256) gemm_o_kernel()
{
    int bh = blockIdx.z;
    int b = bh >> 3, r = bh & 7;
    const float* V = g_qkv2 + ((size_t)bh * 3 + 2) * HD * NHW;
    const float* P = g_s + (size_t)bh * NHW * NHW;
    float* O = g_h + ((size_t)b * NC + r * HD) * NHW;

    int n0 = blockIdx.x << 7;

    __shared__ float As[32][65];    // padded transposed stores
    __shared__ float Bs[32][129];

    int t = threadIdx.x;
    int tx = t & 15, ty = t >> 4;   // m = ty*4.., n = tx*8..

    float acc[4][8] = {};

    for (int k0 = 0; k0 < NHW; k0 += 32) {
        #pragma unroll
        for (int i = t; i < 64 * 32; i += 256) {
            int m = i >> 5, k = i & 31;
            As[k][m] = V[(size_t)m * NHW + k0 + k];
        }
        #pragma unroll
        for (int i = t; i < 128 * 32; i += 256) {
            int n = i >> 5, k = i & 31;
            Bs[k][n] = P[(size_t)(n0 + n) * NHW + k0 + k];
        }
        __syncthreads();
        #pragma unroll
        for (int k = 0; k < 32; k++) {
            float a[4], bb[8];
            #pragma unroll
            for (int i = 0; i < 4; i++) a[i] = As[k][ty * 4 + i];
            #pragma unroll
            for (int j = 0; j < 8; j++) bb[j] = Bs[k][tx * 8 + j];
            #pragma unroll
            for (int i = 0; i < 4; i++)
                #pragma unroll
                for (int j = 0; j < 8; j++)
                    acc[i][j] = fmaf(a[i], bb[j], acc[i][j]);
        }
        __syncthreads();
    }

    #pragma unroll
    for (int i = 0; i < 4; i++) {
        float* orow = O + (size_t)(ty * 4 + i) * NHW + n0 + tx * 8;
        #pragma unroll
        for (int j = 0; j < 8; j++) orow[j] = acc[i][j];
    }
}

// ============================================================
extern "C" void kernel_launch(void* const* d_in, const int* in_sizes, int n_in,
                              void* d_out, int out_size)
{
    const float* x      = (const float*)d_in[0];
    const float* gn_w   = (const float*)d_in[1];
    const float* gn_b   = (const float*)d_in[2];
    const float* qkv_w  = (const float*)d_in[3];
    const float* proj_w = (const float*)d_in[4];
    const float* proj_b = (const float*)d_in[5];
    float* out = (float*)d_out;

    gn_kernel<<<NB * NG, 256>>>(x, gn_w, gn_b);
    gemm_nn<0><<<dim3(8, 12, NB), 256>>>(qkv_w, nullptr, nullptr);
    permute_kernel<<<NB * NHEADS * 3 * 8, 256>>>();
    gemm_s_kernel<<<dim3(8, 8, NB * NHEADS), 256>>>();
    softmax_kernel<<<NB * NHEADS * NHW, 128>>>();
    gemm_o_kernel<<<dim3(8, 1, NB * NHEADS), 256>>>();
    gemm_nn<1><<<dim3(8, 4, NB), 256>>>(proj_w, proj_b, out);
}

// round 4
// speedup vs baseline: 3.0343x; 3.0343x over previous
#include <cuda_runtime.h>
#include <math.h>

#define NB 16
#define NC 512
#define NHW 1024
#define NHEADS 8
#define HD 64
#define NG 32
#define CPG 16

// ---- scratch ----
__device__ float g_xgn[(size_t)NB * NC * NHW];                 //  33.5 MB
__device__ float g_qkv[(size_t)NB * 3 * NC * NHW];             // 100.7 MB  [b][o][n]
__device__ float g_qkv2[(size_t)NB * NHEADS * 3 * HD * NHW];   // 100.7 MB  [bh][s][d2][n2]
__device__ float g_h[(size_t)NB * NC * NHW];                   //  33.5 MB  [b][c][n]

// ---- tf32 helpers ----
__device__ __forceinline__ unsigned f2tf(float f) {
    unsigned u;
    asm("cvt.rna.tf32.f32 %0, %1;" : "=r"(u) : "f"(f));
    return u;
}
__device__ __forceinline__ void mma_tf32(float* c, const unsigned* a, const unsigned* b) {
    asm volatile(
        "mma.sync.aligned.m16n8k8.row.col.f32.tf32.tf32.f32 "
        "{%0,%1,%2,%3}, {%4,%5,%6,%7}, {%8,%9}, {%0,%1,%2,%3};"
        : "+f"(c[0]), "+f"(c[1]), "+f"(c[2]), "+f"(c[3])
        : "r"(a[0]), "r"(a[1]), "r"(a[2]), "r"(a[3]), "r"(b[0]), "r"(b[1]));
}

// ============================================================
// GroupNorm
// ============================================================
__global__ void __launch_bounds__(256) gn_kernel(const float* __restrict__ x,
                                                 const float* __restrict__ w,
                                                 const float* __restrict__ bias)
{
    int b = blockIdx.x >> 5;
    int g = blockIdx.x & 31;
    const float* xp = x + ((size_t)b * NC + g * CPG) * NHW;

    float s = 0.f, s2 = 0.f;
    for (int i = threadIdx.x; i < CPG * NHW; i += 256) {
        float v = xp[i];
        s += v; s2 += v * v;
    }
    __shared__ float r0[8], r1[8];
    #pragma unroll
    for (int o = 16; o; o >>= 1) {
        s  += __shfl_xor_sync(~0u, s,  o);
        s2 += __shfl_xor_sync(~0u, s2, o);
    }
    int wid = threadIdx.x >> 5, lid = threadIdx.x & 31;
    if (lid == 0) { r0[wid] = s; r1[wid] = s2; }
    __syncthreads();
    if (threadIdx.x < 32) {
        s  = (lid < 8) ? r0[lid] : 0.f;
        s2 = (lid < 8) ? r1[lid] : 0.f;
        #pragma unroll
        for (int o = 4; o; o >>= 1) {
            s  += __shfl_xor_sync(~0u, s,  o);
            s2 += __shfl_xor_sync(~0u, s2, o);
        }
        if (lid == 0) { r0[0] = s; r1[0] = s2; }
    }
    __syncthreads();
    const float inv_n = 1.f / (CPG * NHW);
    float mean = r0[0] * inv_n;
    float var  = r1[0] * inv_n - mean * mean;
    float rinv = rsqrtf(var + 1e-5f);

    float* op = g_xgn + ((size_t)b * NC + g * CPG) * NHW;
    for (int i = threadIdx.x; i < CPG * NHW; i += 256) {
        int c = g * CPG + (i >> 10);
        op[i] = (xp[i] - mean) * rinv * w[c] + bias[c];
    }
}

// ============================================================
// tf32 tensor-core GEMM NN: C[b][m][n] = sum_k W[m][k] X[b][k][n]
// MODE 0: qkv; MODE 1: proj (+bias +residual g_xgn)
// CTA tile 128x128, BK=16, 8 warps in 2(m) x 4(n), warp tile 64x32.
// ============================================================
template <int MODE>
__global__ void __launch_bounds__(256) gemm_tc(const float* __restrict__ W,
                                               const float* __restrict__ pbias,
                                               float* __restrict__ outp)
{
    const int Kd = NC;
    const int M  = MODE ? NC : 3 * NC;
    const float* X = MODE ? g_h : g_xgn;
    float* Cout    = MODE ? outp : g_qkv;

    int b  = blockIdx.z;
    int m0 = blockIdx.y << 7;
    int n0 = blockIdx.x << 7;
    const float* Xb = X + (size_t)b * Kd * NHW;

    __shared__ unsigned As[16][132];
    __shared__ unsigned Bs[16][132];

    int t = threadIdx.x;
    int w = t >> 5, lane = t & 31;
    int gid = lane >> 2, tig = lane & 3;
    int mw = (w >> 2) * 64;   // warp m offset in tile
    int nw = (w & 3) * 32;    // warp n offset in tile

    float acc[4][4][4];
    #pragma unroll
    for (int i = 0; i < 4; i++)
        #pragma unroll
        for (int j = 0; j < 4; j++)
            #pragma unroll
            for (int c = 0; c < 4; c++) acc[i][j][c] = 0.f;

    for (int k0 = 0; k0 < Kd; k0 += 16) {
        // A: 128 rows x 16 k. 2 threads/row, 8 consecutive k each (2xfloat4).
        {
            int m  = t >> 1;
            int kq = (t & 1) * 8;
            const float4* src = reinterpret_cast<const float4*>(&W[(size_t)(m0 + m) * Kd + k0 + kq]);
            float4 v0 = src[0], v1 = src[1];
            As[kq + 0][m] = f2tf(v0.x); As[kq + 1][m] = f2tf(v0.y);
            As[kq + 2][m] = f2tf(v0.z); As[kq + 3][m] = f2tf(v0.w);
            As[kq + 4][m] = f2tf(v1.x); As[kq + 5][m] = f2tf(v1.y);
            As[kq + 6][m] = f2tf(v1.z); As[kq + 7][m] = f2tf(v1.w);
        }
        // B: 16 k x 128 n. 16 threads/row, 8 consecutive n each.
        {
            int k  = t >> 4;
            int nq = (t & 15) * 8;
            const float4* src = reinterpret_cast<const float4*>(&Xb[(size_t)(k0 + k) * NHW + n0 + nq]);
            float4 v0 = src[0], v1 = src[1];
            Bs[k][nq + 0] = f2tf(v0.x); Bs[k][nq + 1] = f2tf(v0.y);
            Bs[k][nq + 2] = f2tf(v0.z); Bs[k][nq + 3] = f2tf(v0.w);
            Bs[k][nq + 4] = f2tf(v1.x); Bs[k][nq + 5] = f2tf(v1.y);
            Bs[k][nq + 6] = f2tf(v1.z); Bs[k][nq + 7] = f2tf(v1.w);
        }
        __syncthreads();

        #pragma unroll
        for (int ks = 0; ks < 16; ks += 8) {
            unsigned a[4][4], bb[4][2];
            #pragma unroll
            for (int mf = 0; mf < 4; mf++) {
                int mi = mw + mf * 16 + gid;
                a[mf][0] = As[ks + tig][mi];
                a[mf][1] = As[ks + tig][mi + 8];
                a[mf][2] = As[ks + tig + 4][mi];
                a[mf][3] = As[ks + tig + 4][mi + 8];
            }
            #pragma unroll
            for (int nf = 0; nf < 4; nf++) {
                int ni = nw + nf * 8 + gid;
                bb[nf][0] = Bs[ks + tig][ni];
                bb[nf][1] = Bs[ks + tig + 4][ni];
            }
            #pragma unroll
            for (int mf = 0; mf < 4; mf++)
                #pragma unroll
                for (int nf = 0; nf < 4; nf++)
                    mma_tf32(acc[mf][nf], a[mf], bb[nf]);
        }
        __syncthreads();
    }

    // epilogue
    #pragma unroll
    for (int mf = 0; mf < 4; mf++) {
        int gm = m0 + mw + mf * 16 + gid;
        #pragma unroll
        for (int nf = 0; nf < 4; nf++) {
            int gn = n0 + nw + nf * 8 + 2 * tig;
            float2 v01 = make_float2(acc[mf][nf][0], acc[mf][nf][1]);
            float2 v23 = make_float2(acc[mf][nf][2], acc[mf][nf][3]);
            if (MODE) {
                float pb0 = pbias[gm], pb1 = pbias[gm + 8];
                const float* xg0 = &g_xgn[((size_t)b * NC + gm) * NHW + gn];
                const float* xg1 = &g_xgn[((size_t)b * NC + gm + 8) * NHW + gn];
                v01.x += pb0 + xg0[0]; v01.y += pb0 + xg0[1];
                v23.x += pb1 + xg1[0]; v23.y += pb1 + xg1[1];
            }
            *reinterpret_cast<float2*>(&Cout[((size_t)b * M + gm) * NHW + gn]) = v01;
            *reinterpret_cast<float2*>(&Cout[((size_t)b * M + gm + 8) * NHW + gn]) = v23;
        }
    }
}

// ============================================================
// Permute qkv -> scrambled attention layout (reference reshape quirk)
// ============================================================
__global__ void __launch_bounds__(256) permute_kernel()
{
    int blk  = blockIdx.x;
    int d_lo = blk & 7;
    int s    = (blk >> 3) % 3;
    int bh   = blk / 24;
    int b = bh >> 3, r = bh & 7;

    __shared__ float sm[8][1024];
    const float* src = g_qkv + ((size_t)b * 3 * NC + s * NC + r * 8 + d_lo) * NHW;
    for (int i = threadIdx.x; i < 8 * 1024; i += 256) {
        int h = i >> 10, n = i & 1023;
        sm[h][n] = src[(size_t)h * HD * NHW + n];
    }
    __syncthreads();

    float* dst = g_qkv2 + (((size_t)bh * 3 + s) * HD) * NHW + (size_t)d_lo * 128;
    for (int i = threadIdx.x; i < 64 * 128; i += 256) {
        int d2 = i >> 7, j = i & 127;
        dst[(size_t)d2 * NHW + j] = sm[d2 & 7][j * 8 + (d2 >> 3)];
    }
}

// ============================================================
// Fused flash attention (tf32 mma).
// CTA = (bh, qtile of 128 rows). 8 warps; warp owns 16 query rows.
// Q,K,V tiles [d][n] in smem (tf32 bits); P routed through smem.
// ============================================================
#define FPAD 132
#define Q_OFF 0
#define K_OFF (64 * FPAD)
#define V_OFF (2 * 64 * FPAD)
#define P_OFF (3 * 64 * FPAD)
#define FLASH_SMEM ((3 * 64 * FPAD + 128 * FPAD) * 4)

__global__ void __launch_bounds__(256, 1) flash_kernel()
{
    extern __shared__ unsigned sm[];
    unsigned* qs = sm + Q_OFF;
    unsigned* ks = sm + K_OFF;
    unsigned* vs = sm + V_OFF;
    unsigned* ps = sm + P_OFF;

    int bh    = blockIdx.x >> 3;
    int qtile = blockIdx.x & 7;
    int b = bh >> 3, r = bh & 7;

    const float* Q = g_qkv2 + ((size_t)bh * 3 + 0) * HD * NHW;
    const float* K = g_qkv2 + ((size_t)bh * 3 + 1) * HD * NHW;
    const float* V = g_qkv2 + ((size_t)bh * 3 + 2) * HD * NHW;

    int t = threadIdx.x;
    int w = t >> 5, lane = t & 31;
    int gid = lane >> 2, tig = lane & 3;
    int i0w = w * 16;            // warp's row offset in q-tile
    int i_glob = qtile * 128;

    // load Q tile [64][128] (float4 gmem reads, cvt to tf32)
    for (int idx = t; idx < 64 * 32; idx += 256) {
        int d = idx >> 5, ii = (idx & 31) * 4;
        float4 v = *reinterpret_cast<const float4*>(&Q[(size_t)d * NHW + i_glob + ii]);
        qs[d * FPAD + ii + 0] = f2tf(v.x); qs[d * FPAD + ii + 1] = f2tf(v.y);
        qs[d * FPAD + ii + 2] = f2tf(v.z); qs[d * FPAD + ii + 3] = f2tf(v.w);
    }

    float acc_o[8][4];
    #pragma unroll
    for (int i = 0; i < 8; i++)
        #pragma unroll
        for (int c = 0; c < 4; c++) acc_o[i][c] = 0.f;
    float row_m0 = -1e30f, row_m1 = -1e30f;
    float row_l0 = 0.f, row_l1 = 0.f;

    const float scale = 0.125f;

    for (int kt = 0; kt < 8; kt++) {
        __syncthreads();   // protect K/V smem from previous iteration readers
        int j0 = kt * 128;
        for (int idx = t; idx < 64 * 32; idx += 256) {
            int d = idx >> 5, jj = (idx & 31) * 4;
            float4 kv = *reinterpret_cast<const float4*>(&K[(size_t)d * NHW + j0 + jj]);
            ks[d * FPAD + jj + 0] = f2tf(kv.x); ks[d * FPAD + jj + 1] = f2tf(kv.y);
            ks[d * FPAD + jj + 2] = f2tf(kv.z); ks[d * FPAD + jj + 3] = f2tf(kv.w);
            float4 vv = *reinterpret_cast<const float4*>(&V[(size_t)d * NHW + j0 + jj]);
            vs[d * FPAD + jj + 0] = f2tf(vv.x); vs[d * FPAD + jj + 1] = f2tf(vv.y);
            vs[d * FPAD + jj + 2] = f2tf(vv.z); vs[d * FPAD + jj + 3] = f2tf(vv.w);
        }
        __syncthreads();

        // ---- S = Q^T K for this warp's 16 rows x 128 cols ----
        float acc_s[16][4];
        #pragma unroll
        for (int i = 0; i < 16; i++)
            #pragma unroll
            for (int c = 0; c < 4; c++) acc_s[i][c] = 0.f;

        #pragma unroll
        for (int ksid = 0; ksid < 8; ksid++) {
            int d = ksid * 8;
            unsigned a[4];
            a[0] = qs[(d + tig) * FPAD + i0w + gid];
            a[1] = qs[(d + tig) * FPAD + i0w + gid + 8];
            a[2] = qs[(d + tig + 4) * FPAD + i0w + gid];
            a[3] = qs[(d + tig + 4) * FPAD + i0w + gid + 8];
            #pragma unroll
            for (int nf = 0; nf < 16; nf++) {
                unsigned bb[2];
                bb[0] = ks[(d + tig) * FPAD + nf * 8 + gid];
                bb[1] = ks[(d + tig + 4) * FPAD + nf * 8 + gid];
                mma_tf32(acc_s[nf], a, bb);
            }
        }

        // ---- online softmax (rows gid and gid+8 of this warp) ----
        float tmax0 = -1e30f, tmax1 = -1e30f;
        #pragma unroll
        for (int nf = 0; nf < 16; nf++) {
            tmax0 = fmaxf(tmax0, fmaxf(acc_s[nf][0], acc_s[nf][1]));
            tmax1 = fmaxf(tmax1, fmaxf(acc_s[nf][2], acc_s[nf][3]));
        }
        tmax0 = fmaxf(tmax0, __shfl_xor_sync(~0u, tmax0, 1));
        tmax0 = fmaxf(tmax0, __shfl_xor_sync(~0u, tmax0, 2));
        tmax1 = fmaxf(tmax1, __shfl_xor_sync(~0u, tmax1, 1));
        tmax1 = fmaxf(tmax1, __shfl_xor_sync(~0u, tmax1, 2));

        float nm0 = fmaxf(row_m0, tmax0 * scale);
        float nm1 = fmaxf(row_m1, tmax1 * scale);
        float corr0 = __expf(row_m0 - nm0);
        float corr1 = __expf(row_m1 - nm1);

        float sum0 = 0.f, sum1 = 0.f;
        #pragma unroll
        for (int nf = 0; nf < 16; nf++) {
            float p0 = __expf(acc_s[nf][0] * scale - nm0);
            float p1 = __expf(acc_s[nf][1] * scale - nm0);
            float p2 = __expf(acc_s[nf][2] * scale - nm1);
            float p3 = __expf(acc_s[nf][3] * scale - nm1);
            sum0 += p0 + p1;
            sum1 += p2 + p3;
            int jc = nf * 8 + 2 * tig;
            uint2 w01 = make_uint2(f2tf(p0), f2tf(p1));
            uint2 w23 = make_uint2(f2tf(p2), f2tf(p3));
            *reinterpret_cast<uint2*>(&ps[(i0w + gid) * FPAD + jc])     = w01;
            *reinterpret_cast<uint2*>(&ps[(i0w + gid + 8) * FPAD + jc]) = w23;
        }
        sum0 += __shfl_xor_sync(~0u, sum0, 1);
        sum0 += __shfl_xor_sync(~0u, sum0, 2);
        sum1 += __shfl_xor_sync(~0u, sum1, 1);
        sum1 += __shfl_xor_sync(~0u, sum1, 2);

        row_l0 = row_l0 * corr0 + sum0;
        row_l1 = row_l1 * corr1 + sum1;
        row_m0 = nm0; row_m1 = nm1;

        #pragma unroll
        for (int nf2 = 0; nf2 < 8; nf2++) {
            acc_o[nf2][0] *= corr0; acc_o[nf2][1] *= corr0;
            acc_o[nf2][2] *= corr1; acc_o[nf2][3] *= corr1;
        }
        __syncwarp();   // warp-private P rows: order STS before LDS

        // ---- O += P V^T : warp rows x 64 d-cols, k = j (128) ----
        #pragma unroll
        for (int js = 0; js < 16; js++) {
            int j = js * 8;
            unsigned a[4];
            a[0] = ps[(i0w + gid) * FPAD + j + tig];
            a[1] = ps[(i0w + gid + 8) * FPAD + j + tig];
            a[2] = ps[(i0w + gid) * FPAD + j + tig + 4];
            a[3] = ps[(i0w + gid + 8) * FPAD + j + tig + 4];
            #pragma unroll
            for (int nf2 = 0; nf2 < 8; nf2++) {
                unsigned bb[2];
                bb[0] = vs[(nf2 * 8 + gid) * FPAD + j + tig];
                bb[1] = vs[(nf2 * 8 + gid) * FPAD + j + tig + 4];
                mma_tf32(acc_o[nf2], a, bb);
            }
        }
    }

    // ---- epilogue: O /= l, write to g_h[b][r*64+d][i] ----
    float inv0 = 1.f / row_l0, inv1 = 1.f / row_l1;
    float* O = g_h + ((size_t)b * NC + r * HD) * NHW;
    int i0 = i_glob + i0w + gid;
    #pragma unroll
    for (int nf2 = 0; nf2 < 8; nf2++) {
        int d0 = nf2 * 8 + 2 * tig;
        O[(size_t)d0 * NHW + i0]           = acc_o[nf2][0] * inv0;
        O[(size_t)(d0 + 1) * NHW + i0]     = acc_o[nf2][1] * inv0;
        O[(size_t)d0 * NHW + i0 + 8]       = acc_o[nf2][2] * inv1;
        O[(size_t)(d0 + 1) * NHW + i0 + 8] = acc_o[nf2][3] * inv1;
    }
}

// ============================================================
extern "C" void kernel_launch(void* const* d_in, const int* in_sizes, int n_in,
                              void* d_out, int out_size)
{
    const float* x      = (const float*)d_in[0];
    const float* gn_w   = (const float*)d_in[1];
    const float* gn_b   = (const float*)d_in[2];
    const float* qkv_w  = (const float*)d_in[3];
    const float* proj_w = (const float*)d_in[4];
    const float* proj_b = (const float*)d_in[5];
    float* out = (float*)d_out;

    cudaFuncSetAttribute(flash_kernel, cudaFuncAttributeMaxDynamicSharedMemorySize, FLASH_SMEM);

    gn_kernel<<<NB * NG, 256>>>(x, gn_w, gn_b);
    gemm_tc<0><<<dim3(8, 12, NB), 256>>>(qkv_w, nullptr, nullptr);
    permute_kernel<<<NB * NHEADS * 3 * 8, 256>>>();
    flash_kernel<<<NB * NHEADS * 8, 256, FLASH_SMEM>>>();
    gemm_tc<1><<<dim3(8, 4, NB), 256>>>(proj_w, proj_b, out);
}

// round 5
// speedup vs baseline: 4.2974x; 1.4162x over previous
#include <cuda_runtime.h>
#include <math.h>

#define NB 16
#define NC 512
#define NHW 1024
#define NHEADS 8
#define HD 64
#define NG 32
#define CPG 16

// ---- scratch ----
__device__ float g_xgn[(size_t)NB * NC * NHW];                 //  33.5 MB
__device__ float g_qkv[(size_t)NB * 3 * NC * NHW];             // 100.7 MB  [b][o][n]
__device__ float g_qkv2[(size_t)NB * NHEADS * 3 * HD * NHW];   // 100.7 MB  [bh][s][d2][n2]
__device__ float g_h[(size_t)NB * NC * NHW];                   //  33.5 MB  [b][c][n]

// ---- helpers ----
__device__ __forceinline__ void mma_tf32(float* c, const unsigned* a, const unsigned* b) {
    asm volatile(
        "mma.sync.aligned.m16n8k8.row.col.f32.tf32.tf32.f32 "
        "{%0,%1,%2,%3}, {%4,%5,%6,%7}, {%8,%9}, {%0,%1,%2,%3};"
        : "+f"(c[0]), "+f"(c[1]), "+f"(c[2]), "+f"(c[3])
        : "r"(a[0]), "r"(a[1]), "r"(a[2]), "r"(a[3]), "r"(b[0]), "r"(b[1]));
}
__device__ __forceinline__ void cp16(unsigned dst, const void* src) {
    asm volatile("cp.async.cg.shared.global [%0], [%1], 16;" :: "r"(dst), "l"(src));
}

// ============================================================
// GroupNorm
// ============================================================
__global__ void __launch_bounds__(256) gn_kernel(const float* __restrict__ x,
                                                 const float* __restrict__ w,
                                                 const float* __restrict__ bias)
{
    int b = blockIdx.x >> 5;
    int g = blockIdx.x & 31;
    const float* xp = x + ((size_t)b * NC + g * CPG) * NHW;

    float s = 0.f, s2 = 0.f;
    for (int i = threadIdx.x; i < CPG * NHW; i += 256) {
        float v = xp[i];
        s += v; s2 += v * v;
    }
    __shared__ float r0[8], r1[8];
    #pragma unroll
    for (int o = 16; o; o >>= 1) {
        s  += __shfl_xor_sync(~0u, s,  o);
        s2 += __shfl_xor_sync(~0u, s2, o);
    }
    int wid = threadIdx.x >> 5, lid = threadIdx.x & 31;
    if (lid == 0) { r0[wid] = s; r1[wid] = s2; }
    __syncthreads();
    if (threadIdx.x < 32) {
        s  = (lid < 8) ? r0[lid] : 0.f;
        s2 = (lid < 8) ? r1[lid] : 0.f;
        #pragma unroll
        for (int o = 4; o; o >>= 1) {
            s  += __shfl_xor_sync(~0u, s,  o);
            s2 += __shfl_xor_sync(~0u, s2, o);
        }
        if (lid == 0) { r0[0] = s; r1[0] = s2; }
    }
    __syncthreads();
    const float inv_n = 1.f / (CPG * NHW);
    float mean = r0[0] * inv_n;
    float var  = r1[0] * inv_n - mean * mean;
    float rinv = rsqrtf(var + 1e-5f);

    float* op = g_xgn + ((size_t)b * NC + g * CPG) * NHW;
    for (int i = threadIdx.x; i < CPG * NHW; i += 256) {
        int c = g * CPG + (i >> 10);
        op[i] = (xp[i] - mean) * rinv * w[c] + bias[c];
    }
}

// ============================================================
// tf32 tensor-core GEMM NN with cp.async 2-stage pipeline.
// C[b][m][n] = sum_k W[m][k] X[b][k][n]
// MODE 0: qkv; MODE 1: proj (+bias +residual g_xgn)
// CTA tile 128x128, BK=16, 8 warps 2(m)x4(n), warp tile 64x32.
// A smem [m][k] (pad 20), B smem [k][n] (pad 132): raw fp32 bits,
// HMMA truncates to tf32.
// ============================================================
template <int MODE>
__global__ void __launch_bounds__(256, 2) gemm_tc(const float* __restrict__ W,
                                                  const float* __restrict__ pbias,
                                                  float* __restrict__ outp)
{
    const int Kd = NC;
    const int M  = MODE ? NC : 3 * NC;
    const float* X = MODE ? g_h : g_xgn;
    float* Cout    = MODE ? outp : g_qkv;

    int b  = blockIdx.z;
    int m0 = blockIdx.y << 7;
    int n0 = blockIdx.x << 7;
    const float* Xb = X + (size_t)b * Kd * NHW;

    __shared__ float As[2][128][20];
    __shared__ float Bs[2][16][132];

    int t = threadIdx.x;
    int w = t >> 5, lane = t & 31;
    int gid = lane >> 2, tig = lane & 3;
    int mw = (w >> 2) * 64;
    int nw = (w & 3) * 32;

    float acc[4][4][4];
    #pragma unroll
    for (int i = 0; i < 4; i++)
        #pragma unroll
        for (int j = 0; j < 4; j++)
            #pragma unroll
            for (int c = 0; c < 4; c++) acc[i][j][c] = 0.f;

    auto load_stage = [&](int s, int k0) {
        #pragma unroll
        for (int h = 0; h < 2; h++) {
            int ca = t + h * 256;
            int m = ca >> 2, kq = (ca & 3) * 4;
            cp16((unsigned)__cvta_generic_to_shared(&As[s][m][kq]),
                 &W[(size_t)(m0 + m) * Kd + k0 + kq]);
            int k = ca >> 5, nq = (ca & 31) * 4;
            cp16((unsigned)__cvta_generic_to_shared(&Bs[s][k][nq]),
                 &Xb[(size_t)(k0 + k) * NHW + n0 + nq]);
        }
    };

    load_stage(0, 0);
    asm volatile("cp.async.commit_group;");

    const int NIT = Kd / 16;  // 32
    for (int it = 0; it < NIT; it++) {
        int s = it & 1;
        if (it + 1 < NIT) {
            load_stage(s ^ 1, (it + 1) * 16);
            asm volatile("cp.async.commit_group;");
            asm volatile("cp.async.wait_group 1;");
        } else {
            asm volatile("cp.async.wait_group 0;");
        }
        __syncthreads();

        #pragma unroll
        for (int ks = 0; ks < 16; ks += 8) {
            unsigned a[4][4], bb[4][2];
            #pragma unroll
            for (int mf = 0; mf < 4; mf++) {
                int mi = mw + mf * 16 + gid;
                a[mf][0] = __float_as_uint(As[s][mi][ks + tig]);
                a[mf][1] = __float_as_uint(As[s][mi + 8][ks + tig]);
                a[mf][2] = __float_as_uint(As[s][mi][ks + tig + 4]);
                a[mf][3] = __float_as_uint(As[s][mi + 8][ks + tig + 4]);
            }
            #pragma unroll
            for (int nf = 0; nf < 4; nf++) {
                int ni = nw + nf * 8 + gid;
                bb[nf][0] = __float_as_uint(Bs[s][ks + tig][ni]);
                bb[nf][1] = __float_as_uint(Bs[s][ks + tig + 4][ni]);
            }
            #pragma unroll
            for (int mf = 0; mf < 4; mf++)
                #pragma unroll
                for (int nf = 0; nf < 4; nf++)
                    mma_tf32(acc[mf][nf], a[mf], bb[nf]);
        }
        __syncthreads();
    }

    // epilogue
    #pragma unroll
    for (int mf = 0; mf < 4; mf++) {
        int gm = m0 + mw + mf * 16 + gid;
        #pragma unroll
        for (int nf = 0; nf < 4; nf++) {
            int gn = n0 + nw + nf * 8 + 2 * tig;
            float2 v01 = make_float2(acc[mf][nf][0], acc[mf][nf][1]);
            float2 v23 = make_float2(acc[mf][nf][2], acc[mf][nf][3]);
            if (MODE) {
                float pb0 = pbias[gm], pb1 = pbias[gm + 8];
                const float* xg0 = &g_xgn[((size_t)b * NC + gm) * NHW + gn];
                const float* xg1 = &g_xgn[((size_t)b * NC + gm + 8) * NHW + gn];
                v01.x += pb0 + xg0[0]; v01.y += pb0 + xg0[1];
                v23.x += pb1 + xg1[0]; v23.y += pb1 + xg1[1];
            }
            *reinterpret_cast<float2*>(&Cout[((size_t)b * M + gm) * NHW + gn]) = v01;
            *reinterpret_cast<float2*>(&Cout[((size_t)b * M + gm + 8) * NHW + gn]) = v23;
        }
    }
}

// ============================================================
// Permute qkv -> scrambled attention layout (reference reshape quirk)
// ============================================================
__global__ void __launch_bounds__(256) permute_kernel()
{
    int blk  = blockIdx.x;
    int d_lo = blk & 7;
    int s    = (blk >> 3) % 3;
    int bh   = blk / 24;
    int b = bh >> 3, r = bh & 7;

    __shared__ float sm[8][1024];
    const float* src = g_qkv + ((size_t)b * 3 * NC + s * NC + r * 8 + d_lo) * NHW;
    for (int i = threadIdx.x; i < 8 * 1024; i += 256) {
        int h = i >> 10, n = i & 1023;
        sm[h][n] = src[(size_t)h * HD * NHW + n];
    }
    __syncthreads();

    float* dst = g_qkv2 + (((size_t)bh * 3 + s) * HD) * NHW + (size_t)d_lo * 128;
    for (int i = threadIdx.x; i < 64 * 128; i += 256) {
        int d2 = i >> 7, j = i & 127;
        dst[(size_t)d2 * NHW + j] = sm[d2 & 7][j * 8 + (d2 >> 3)];
    }
}

// ============================================================
// Fused flash attention v3 (tf32 mma).
// CTA = (bh, qtile of 128 rows); 8 warps x 16 rows; j-block = 64.
// Q fragments in registers; K/V in fragment-packed XOR-swizzled smem
// (LDS.64 per b-frag, conflict-free); P via intra-quad shuffles
// (no P smem). smem = 32KB -> 2 CTAs/SM.
// ============================================================
__global__ void __launch_bounds__(256, 2) flash_kernel()
{
    __shared__ unsigned ksm[8 * 8 * 32 * 2];   // 16 KB
    __shared__ unsigned vsm[8 * 8 * 32 * 2];   // 16 KB

    int bh    = blockIdx.x >> 3;
    int qtile = blockIdx.x & 7;
    int b = bh >> 3, r = bh & 7;

    const float* Q = g_qkv2 + ((size_t)bh * 3 + 0) * HD * NHW;
    const float* K = g_qkv2 + ((size_t)bh * 3 + 1) * HD * NHW;
    const float* V = g_qkv2 + ((size_t)bh * 3 + 2) * HD * NHW;

    int t = threadIdx.x;
    int w = t >> 5, lane = t & 31;
    int gid = lane >> 2, tig = lane & 3;
    int i0w = w * 16;
    int i_glob = qtile * 128;

    // ---- Q a-fragments straight into registers (one-time) ----
    unsigned qf[8][4];
    {
        int ibase = i_glob + i0w + gid;
        #pragma unroll
        for (int ksid = 0; ksid < 8; ksid++) {
            const float* q0 = Q + (size_t)(ksid * 8 + tig) * NHW + ibase;
            const float* q1 = Q + (size_t)(ksid * 8 + tig + 4) * NHW + ibase;
            qf[ksid][0] = __float_as_uint(q0[0]);
            qf[ksid][1] = __float_as_uint(q0[8]);
            qf[ksid][2] = __float_as_uint(q1[0]);
            qf[ksid][3] = __float_as_uint(q1[8]);
        }
    }

    float acc_o[8][4];
    #pragma unroll
    for (int i = 0; i < 8; i++)
        #pragma unroll
        for (int c = 0; c < 4; c++) acc_o[i][c] = 0.f;
    float row_m0 = -1e30f, row_m1 = -1e30f;
    float row_l0 = 0.f, row_l1 = 0.f;
    const float scale = 0.125f;

    for (int kt = 0; kt < 16; kt++) {
        int j0 = kt * 64;
        __syncthreads();
        // ---- load K,V [64d][64j] subtiles into packed swizzled smem ----
        #pragma unroll
        for (int it = 0; it < 4; it++) {
            int pos = it * 1024 + t * 4;
            int d2 = pos >> 6, jj = pos & 63;
            float4 kv = *reinterpret_cast<const float4*>(&K[(size_t)d2 * NHW + j0 + jj]);
            float4 vv = *reinterpret_cast<const float4*>(&V[(size_t)d2 * NHW + j0 + jj]);
            int ksid = d2 >> 3, dt = d2 & 7;
            int tgk = dt & 3, halfk = dt >> 2;     // K store fields
            int nf2 = d2 >> 3, gidv = d2 & 7;      // V store fields
            float ka[4] = {kv.x, kv.y, kv.z, kv.w};
            float va[4] = {vv.x, vv.y, vv.z, vv.w};
            #pragma unroll
            for (int e = 0; e < 4; e++) {
                int jje = jj + e;
                {   // Kpack: b-pair (ksid, nf): w0=K[ksid*8+tig][nf*8+gid], w1=+4 row
                    int nf = jje >> 3, gidk = jje & 7;
                    int lc = (gidk * 4 + tgk) ^ ((nf & 3) * 5);
                    ksm[((ksid * 8 + nf) * 32 + lc) * 2 + halfk] = __float_as_uint(ka[e]);
                }
                {   // Vpack: b-pair (js, nf2): w0=V[nf2*8+gid][js*8+tig], w1=+4 col
                    int js = jje >> 3, jt = jje & 7;
                    int tgv = jt & 3, halfv = jt >> 2;
                    int lc = (gidv * 4 + tgv) ^ ((js & 3) * 5);
                    vsm[((js * 8 + nf2) * 32 + lc) * 2 + halfv] = __float_as_uint(va[e]);
                }
            }
        }
        __syncthreads();

        // ---- S = Q^T K : warp rows x 64 cols ----
        float p[8][4];
        #pragma unroll
        for (int i = 0; i < 8; i++)
            #pragma unroll
            for (int c = 0; c < 4; c++) p[i][c] = 0.f;

        #pragma unroll
        for (int ksid = 0; ksid < 8; ksid++) {
            #pragma unroll
            for (int nf = 0; nf < 8; nf++) {
                uint2 kb = *reinterpret_cast<const uint2*>(
                    &ksm[((ksid * 8 + nf) * 32 + (lane ^ ((nf & 3) * 5))) * 2]);
                unsigned bb[2] = {kb.x, kb.y};
                mma_tf32(p[nf], qf[ksid], bb);
            }
        }

        // ---- online softmax over this 64-col block ----
        float tmax0 = -1e30f, tmax1 = -1e30f;
        #pragma unroll
        for (int nf = 0; nf < 8; nf++) {
            tmax0 = fmaxf(tmax0, fmaxf(p[nf][0], p[nf][1]));
            tmax1 = fmaxf(tmax1, fmaxf(p[nf][2], p[nf][3]));
        }
        tmax0 = fmaxf(tmax0, __shfl_xor_sync(~0u, tmax0, 1));
        tmax0 = fmaxf(tmax0, __shfl_xor_sync(~0u, tmax0, 2));
        tmax1 = fmaxf(tmax1, __shfl_xor_sync(~0u, tmax1, 1));
        tmax1 = fmaxf(tmax1, __shfl_xor_sync(~0u, tmax1, 2));

        float nm0 = fmaxf(row_m0, tmax0 * scale);
        float nm1 = fmaxf(row_m1, tmax1 * scale);
        float corr0 = __expf(row_m0 - nm0);
        float corr1 = __expf(row_m1 - nm1);

        float sum0 = 0.f, sum1 = 0.f;
        #pragma unroll
        for (int nf = 0; nf < 8; nf++) {
            p[nf][0] = __expf(p[nf][0] * scale - nm0);
            p[nf][1] = __expf(p[nf][1] * scale - nm0);
            p[nf][2] = __expf(p[nf][2] * scale - nm1);
            p[nf][3] = __expf(p[nf][3] * scale - nm1);
            sum0 += p[nf][0] + p[nf][1];
            sum1 += p[nf][2] + p[nf][3];
        }
        sum0 += __shfl_xor_sync(~0u, sum0, 1);
        sum0 += __shfl_xor_sync(~0u, sum0, 2);
        sum1 += __shfl_xor_sync(~0u, sum1, 1);
        sum1 += __shfl_xor_sync(~0u, sum1, 2);

        row_l0 = row_l0 * corr0 + sum0;
        row_l1 = row_l1 * corr1 + sum1;
        row_m0 = nm0; row_m1 = nm1;

        #pragma unroll
        for (int nf2 = 0; nf2 < 8; nf2++) {
            acc_o[nf2][0] *= corr0; acc_o[nf2][1] *= corr0;
            acc_o[nf2][2] *= corr1; acc_o[nf2][3] *= corr1;
        }

        // ---- O += P V^T : a-frags from P via intra-quad shuffles ----
        #pragma unroll
        for (int js = 0; js < 8; js++) {
            float p0 = p[js][0], p1 = p[js][1], p2 = p[js][2], p3 = p[js][3];
            int srcA = (lane & ~3) | (tig >> 1);
            int srcB = srcA + 2;
            float q0a = __shfl_sync(~0u, p0, srcA), q1a = __shfl_sync(~0u, p1, srcA);
            float q2a = __shfl_sync(~0u, p2, srcA), q3a = __shfl_sync(~0u, p3, srcA);
            float q0b = __shfl_sync(~0u, p0, srcB), q1b = __shfl_sync(~0u, p1, srcB);
            float q2b = __shfl_sync(~0u, p2, srcB), q3b = __shfl_sync(~0u, p3, srcB);
            bool odd = (tig & 1) != 0;
            unsigned pa[4];
            pa[0] = __float_as_uint(odd ? q1a : q0a);   // P[gid  ][tig]
            pa[1] = __float_as_uint(odd ? q3a : q2a);   // P[gid+8][tig]
            pa[2] = __float_as_uint(odd ? q1b : q0b);   // P[gid  ][tig+4]
            pa[3] = __float_as_uint(odd ? q3b : q2b);   // P[gid+8][tig+4]
            #pragma unroll
            for (int nf2 = 0; nf2 < 8; nf2++) {
                uint2 vb = *reinterpret_cast<const uint2*>(
                    &vsm[((js * 8 + nf2) * 32 + (lane ^ ((js & 3) * 5))) * 2]);
                unsigned bb[2] = {vb.x, vb.y};
                mma_tf32(acc_o[nf2], pa, bb);
            }
        }
    }

    // ---- epilogue: O /= l, write to g_h[b][r*64+d][i] ----
    float inv0 = 1.f / row_l0, inv1 = 1.f / row_l1;
    float* O = g_h + ((size_t)b * NC + r * HD) * NHW;
    int i0 = i_glob + i0w + gid;
    #pragma unroll
    for (int nf2 = 0; nf2 < 8; nf2++) {
        int d0 = nf2 * 8 + 2 * tig;
        O[(size_t)d0 * NHW + i0]           = acc_o[nf2][0] * inv0;
        O[(size_t)(d0 + 1) * NHW + i0]     = acc_o[nf2][1] * inv0;
        O[(size_t)d0 * NHW + i0 + 8]       = acc_o[nf2][2] * inv1;
        O[(size_t)(d0 + 1) * NHW + i0 + 8] = acc_o[nf2][3] * inv1;
    }
}

// ============================================================
extern "C" void kernel_launch(void* const* d_in, const int* in_sizes, int n_in,
                              void* d_out, int out_size)
{
    const float* x      = (const float*)d_in[0];
    const float* gn_w   = (const float*)d_in[1];
    const float* gn_b   = (const float*)d_in[2];
    const float* qkv_w  = (const float*)d_in[3];
    const float* proj_w = (const float*)d_in[4];
    const float* proj_b = (const float*)d_in[5];
    float* out = (float*)d_out;

    gn_kernel<<<NB * NG, 256>>>(x, gn_w, gn_b);
    gemm_tc<0><<<dim3(8, 12, NB), 256>>>(qkv_w, nullptr, nullptr);
    permute_kernel<<<NB * NHEADS * 3 * 8, 256>>>();
    flash_kernel<<<NB * NHEADS * 8, 256>>>();
    gemm_tc<1><<<dim3(8, 4, NB), 256>>>(proj_w, proj_b, out);
}

// round 6
// speedup vs baseline: 4.6094x; 1.0726x over previous
#include <cuda_runtime.h>
#include <math.h>

#define NB 16
#define NC 512
#define NHW 1024
#define NHEADS 8
#define HD 64
#define NG 32
#define CPG 16

// ---- scratch ----
__device__ float g_xgn[(size_t)NB * NC * NHW];                 //  33.5 MB
__device__ float g_qkv[(size_t)NB * 3 * NC * NHW];             // 100.7 MB  [b][o][n]
__device__ float g_qkv2[(size_t)NB * NHEADS * 3 * HD * NHW];   // 100.7 MB  [bh][s][d2][n2]
__device__ float g_h[(size_t)NB * NC * NHW];                   //  33.5 MB  [b][c][n]

// ---- helpers ----
__device__ __forceinline__ void mma_tf32(float* c, const unsigned* a, const unsigned* b) {
    asm volatile(
        "mma.sync.aligned.m16n8k8.row.col.f32.tf32.tf32.f32 "
        "{%0,%1,%2,%3}, {%4,%5,%6,%7}, {%8,%9}, {%0,%1,%2,%3};"
        : "+f"(c[0]), "+f"(c[1]), "+f"(c[2]), "+f"(c[3])
        : "r"(a[0]), "r"(a[1]), "r"(a[2]), "r"(a[3]), "r"(b[0]), "r"(b[1]));
}
__device__ __forceinline__ void mma_bf16(float* c, const unsigned* a, const unsigned* b) {
    asm volatile(
        "mma.sync.aligned.m16n8k16.row.col.f32.bf16.bf16.f32 "
        "{%0,%1,%2,%3}, {%4,%5,%6,%7}, {%8,%9}, {%0,%1,%2,%3};"
        : "+f"(c[0]), "+f"(c[1]), "+f"(c[2]), "+f"(c[3])
        : "r"(a[0]), "r"(a[1]), "r"(a[2]), "r"(a[3]), "r"(b[0]), "r"(b[1]));
}
// packed bf16x2: low half = lo, high half = hi
__device__ __forceinline__ unsigned packbf(float lo, float hi) {
    unsigned d;
    asm("cvt.rn.bf16x2.f32 %0, %1, %2;" : "=r"(d) : "f"(hi), "f"(lo));
    return d;
}
__device__ __forceinline__ void cp16(unsigned dst, const void* src) {
    asm volatile("cp.async.cg.shared.global [%0], [%1], 16;" :: "r"(dst), "l"(src));
}

// ============================================================
// GroupNorm
// ============================================================
__global__ void __launch_bounds__(256) gn_kernel(const float* __restrict__ x,
                                                 const float* __restrict__ w,
                                                 const float* __restrict__ bias)
{
    int b = blockIdx.x >> 5;
    int g = blockIdx.x & 31;
    const float* xp = x + ((size_t)b * NC + g * CPG) * NHW;

    float s = 0.f, s2 = 0.f;
    for (int i = threadIdx.x; i < CPG * NHW; i += 256) {
        float v = xp[i];
        s += v; s2 += v * v;
    }
    __shared__ float r0[8], r1[8];
    #pragma unroll
    for (int o = 16; o; o >>= 1) {
        s  += __shfl_xor_sync(~0u, s,  o);
        s2 += __shfl_xor_sync(~0u, s2, o);
    }
    int wid = threadIdx.x >> 5, lid = threadIdx.x & 31;
    if (lid == 0) { r0[wid] = s; r1[wid] = s2; }
    __syncthreads();
    if (threadIdx.x < 32) {
        s  = (lid < 8) ? r0[lid] : 0.f;
        s2 = (lid < 8) ? r1[lid] : 0.f;
        #pragma unroll
        for (int o = 4; o; o >>= 1) {
            s  += __shfl_xor_sync(~0u, s,  o);
            s2 += __shfl_xor_sync(~0u, s2, o);
        }
        if (lid == 0) { r0[0] = s; r1[0] = s2; }
    }
    __syncthreads();
    const float inv_n = 1.f / (CPG * NHW);
    float mean = r0[0] * inv_n;
    float var  = r1[0] * inv_n - mean * mean;
    float rinv = rsqrtf(var + 1e-5f);

    float* op = g_xgn + ((size_t)b * NC + g * CPG) * NHW;
    for (int i = threadIdx.x; i < CPG * NHW; i += 256) {
        int c = g * CPG + (i >> 10);
        op[i] = (xp[i] - mean) * rinv * w[c] + bias[c];
    }
}

// ============================================================
// tf32 tensor-core GEMM NN with cp.async 2-stage pipeline.
// ============================================================
template <int MODE>
__global__ void __launch_bounds__(256, 2) gemm_tc(const float* __restrict__ W,
                                                  const float* __restrict__ pbias,
                                                  float* __restrict__ outp)
{
    const int Kd = NC;
    const int M  = MODE ? NC : 3 * NC;
    const float* X = MODE ? g_h : g_xgn;
    float* Cout    = MODE ? outp : g_qkv;

    int b  = blockIdx.z;
    int m0 = blockIdx.y << 7;
    int n0 = blockIdx.x << 7;
    const float* Xb = X + (size_t)b * Kd * NHW;

    __shared__ float As[2][128][20];
    __shared__ float Bs[2][16][132];

    int t = threadIdx.x;
    int w = t >> 5, lane = t & 31;
    int gid = lane >> 2, tig = lane & 3;
    int mw = (w >> 2) * 64;
    int nw = (w & 3) * 32;

    float acc[4][4][4];
    #pragma unroll
    for (int i = 0; i < 4; i++)
        #pragma unroll
        for (int j = 0; j < 4; j++)
            #pragma unroll
            for (int c = 0; c < 4; c++) acc[i][j][c] = 0.f;

    auto load_stage = [&](int s, int k0) {
        #pragma unroll
        for (int h = 0; h < 2; h++) {
            int ca = t + h * 256;
            int m = ca >> 2, kq = (ca & 3) * 4;
            cp16((unsigned)__cvta_generic_to_shared(&As[s][m][kq]),
                 &W[(size_t)(m0 + m) * Kd + k0 + kq]);
            int k = ca >> 5, nq = (ca & 31) * 4;
            cp16((unsigned)__cvta_generic_to_shared(&Bs[s][k][nq]),
                 &Xb[(size_t)(k0 + k) * NHW + n0 + nq]);
        }
    };

    load_stage(0, 0);
    asm volatile("cp.async.commit_group;");

    const int NIT = Kd / 16;
    for (int it = 0; it < NIT; it++) {
        int s = it & 1;
        if (it + 1 < NIT) {
            load_stage(s ^ 1, (it + 1) * 16);
            asm volatile("cp.async.commit_group;");
            asm volatile("cp.async.wait_group 1;");
        } else {
            asm volatile("cp.async.wait_group 0;");
        }
        __syncthreads();

        #pragma unroll
        for (int ks = 0; ks < 16; ks += 8) {
            unsigned a[4][4], bb[4][2];
            #pragma unroll
            for (int mf = 0; mf < 4; mf++) {
                int mi = mw + mf * 16 + gid;
                a[mf][0] = __float_as_uint(As[s][mi][ks + tig]);
                a[mf][1] = __float_as_uint(As[s][mi + 8][ks + tig]);
                a[mf][2] = __float_as_uint(As[s][mi][ks + tig + 4]);
                a[mf][3] = __float_as_uint(As[s][mi + 8][ks + tig + 4]);
            }
            #pragma unroll
            for (int nf = 0; nf < 4; nf++) {
                int ni = nw + nf * 8 + gid;
                bb[nf][0] = __float_as_uint(Bs[s][ks + tig][ni]);
                bb[nf][1] = __float_as_uint(Bs[s][ks + tig + 4][ni]);
            }
            #pragma unroll
            for (int mf = 0; mf < 4; mf++)
                #pragma unroll
                for (int nf = 0; nf < 4; nf++)
                    mma_tf32(acc[mf][nf], a[mf], bb[nf]);
        }
        __syncthreads();
    }

    #pragma unroll
    for (int mf = 0; mf < 4; mf++) {
        int gm = m0 + mw + mf * 16 + gid;
        #pragma unroll
        for (int nf = 0; nf < 4; nf++) {
            int gn = n0 + nw + nf * 8 + 2 * tig;
            float2 v01 = make_float2(acc[mf][nf][0], acc[mf][nf][1]);
            float2 v23 = make_float2(acc[mf][nf][2], acc[mf][nf][3]);
            if (MODE) {
                float pb0 = pbias[gm], pb1 = pbias[gm + 8];
                const float* xg0 = &g_xgn[((size_t)b * NC + gm) * NHW + gn];
                const float* xg1 = &g_xgn[((size_t)b * NC + gm + 8) * NHW + gn];
                v01.x += pb0 + xg0[0]; v01.y += pb0 + xg0[1];
                v23.x += pb1 + xg1[0]; v23.y += pb1 + xg1[1];
            }
            *reinterpret_cast<float2*>(&Cout[((size_t)b * M + gm) * NHW + gn]) = v01;
            *reinterpret_cast<float2*>(&Cout[((size_t)b * M + gm + 8) * NHW + gn]) = v23;
        }
    }
}

// ============================================================
// Permute qkv -> scrambled attention layout
// ============================================================
__global__ void __launch_bounds__(256) permute_kernel()
{
    int blk  = blockIdx.x;
    int d_lo = blk & 7;
    int s    = (blk >> 3) % 3;
    int bh   = blk / 24;
    int b = bh >> 3, r = bh & 7;

    __shared__ float sm[8][1024];
    const float* src = g_qkv + ((size_t)b * 3 * NC + s * NC + r * 8 + d_lo) * NHW;
    for (int i = threadIdx.x; i < 8 * 1024; i += 256) {
        int h = i >> 10, n = i & 1023;
        sm[h][n] = src[(size_t)h * HD * NHW + n];
    }
    __syncthreads();

    float* dst = g_qkv2 + (((size_t)bh * 3 + s) * HD) * NHW + (size_t)d_lo * 128;
    for (int i = threadIdx.x; i < 64 * 128; i += 256) {
        int d2 = i >> 7, j = i & 127;
        dst[(size_t)d2 * NHW + j] = sm[d2 & 7][j * 8 + (d2 >> 3)];
    }
}

// ============================================================
// Fused flash attention v4.
// S = QK^T in tf32 (K packed-swizzled smem, Q regs).
// PV in bf16 m16n8k16: S-accumulator feeds A-fragment DIRECTLY
// (FA2 layout identity) — no shuffles, no P smem. V as packed
// bf16x2 b-fragments (8KB).  smem 24KB, 2 CTAs/SM.
// ============================================================
__global__ void __launch_bounds__(256, 2) flash_kernel()
{
    __shared__ unsigned ksm[8 * 8 * 32 * 2];   // 16 KB tf32 K b-frags
    __shared__ unsigned vsm[4 * 8 * 32 * 2];   //  8 KB bf16x2 V b-frags

    int bh    = blockIdx.x >> 3;
    int qtile = blockIdx.x & 7;
    int b = bh >> 3, r = bh & 7;

    const float* Q = g_qkv2 + ((size_t)bh * 3 + 0) * HD * NHW;
    const float* K = g_qkv2 + ((size_t)bh * 3 + 1) * HD * NHW;
    const float* V = g_qkv2 + ((size_t)bh * 3 + 2) * HD * NHW;

    int t = threadIdx.x;
    int w = t >> 5, lane = t & 31;
    int gid = lane >> 2, tig = lane & 3;
    int i0w = w * 16;
    int i_glob = qtile * 128;

    // ---- Q a-fragments into registers (one-time) ----
    unsigned qf[8][4];
    {
        int ibase = i_glob + i0w + gid;
        #pragma unroll
        for (int ksid = 0; ksid < 8; ksid++) {
            const float* q0 = Q + (size_t)(ksid * 8 + tig) * NHW + ibase;
            const float* q1 = Q + (size_t)(ksid * 8 + tig + 4) * NHW + ibase;
            qf[ksid][0] = __float_as_uint(q0[0]);
            qf[ksid][1] = __float_as_uint(q0[8]);
            qf[ksid][2] = __float_as_uint(q1[0]);
            qf[ksid][3] = __float_as_uint(q1[8]);
        }
    }

    float acc_o[8][4];
    #pragma unroll
    for (int i = 0; i < 8; i++)
        #pragma unroll
        for (int c = 0; c < 4; c++) acc_o[i][c] = 0.f;
    float row_m0 = -1e30f, row_m1 = -1e30f;
    float row_l0 = 0.f, row_l1 = 0.f;
    const float scale = 0.125f;

    for (int kt = 0; kt < 16; kt++) {
        int j0 = kt * 64;
        __syncthreads();
        // ---- load K (tf32 pack) and V (bf16x2 pack) subtiles ----
        #pragma unroll
        for (int it = 0; it < 4; it++) {
            int pos = it * 1024 + t * 4;
            int d2 = pos >> 6, jj = pos & 63;
            float4 kv = *reinterpret_cast<const float4*>(&K[(size_t)d2 * NHW + j0 + jj]);
            float4 vv = *reinterpret_cast<const float4*>(&V[(size_t)d2 * NHW + j0 + jj]);
            // K pack (unchanged from v3)
            {
                int ksid = d2 >> 3, dt = d2 & 7;
                int tgk = dt & 3, halfk = dt >> 2;
                float ka[4] = {kv.x, kv.y, kv.z, kv.w};
                #pragma unroll
                for (int e = 0; e < 4; e++) {
                    int jje = jj + e;
                    int nf = jje >> 3, gidk = jje & 7;
                    int lc = (gidk * 4 + tgk) ^ ((nf & 3) * 5);
                    ksm[((ksid * 8 + nf) * 32 + lc) * 2 + halfk] = __float_as_uint(ka[e]);
                }
            }
            // V pack: b-frag for bf16 k16: word(d, p) holds V[d][js*16+2p], +1
            {
                int nf2 = d2 >> 3, gidv = d2 & 7;
                int jsv = jj >> 4;
                int p0 = (jj & 15) >> 1;   // 0,2,4,6
                unsigned wA = packbf(vv.x, vv.y);
                unsigned wB = packbf(vv.z, vv.w);
                int lcA = (gidv * 4 + (p0 & 3)) ^ (jsv & 1);
                int lcB = (gidv * 4 + ((p0 + 1) & 3)) ^ (jsv & 1);
                vsm[((jsv * 8 + nf2) * 32 + lcA) * 2 + (p0 >> 2)]       = wA;
                vsm[((jsv * 8 + nf2) * 32 + lcB) * 2 + ((p0 + 1) >> 2)] = wB;
            }
        }
        __syncthreads();

        // ---- S = Q^T K : warp rows x 64 cols (tf32) ----
        float p[8][4];
        #pragma unroll
        for (int i = 0; i < 8; i++)
            #pragma unroll
            for (int c = 0; c < 4; c++) p[i][c] = 0.f;

        #pragma unroll
        for (int ksid = 0; ksid < 8; ksid++) {
            #pragma unroll
            for (int nf = 0; nf < 8; nf++) {
                uint2 kb = *reinterpret_cast<const uint2*>(
                    &ksm[((ksid * 8 + nf) * 32 + (lane ^ ((nf & 3) * 5))) * 2]);
                unsigned bb[2] = {kb.x, kb.y};
                mma_tf32(p[nf], qf[ksid], bb);
            }
        }

        // ---- online softmax ----
        float tmax0 = -1e30f, tmax1 = -1e30f;
        #pragma unroll
        for (int nf = 0; nf < 8; nf++) {
            tmax0 = fmaxf(tmax0, fmaxf(p[nf][0], p[nf][1]));
            tmax1 = fmaxf(tmax1, fmaxf(p[nf][2], p[nf][3]));
        }
        tmax0 = fmaxf(tmax0, __shfl_xor_sync(~0u, tmax0, 1));
        tmax0 = fmaxf(tmax0, __shfl_xor_sync(~0u, tmax0, 2));
        tmax1 = fmaxf(tmax1, __shfl_xor_sync(~0u, tmax1, 1));
        tmax1 = fmaxf(tmax1, __shfl_xor_sync(~0u, tmax1, 2));

        float nm0 = fmaxf(row_m0, tmax0 * scale);
        float nm1 = fmaxf(row_m1, tmax1 * scale);
        float corr0 = __expf(row_m0 - nm0);
        float corr1 = __expf(row_m1 - nm1);

        float sum0 = 0.f, sum1 = 0.f;
        #pragma unroll
        for (int nf = 0; nf < 8; nf++) {
            p[nf][0] = __expf(p[nf][0] * scale - nm0);
            p[nf][1] = __expf(p[nf][1] * scale - nm0);
            p[nf][2] = __expf(p[nf][2] * scale - nm1);
            p[nf][3] = __expf(p[nf][3] * scale - nm1);
            sum0 += p[nf][0] + p[nf][1];
            sum1 += p[nf][2] + p[nf][3];
        }
        sum0 += __shfl_xor_sync(~0u, sum0, 1);
        sum0 += __shfl_xor_sync(~0u, sum0, 2);
        sum1 += __shfl_xor_sync(~0u, sum1, 1);
        sum1 += __shfl_xor_sync(~0u, sum1, 2);

        row_l0 = row_l0 * corr0 + sum0;
        row_l1 = row_l1 * corr1 + sum1;
        row_m0 = nm0; row_m1 = nm1;

        #pragma unroll
        for (int nf2 = 0; nf2 < 8; nf2++) {
            acc_o[nf2][0] *= corr0; acc_o[nf2][1] *= corr0;
            acc_o[nf2][2] *= corr1; acc_o[nf2][3] *= corr1;
        }

        // ---- O += P V^T via bf16 m16n8k16: S c-frag == bf16 a-frag ----
        #pragma unroll
        for (int js = 0; js < 4; js++) {
            unsigned pa[4];
            pa[0] = packbf(p[2 * js][0],     p[2 * js][1]);
            pa[1] = packbf(p[2 * js][2],     p[2 * js][3]);
            pa[2] = packbf(p[2 * js + 1][0], p[2 * js + 1][1]);
            pa[3] = packbf(p[2 * js + 1][2], p[2 * js + 1][3]);
            #pragma unroll
            for (int nf2 = 0; nf2 < 8; nf2++) {
                uint2 vb = *reinterpret_cast<const uint2*>(
                    &vsm[((js * 8 + nf2) * 32 + (lane ^ (js & 1))) * 2]);
                unsigned bb[2] = {vb.x, vb.y};
                mma_bf16(acc_o[nf2], pa, bb);
            }
        }
    }

    // ---- epilogue ----
    float inv0 = 1.f / row_l0, inv1 = 1.f / row_l1;
    float* O = g_h + ((size_t)b * NC + r * HD) * NHW;
    int i0 = i_glob + i0w + gid;
    #pragma unroll
    for (int nf2 = 0; nf2 < 8; nf2++) {
        int d0 = nf2 * 8 + 2 * tig;
        O[(size_t)d0 * NHW + i0]           = acc_o[nf2][0] * inv0;
        O[(size_t)(d0 + 1) * NHW + i0]     = acc_o[nf2][1] * inv0;
        O[(size_t)d0 * NHW + i0 + 8]       = acc_o[nf2][2] * inv1;
        O[(size_t)(d0 + 1) * NHW + i0 + 8] = acc_o[nf2][3] * inv1;
    }
}

// ============================================================
extern "C" void kernel_launch(void* const* d_in, const int* in_sizes, int n_in,
                              void* d_out, int out_size)
{
    const float* x      = (const float*)d_in[0];
    const float* gn_w   = (const float*)d_in[1];
    const float* gn_b   = (const float*)d_in[2];
    const float* qkv_w  = (const float*)d_in[3];
    const float* proj_w = (const float*)d_in[4];
    const float* proj_b = (const float*)d_in[5];
    float* out = (float*)d_out;

    gn_kernel<<<NB * NG, 256>>>(x, gn_w, gn_b);
    gemm_tc<0><<<dim3(8, 12, NB), 256>>>(qkv_w, nullptr, nullptr);
    permute_kernel<<<NB * NHEADS * 3 * 8, 256>>>();
    flash_kernel<<<NB * NHEADS * 8, 256>>>();
    gemm_tc<1><<<dim3(8, 4, NB), 256>>>(proj_w, proj_b, out);
}

// round 7
// speedup vs baseline: 5.7693x; 1.2516x over previous
#include <cuda_runtime.h>
#include <cuda_bf16.h>
#include <math.h>

#define NB 16
#define NC 512
#define NHW 1024
#define NHEADS 8
#define HD 64
#define NG 32
#define CPG 16

// ---- scratch ----
__device__ float g_xgn[(size_t)NB * NC * NHW];                 //  33.5 MB
__device__ float g_qkv[(size_t)NB * 3 * NC * NHW];             // 100.7 MB  [b][o][n]
__device__ float g_q2[(size_t)NB * NHEADS * HD * NHW];         //  33.5 MB  fp32 Q [bh][d2][n2]
__device__ __nv_bfloat16 g_kbf[(size_t)NB * NHEADS * NHW * HD]; // 16.8 MB  bf16 K [bh][n2][d2] (transposed)
__device__ __nv_bfloat16 g_vbf[(size_t)NB * NHEADS * HD * NHW]; // 16.8 MB  bf16 V [bh][d2][n2]
__device__ float g_h[(size_t)NB * NC * NHW];                   //  33.5 MB  [b][c][n]

// ---- helpers ----
__device__ __forceinline__ void mma_tf32(float* c, const unsigned* a, const unsigned* b) {
    asm volatile(
        "mma.sync.aligned.m16n8k8.row.col.f32.tf32.tf32.f32 "
        "{%0,%1,%2,%3}, {%4,%5,%6,%7}, {%8,%9}, {%0,%1,%2,%3};"
        : "+f"(c[0]), "+f"(c[1]), "+f"(c[2]), "+f"(c[3])
        : "r"(a[0]), "r"(a[1]), "r"(a[2]), "r"(a[3]), "r"(b[0]), "r"(b[1]));
}
__device__ __forceinline__ void mma_bf16(float* c, const unsigned* a, const unsigned* b) {
    asm volatile(
        "mma.sync.aligned.m16n8k16.row.col.f32.bf16.bf16.f32 "
        "{%0,%1,%2,%3}, {%4,%5,%6,%7}, {%8,%9}, {%0,%1,%2,%3};"
        : "+f"(c[0]), "+f"(c[1]), "+f"(c[2]), "+f"(c[3])
        : "r"(a[0]), "r"(a[1]), "r"(a[2]), "r"(a[3]), "r"(b[0]), "r"(b[1]));
}
// packed bf16x2: low half = lo, high half = hi
__device__ __forceinline__ unsigned packbf(float lo, float hi) {
    unsigned d;
    asm("cvt.rn.bf16x2.f32 %0, %1, %2;" : "=r"(d) : "f"(hi), "f"(lo));
    return d;
}
__device__ __forceinline__ void cp16(unsigned dst, const void* src) {
    asm volatile("cp.async.cg.shared.global [%0], [%1], 16;" :: "r"(dst), "l"(src));
}

// ============================================================
// GroupNorm
// ============================================================
__global__ void __launch_bounds__(256) gn_kernel(const float* __restrict__ x,
                                                 const float* __restrict__ w,
                                                 const float* __restrict__ bias)
{
    int b = blockIdx.x >> 5;
    int g = blockIdx.x & 31;
    const float* xp = x + ((size_t)b * NC + g * CPG) * NHW;

    float s = 0.f, s2 = 0.f;
    for (int i = threadIdx.x; i < CPG * NHW; i += 256) {
        float v = xp[i];
        s += v; s2 += v * v;
    }
    __shared__ float r0[8], r1[8];
    #pragma unroll
    for (int o = 16; o; o >>= 1) {
        s  += __shfl_xor_sync(~0u, s,  o);
        s2 += __shfl_xor_sync(~0u, s2, o);
    }
    int wid = threadIdx.x >> 5, lid = threadIdx.x & 31;
    if (lid == 0) { r0[wid] = s; r1[wid] = s2; }
    __syncthreads();
    if (threadIdx.x < 32) {
        s  = (lid < 8) ? r0[lid] : 0.f;
        s2 = (lid < 8) ? r1[lid] : 0.f;
        #pragma unroll
        for (int o = 4; o; o >>= 1) {
            s  += __shfl_xor_sync(~0u, s,  o);
            s2 += __shfl_xor_sync(~0u, s2, o);
        }
        if (lid == 0) { r0[0] = s; r1[0] = s2; }
    }
    __syncthreads();
    const float inv_n = 1.f / (CPG * NHW);
    float mean = r0[0] * inv_n;
    float var  = r1[0] * inv_n - mean * mean;
    float rinv = rsqrtf(var + 1e-5f);

    float* op = g_xgn + ((size_t)b * NC + g * CPG) * NHW;
    for (int i = threadIdx.x; i < CPG * NHW; i += 256) {
        int c = g * CPG + (i >> 10);
        op[i] = (xp[i] - mean) * rinv * w[c] + bias[c];
    }
}

// ============================================================
// tf32 tensor-core GEMM NN with cp.async 2-stage pipeline.
// ============================================================
template <int MODE>
__global__ void __launch_bounds__(256, 2) gemm_tc(const float* __restrict__ W,
                                                  const float* __restrict__ pbias,
                                                  float* __restrict__ outp)
{
    const int Kd = NC;
    const int M  = MODE ? NC : 3 * NC;
    const float* X = MODE ? g_h : g_xgn;
    float* Cout    = MODE ? outp : g_qkv;

    int b  = blockIdx.z;
    int m0 = blockIdx.y << 7;
    int n0 = blockIdx.x << 7;
    const float* Xb = X + (size_t)b * Kd * NHW;

    __shared__ float As[2][128][20];
    __shared__ float Bs[2][16][132];

    int t = threadIdx.x;
    int w = t >> 5, lane = t & 31;
    int gid = lane >> 2, tig = lane & 3;
    int mw = (w >> 2) * 64;
    int nw = (w & 3) * 32;

    float acc[4][4][4];
    #pragma unroll
    for (int i = 0; i < 4; i++)
        #pragma unroll
        for (int j = 0; j < 4; j++)
            #pragma unroll
            for (int c = 0; c < 4; c++) acc[i][j][c] = 0.f;

    auto load_stage = [&](int s, int k0) {
        #pragma unroll
        for (int h = 0; h < 2; h++) {
            int ca = t + h * 256;
            int m = ca >> 2, kq = (ca & 3) * 4;
            cp16((unsigned)__cvta_generic_to_shared(&As[s][m][kq]),
                 &W[(size_t)(m0 + m) * Kd + k0 + kq]);
            int k = ca >> 5, nq = (ca & 31) * 4;
            cp16((unsigned)__cvta_generic_to_shared(&Bs[s][k][nq]),
                 &Xb[(size_t)(k0 + k) * NHW + n0 + nq]);
        }
    };

    load_stage(0, 0);
    asm volatile("cp.async.commit_group;");

    const int NIT = Kd / 16;
    for (int it = 0; it < NIT; it++) {
        int s = it & 1;
        if (it + 1 < NIT) {
            load_stage(s ^ 1, (it + 1) * 16);
            asm volatile("cp.async.commit_group;");
            asm volatile("cp.async.wait_group 1;");
        } else {
            asm volatile("cp.async.wait_group 0;");
        }
        __syncthreads();

        #pragma unroll
        for (int ks = 0; ks < 16; ks += 8) {
            unsigned a[4][4], bb[4][2];
            #pragma unroll
            for (int mf = 0; mf < 4; mf++) {
                int mi = mw + mf * 16 + gid;
                a[mf][0] = __float_as_uint(As[s][mi][ks + tig]);
                a[mf][1] = __float_as_uint(As[s][mi + 8][ks + tig]);
                a[mf][2] = __float_as_uint(As[s][mi][ks + tig + 4]);
                a[mf][3] = __float_as_uint(As[s][mi + 8][ks + tig + 4]);
            }
            #pragma unroll
            for (int nf = 0; nf < 4; nf++) {
                int ni = nw + nf * 8 + gid;
                bb[nf][0] = __float_as_uint(Bs[s][ks + tig][ni]);
                bb[nf][1] = __float_as_uint(Bs[s][ks + tig + 4][ni]);
            }
            #pragma unroll
            for (int mf = 0; mf < 4; mf++)
                #pragma unroll
                for (int nf = 0; nf < 4; nf++)
                    mma_tf32(acc[mf][nf], a[mf], bb[nf]);
        }
        __syncthreads();
    }

    #pragma unroll
    for (int mf = 0; mf < 4; mf++) {
        int gm = m0 + mw + mf * 16 + gid;
        #pragma unroll
        for (int nf = 0; nf < 4; nf++) {
            int gn = n0 + nw + nf * 8 + 2 * tig;
            float2 v01 = make_float2(acc[mf][nf][0], acc[mf][nf][1]);
            float2 v23 = make_float2(acc[mf][nf][2], acc[mf][nf][3]);
            if (MODE) {
                float pb0 = pbias[gm], pb1 = pbias[gm + 8];
                const float* xg0 = &g_xgn[((size_t)b * NC + gm) * NHW + gn];
                const float* xg1 = &g_xgn[((size_t)b * NC + gm + 8) * NHW + gn];
                v01.x += pb0 + xg0[0]; v01.y += pb0 + xg0[1];
                v23.x += pb1 + xg1[0]; v23.y += pb1 + xg1[1];
            }
            *reinterpret_cast<float2*>(&Cout[((size_t)b * M + gm) * NHW + gn]) = v01;
            *reinterpret_cast<float2*>(&Cout[((size_t)b * M + gm + 8) * NHW + gn]) = v23;
        }
    }
}

// ============================================================
// Permute qkv -> attention layouts.
// Q: fp32 [bh][d2][n2]; K: bf16 [bh][n2][d2] (transposed);
// V: bf16 [bh][d2][n2].
// value(d2, n2 = d_lo*128+jj) = sm[d2&7][jj*8 + (d2>>3)]
// ============================================================
__global__ void __launch_bounds__(256) permute_kernel()
{
    int blk  = blockIdx.x;
    int d_lo = blk & 7;
    int s    = (blk >> 3) % 3;
    int bh   = blk / 24;
    int b = bh >> 3, r = bh & 7;

    __shared__ float sm[8][1024];
    const float* src = g_qkv + ((size_t)b * 3 * NC + s * NC + r * 8 + d_lo) * NHW;
    for (int i = threadIdx.x; i < 8 * 1024; i += 256) {
        int h = i >> 10, n = i & 1023;
        sm[h][n] = src[(size_t)h * HD * NHW + n];
    }
    __syncthreads();

    if (s == 0) {
        float* dst = g_q2 + ((size_t)bh * HD) * NHW + (size_t)d_lo * 128;
        for (int i = threadIdx.x; i < 64 * 128; i += 256) {
            int d2 = i >> 7, j = i & 127;
            dst[(size_t)d2 * NHW + j] = sm[d2 & 7][j * 8 + (d2 >> 3)];
        }
    } else if (s == 1) {
        // K transposed: word (n2, d2pair) — coalesced bf16x2 stores
        unsigned* dst = reinterpret_cast<unsigned*>(
            g_kbf + ((size_t)bh * NHW + (size_t)d_lo * 128) * HD);
        for (int i = threadIdx.x; i < 128 * 32; i += 256) {
            int jj = i >> 5, pr = i & 31;
            int d2 = 2 * pr;
            float lo = sm[d2 & 7][jj * 8 + (d2 >> 3)];
            float hi = sm[(d2 + 1) & 7][jj * 8 + ((d2 + 1) >> 3)];
            dst[jj * 32 + pr] = packbf(lo, hi);
        }
    } else {
        // V: [d2][n2] bf16, pack adjacent n2
        unsigned* dst = reinterpret_cast<unsigned*>(
            g_vbf + (size_t)bh * HD * NHW + (size_t)d_lo * 128);
        for (int i = threadIdx.x; i < 64 * 64; i += 256) {
            int d2 = i >> 6, jp = i & 63;
            int jj = 2 * jp;
            float lo = sm[d2 & 7][jj * 8 + (d2 >> 3)];
            float hi = sm[d2 & 7][(jj + 1) * 8 + (d2 >> 3)];
            dst[d2 * (NHW / 2) + jp] = packbf(lo, hi);
        }
    }
}

// ============================================================
// Fused flash attention v5 — all-bf16 mma, cp.async double buffer.
// K smem: raw [j][d] bf16 rows (64+8pad bf16 = 36 words) — col-major B
// for S. V smem: raw [d][j] bf16 rows (36 words) — col-major B for PV.
// Q bf16 a-frags in regs. Zero pack ALU in the loop; conflict-free LDS.32.
// smem 36KB, 2 CTAs/SM.
// ============================================================
#define KVSTRIDE 36   // words per row (32 data + 4 pad)

__global__ void __launch_bounds__(256, 2) flash_kernel()
{
    __shared__ unsigned kbuf[2][64 * KVSTRIDE];   // 18 KB
    __shared__ unsigned vbuf[2][64 * KVSTRIDE];   // 18 KB

    int bh    = blockIdx.x >> 3;
    int qtile = blockIdx.x & 7;
    int b = bh >> 3, r = bh & 7;

    const float* Q = g_q2 + (size_t)bh * HD * NHW;
    const __nv_bfloat16* Kp = g_kbf + (size_t)bh * NHW * HD;
    const __nv_bfloat16* Vp = g_vbf + (size_t)bh * HD * NHW;

    int t = threadIdx.x;
    int w = t >> 5, lane = t & 31;
    int gid = lane >> 2, tig = lane & 3;
    int i0w = w * 16;
    int i_glob = qtile * 128;
    int ibase = i_glob + i0w + gid;

    // ---- Q bf16 a-fragments (one-time): a-frag(ds): rows d=ds*16+2tig.. ----
    unsigned qa[4][4];
    #pragma unroll
    for (int ds = 0; ds < 4; ds++) {
        int d0 = ds * 16 + 2 * tig;
        const float* r0 = Q + (size_t)d0 * NHW + ibase;
        const float* r1 = r0 + NHW;
        const float* r2 = Q + (size_t)(d0 + 8) * NHW + ibase;
        const float* r3 = r2 + NHW;
        qa[ds][0] = packbf(r0[0], r1[0]);
        qa[ds][1] = packbf(r0[8], r1[8]);
        qa[ds][2] = packbf(r2[0], r3[0]);
        qa[ds][3] = packbf(r2[8], r3[8]);
    }

    float acc_o[8][4];
    #pragma unroll
    for (int i = 0; i < 8; i++)
        #pragma unroll
        for (int c = 0; c < 4; c++) acc_o[i][c] = 0.f;
    float row_m0 = -1e30f, row_m1 = -1e30f;
    float row_l0 = 0.f, row_l1 = 0.f;
    const float scale = 0.125f;

    auto load_tiles = [&](int s, int kt) {
        int j0 = kt * 64;
        #pragma unroll
        for (int h = 0; h < 2; h++) {
            int ca = t + h * 256;
            int row = ca >> 3, ch = ca & 7;
            cp16((unsigned)__cvta_generic_to_shared(&kbuf[s][row * KVSTRIDE + ch * 4]),
                 Kp + (size_t)(j0 + row) * HD + ch * 8);
            cp16((unsigned)__cvta_generic_to_shared(&vbuf[s][row * KVSTRIDE + ch * 4]),
                 Vp + (size_t)row * NHW + j0 + ch * 8);
        }
    };

    load_tiles(0, 0);
    asm volatile("cp.async.commit_group;");

    for (int kt = 0; kt < 16; kt++) {
        int s = kt & 1;
        if (kt + 1 < 16) {
            load_tiles(s ^ 1, kt + 1);
            asm volatile("cp.async.commit_group;");
            asm volatile("cp.async.wait_group 1;");
        } else {
            asm volatile("cp.async.wait_group 0;");
        }
        __syncthreads();

        // ---- S = Q^T K (bf16 k16): warp rows x 64 cols ----
        float p[8][4];
        #pragma unroll
        for (int i = 0; i < 8; i++)
            #pragma unroll
            for (int c = 0; c < 4; c++) p[i][c] = 0.f;

        #pragma unroll
        for (int ds = 0; ds < 4; ds++) {
            #pragma unroll
            for (int nf = 0; nf < 8; nf++) {
                unsigned bb[2];
                const unsigned* kr = &kbuf[s][(nf * 8 + gid) * KVSTRIDE + ds * 8 + tig];
                bb[0] = kr[0];
                bb[1] = kr[4];
                mma_bf16(p[nf], qa[ds], bb);
            }
        }

        // ---- online softmax ----
        float tmax0 = -1e30f, tmax1 = -1e30f;
        #pragma unroll
        for (int nf = 0; nf < 8; nf++) {
            tmax0 = fmaxf(tmax0, fmaxf(p[nf][0], p[nf][1]));
            tmax1 = fmaxf(tmax1, fmaxf(p[nf][2], p[nf][3]));
        }
        tmax0 = fmaxf(tmax0, __shfl_xor_sync(~0u, tmax0, 1));
        tmax0 = fmaxf(tmax0, __shfl_xor_sync(~0u, tmax0, 2));
        tmax1 = fmaxf(tmax1, __shfl_xor_sync(~0u, tmax1, 1));
        tmax1 = fmaxf(tmax1, __shfl_xor_sync(~0u, tmax1, 2));

        float nm0 = fmaxf(row_m0, tmax0 * scale);
        float nm1 = fmaxf(row_m1, tmax1 * scale);
        float corr0 = __expf(row_m0 - nm0);
        float corr1 = __expf(row_m1 - nm1);

        float sum0 = 0.f, sum1 = 0.f;
        #pragma unroll
        for (int nf = 0; nf < 8; nf++) {
            p[nf][0] = __expf(p[nf][0] * scale - nm0);
            p[nf][1] = __expf(p[nf][1] * scale - nm0);
            p[nf][2] = __expf(p[nf][2] * scale - nm1);
            p[nf][3] = __expf(p[nf][3] * scale - nm1);
            sum0 += p[nf][0] + p[nf][1];
            sum1 += p[nf][2] + p[nf][3];
        }
        sum0 += __shfl_xor_sync(~0u, sum0, 1);
        sum0 += __shfl_xor_sync(~0u, sum0, 2);
        sum1 += __shfl_xor_sync(~0u, sum1, 1);
        sum1 += __shfl_xor_sync(~0u, sum1, 2);

        row_l0 = row_l0 * corr0 + sum0;
        row_l1 = row_l1 * corr1 + sum1;
        row_m0 = nm0; row_m1 = nm1;

        #pragma unroll
        for (int nf2 = 0; nf2 < 8; nf2++) {
            acc_o[nf2][0] *= corr0; acc_o[nf2][1] *= corr0;
            acc_o[nf2][2] *= corr1; acc_o[nf2][3] *= corr1;
        }

        // ---- O += P V^T (bf16 k16): S c-frag == bf16 a-frag ----
        #pragma unroll
        for (int js = 0; js < 4; js++) {
            unsigned pa[4];
            pa[0] = packbf(p[2 * js][0],     p[2 * js][1]);
            pa[1] = packbf(p[2 * js][2],     p[2 * js][3]);
            pa[2] = packbf(p[2 * js + 1][0], p[2 * js + 1][1]);
            pa[3] = packbf(p[2 * js + 1][2], p[2 * js + 1][3]);
            #pragma unroll
            for (int nf2 = 0; nf2 < 8; nf2++) {
                unsigned bb[2];
                const unsigned* vr = &vbuf[s][(nf2 * 8 + gid) * KVSTRIDE + js * 8 + tig];
                bb[0] = vr[0];
                bb[1] = vr[4];
                mma_bf16(acc_o[nf2], pa, bb);
            }
        }
        __syncthreads();
    }

    // ---- epilogue: O /= l, write to g_h[b][r*64+d][i] ----
    float inv0 = 1.f / row_l0, inv1 = 1.f / row_l1;
    float* O = g_h + ((size_t)b * NC + r * HD) * NHW;
    int i0 = ibase;
    #pragma unroll
    for (int nf2 = 0; nf2 < 8; nf2++) {
        int d0 = nf2 * 8 + 2 * tig;
        O[(size_t)d0 * NHW + i0]           = acc_o[nf2][0] * inv0;
        O[(size_t)(d0 + 1) * NHW + i0]     = acc_o[nf2][1] * inv0;
        O[(size_t)d0 * NHW + i0 + 8]       = acc_o[nf2][2] * inv1;
        O[(size_t)(d0 + 1) * NHW + i0 + 8] = acc_o[nf2][3] * inv1;
    }
}

// ============================================================
extern "C" void kernel_launch(void* const* d_in, const int* in_sizes, int n_in,
                              void* d_out, int out_size)
{
    const float* x      = (const float*)d_in[0];
    const float* gn_w   = (const float*)d_in[1];
    const float* gn_b   = (const float*)d_in[2];
    const float* qkv_w  = (const float*)d_in[3];
    const float* proj_w = (const float*)d_in[4];
    const float* proj_b = (const float*)d_in[5];
    float* out = (float*)d_out;

    gn_kernel<<<NB * NG, 256>>>(x, gn_w, gn_b);
    gemm_tc<0><<<dim3(8, 12, NB), 256>>>(qkv_w, nullptr, nullptr);
    permute_kernel<<<NB * NHEADS * 3 * 8, 256>>>();
    flash_kernel<<<NB * NHEADS * 8, 256>>>();
    gemm_tc<1><<<dim3(8, 4, NB), 256>>>(proj_w, proj_b, out);
}

// round 8
// speedup vs baseline: 8.1364x; 1.4103x over previous
#include <cuda_runtime.h>
#include <cuda_bf16.h>
#include <math.h>

#define NB 16
#define NC 512
#define NHW 1024
#define NHEADS 8
#define HD 64
#define NG 32
#define CPG 16

// ---- scratch ----
__device__ float g_xgn[(size_t)NB * NC * NHW];                  //  33.5 MB fp32 (residual)
__device__ unsigned g_xbf[(size_t)NB * (NC / 2) * NHW];         //  33.5 MB bf16x2 packed [b][c/2][n]
__device__ float g_qkv[(size_t)NB * 3 * NC * NHW];              // 100.7 MB fp32 [b][o][n]
__device__ float g_q2[(size_t)NB * NHEADS * HD * NHW];          //  33.5 MB fp32 Q [bh][d2][n2]
__device__ __nv_bfloat16 g_kbf[(size_t)NB * NHEADS * NHW * HD]; //  16.8 MB bf16 K [bh][n2][d2]
__device__ __nv_bfloat16 g_vbf[(size_t)NB * NHEADS * HD * NHW]; //  16.8 MB bf16 V [bh][d2][n2]
__device__ unsigned g_hbf[(size_t)NB * (NC / 2) * NHW];         //  33.5 MB bf16x2 packed h
__device__ unsigned g_wqkv[3 * NC * NC / 2];                    //   1.5 MB bf16 qkv_w
__device__ unsigned g_wproj[NC * NC / 2];                       //   0.5 MB bf16 proj_w

// ---- helpers ----
__device__ __forceinline__ void mma_bf16(float* c, const unsigned* a, const unsigned* b) {
    asm volatile(
        "mma.sync.aligned.m16n8k16.row.col.f32.bf16.bf16.f32 "
        "{%0,%1,%2,%3}, {%4,%5,%6,%7}, {%8,%9}, {%0,%1,%2,%3};"
        : "+f"(c[0]), "+f"(c[1]), "+f"(c[2]), "+f"(c[3])
        : "r"(a[0]), "r"(a[1]), "r"(a[2]), "r"(a[3]), "r"(b[0]), "r"(b[1]));
}
// packed bf16x2: low half = lo, high half = hi
__device__ __forceinline__ unsigned packbf(float lo, float hi) {
    unsigned d;
    asm("cvt.rn.bf16x2.f32 %0, %1, %2;" : "=r"(d) : "f"(hi), "f"(lo));
    return d;
}
__device__ __forceinline__ void cp16(unsigned dst, const void* src) {
    asm volatile("cp.async.cg.shared.global [%0], [%1], 16;" :: "r"(dst), "l"(src));
}

// ============================================================
// Weight pre-pack: fp32 -> bf16 [m][k]
// ============================================================
__global__ void __launch_bounds__(256) convw_kernel(const float* __restrict__ qkvw,
                                                    const float* __restrict__ projw)
{
    int i = blockIdx.x * 256 + threadIdx.x;
    const int NQ = 3 * NC * NC / 4;   // float4 count
    const int NP = NC * NC / 4;
    if (i < NQ) {
        float4 v = reinterpret_cast<const float4*>(qkvw)[i];
        uint2 o = make_uint2(packbf(v.x, v.y), packbf(v.z, v.w));
        reinterpret_cast<uint2*>(g_wqkv)[i] = o;
    } else if (i < NQ + NP) {
        int j = i - NQ;
        float4 v = reinterpret_cast<const float4*>(projw)[j];
        uint2 o = make_uint2(packbf(v.x, v.y), packbf(v.z, v.w));
        reinterpret_cast<uint2*>(g_wproj)[j] = o;
    }
}

// ============================================================
// GroupNorm: fp32 out (residual) + packed bf16x2 out (GEMM B operand)
// ============================================================
__global__ void __launch_bounds__(256) gn_kernel(const float* __restrict__ x,
                                                 const float* __restrict__ w,
                                                 const float* __restrict__ bias)
{
    int b = blockIdx.x >> 5;
    int g = blockIdx.x & 31;
    const float* xp = x + ((size_t)b * NC + g * CPG) * NHW;

    float s = 0.f, s2 = 0.f;
    for (int i = threadIdx.x; i < CPG * NHW; i += 256) {
        float v = xp[i];
        s += v; s2 += v * v;
    }
    __shared__ float r0[8], r1[8];
    #pragma unroll
    for (int o = 16; o; o >>= 1) {
        s  += __shfl_xor_sync(~0u, s,  o);
        s2 += __shfl_xor_sync(~0u, s2, o);
    }
    int wid = threadIdx.x >> 5, lid = threadIdx.x & 31;
    if (lid == 0) { r0[wid] = s; r1[wid] = s2; }
    __syncthreads();
    if (threadIdx.x < 32) {
        s  = (lid < 8) ? r0[lid] : 0.f;
        s2 = (lid < 8) ? r1[lid] : 0.f;
        #pragma unroll
        for (int o = 4; o; o >>= 1) {
            s  += __shfl_xor_sync(~0u, s,  o);
            s2 += __shfl_xor_sync(~0u, s2, o);
        }
        if (lid == 0) { r0[0] = s; r1[0] = s2; }
    }
    __syncthreads();
    const float inv_n = 1.f / (CPG * NHW);
    float mean = r0[0] * inv_n;
    float var  = r1[0] * inv_n - mean * mean;
    float rinv = rsqrtf(var + 1e-5f);

    float* op = g_xgn + ((size_t)b * NC + g * CPG) * NHW;
    unsigned* xb = g_xbf + ((size_t)b * (NC / 2) + g * (CPG / 2)) * NHW;
    for (int i = threadIdx.x; i < (CPG / 2) * NHW; i += 256) {
        int ul = i >> 10, n = i & 1023;
        int c0 = g * CPG + 2 * ul;
        float v0 = (xp[(2 * ul) * NHW + n]     - mean) * rinv * w[c0]     + bias[c0];
        float v1 = (xp[(2 * ul + 1) * NHW + n] - mean) * rinv * w[c0 + 1] + bias[c0 + 1];
        op[(2 * ul) * NHW + n]     = v0;
        op[(2 * ul + 1) * NHW + n] = v1;
        xb[ul * NHW + n] = packbf(v0, v1);
    }
}

// ============================================================
// bf16 tensor-core GEMM NN, cp.async 2-stage, fp32 accumulate.
// C[b][m][n] = sum_k W[m][k] X[b][k][n]
// MODE 0: qkv (A=g_wqkv, B=g_xbf, C=g_qkv fp32)
// MODE 1: proj (A=g_wproj, B=g_hbf, C=out + bias + residual g_xgn)
// CTA 128x128, BK=32, 8 warps 2(m)x4(n).
// A smem [m][kpair] stride 20 wd; B smem [kpair][n] stride 136 wd.
// ============================================================
template <int MODE>
__global__ void __launch_bounds__(256, 2) gemm_bf(const float* __restrict__ pbias,
                                                  float* __restrict__ outp)
{
    const int M  = MODE ? NC : 3 * NC;
    const unsigned* Aw = MODE ? g_wproj : g_wqkv;
    float* Cout        = MODE ? outp : g_qkv;

    int b  = blockIdx.z;
    int m0 = blockIdx.y << 7;
    int n0 = blockIdx.x << 7;
    const unsigned* Bw = (MODE ? g_hbf : g_xbf) + (size_t)b * (NC / 2) * NHW;

    __shared__ unsigned As[2][128][20];
    __shared__ unsigned Bs[2][16][136];

    int t = threadIdx.x;
    int w = t >> 5, lane = t & 31;
    int gid = lane >> 2, tig = lane & 3;
    int mw = (w >> 2) * 64;
    int nw = (w & 3) * 32;

    float acc[4][4][4];
    #pragma unroll
    for (int i = 0; i < 4; i++)
        #pragma unroll
        for (int j = 0; j < 4; j++)
            #pragma unroll
            for (int c = 0; c < 4; c++) acc[i][j][c] = 0.f;

    auto load_stage = [&](int s, int kp0) {
        #pragma unroll
        for (int h = 0; h < 2; h++) {
            int ca = t + h * 256;
            // A: 128 rows x 16 words; 4 cp16 per row
            int m = ca >> 2, kq = ca & 3;
            cp16((unsigned)__cvta_generic_to_shared(&As[s][m][kq * 4]),
                 Aw + (size_t)(m0 + m) * (NC / 2) + kp0 + kq * 4);
            // B: 16 rows x 128 words; 32 cp16 per row
            int kp = ca >> 5, nq = (ca & 31) * 4;
            cp16((unsigned)__cvta_generic_to_shared(&Bs[s][kp][nq]),
                 Bw + (size_t)(kp0 + kp) * NHW + n0 + nq);
        }
    };

    load_stage(0, 0);
    asm volatile("cp.async.commit_group;");

    const int NIT = (NC / 2) / 16;   // 16
    for (int it = 0; it < NIT; it++) {
        int s = it & 1;
        if (it + 1 < NIT) {
            load_stage(s ^ 1, (it + 1) * 16);
            asm volatile("cp.async.commit_group;");
            asm volatile("cp.async.wait_group 1;");
        } else {
            asm volatile("cp.async.wait_group 0;");
        }
        __syncthreads();

        #pragma unroll
        for (int c2 = 0; c2 < 2; c2++) {
            unsigned a[4][4], bb[4][2];
            #pragma unroll
            for (int mf = 0; mf < 4; mf++) {
                int mi = mw + mf * 16 + gid;
                a[mf][0] = As[s][mi][c2 * 8 + tig];
                a[mf][1] = As[s][mi + 8][c2 * 8 + tig];
                a[mf][2] = As[s][mi][c2 * 8 + tig + 4];
                a[mf][3] = As[s][mi + 8][c2 * 8 + tig + 4];
            }
            #pragma unroll
            for (int nf = 0; nf < 4; nf++) {
                int ni = nw + nf * 8 + gid;
                bb[nf][0] = Bs[s][c2 * 8 + tig][ni];
                bb[nf][1] = Bs[s][c2 * 8 + tig + 4][ni];
            }
            #pragma unroll
            for (int mf = 0; mf < 4; mf++)
                #pragma unroll
                for (int nf = 0; nf < 4; nf++)
                    mma_bf16(acc[mf][nf], a[mf], bb[nf]);
        }
        __syncthreads();
    }

    #pragma unroll
    for (int mf = 0; mf < 4; mf++) {
        int gm = m0 + mw + mf * 16 + gid;
        #pragma unroll
        for (int nf = 0; nf < 4; nf++) {
            int gn = n0 + nw + nf * 8 + 2 * tig;
            float2 v01 = make_float2(acc[mf][nf][0], acc[mf][nf][1]);
            float2 v23 = make_float2(acc[mf][nf][2], acc[mf][nf][3]);
            if (MODE) {
                float pb0 = pbias[gm], pb1 = pbias[gm + 8];
                const float* xg0 = &g_xgn[((size_t)b * NC + gm) * NHW + gn];
                const float* xg1 = &g_xgn[((size_t)b * NC + gm + 8) * NHW + gn];
                v01.x += pb0 + xg0[0]; v01.y += pb0 + xg0[1];
                v23.x += pb1 + xg1[0]; v23.y += pb1 + xg1[1];
            }
            *reinterpret_cast<float2*>(&Cout[((size_t)b * M + gm) * NHW + gn]) = v01;
            *reinterpret_cast<float2*>(&Cout[((size_t)b * M + gm + 8) * NHW + gn]) = v23;
        }
    }
}

// ============================================================
// Permute qkv -> attention layouts.
// Q: fp32 [bh][d2][n2]; K: bf16 [bh][n2][d2]; V: bf16 [bh][d2][n2].
// value(d2, n2 = d_lo*128+jj) = sm[d2&7][jj*8 + (d2>>3)]
// ============================================================
__global__ void __launch_bounds__(256) permute_kernel()
{
    int blk  = blockIdx.x;
    int d_lo = blk & 7;
    int s    = (blk >> 3) % 3;
    int bh   = blk / 24;
    int b = bh >> 3, r = bh & 7;

    __shared__ float sm[8][1024];
    const float* src = g_qkv + ((size_t)b * 3 * NC + s * NC + r * 8 + d_lo) * NHW;
    for (int i = threadIdx.x; i < 8 * 1024; i += 256) {
        int h = i >> 10, n = i & 1023;
        sm[h][n] = src[(size_t)h * HD * NHW + n];
    }
    __syncthreads();

    if (s == 0) {
        float* dst = g_q2 + ((size_t)bh * HD) * NHW + (size_t)d_lo * 128;
        for (int i = threadIdx.x; i < 64 * 128; i += 256) {
            int d2 = i >> 7, j = i & 127;
            dst[(size_t)d2 * NHW + j] = sm[d2 & 7][j * 8 + (d2 >> 3)];
        }
    } else if (s == 1) {
        unsigned* dst = reinterpret_cast<unsigned*>(
            g_kbf + ((size_t)bh * NHW + (size_t)d_lo * 128) * HD);
        for (int i = threadIdx.x; i < 128 * 32; i += 256) {
            int jj = i >> 5, pr = i & 31;
            int d2 = 2 * pr;
            float lo = sm[d2 & 7][jj * 8 + (d2 >> 3)];
            float hi = sm[(d2 + 1) & 7][jj * 8 + ((d2 + 1) >> 3)];
            dst[jj * 32 + pr] = packbf(lo, hi);
        }
    } else {
        unsigned* dst = reinterpret_cast<unsigned*>(
            g_vbf + (size_t)bh * HD * NHW + (size_t)d_lo * 128);
        for (int i = threadIdx.x; i < 64 * 64; i += 256) {
            int d2 = i >> 6, jp = i & 63;
            int jj = 2 * jp;
            float lo = sm[d2 & 7][jj * 8 + (d2 >> 3)];
            float hi = sm[d2 & 7][(jj + 1) * 8 + (d2 >> 3)];
            dst[d2 * (NHW / 2) + jp] = packbf(lo, hi);
        }
    }
}

// ============================================================
// Fused flash attention v5 — all-bf16 mma, cp.async double buffer.
// Epilogue writes packed bf16x2 h (proj's B operand).
// ============================================================
#define KVSTRIDE 36   // words per row (32 data + 4 pad)

__global__ void __launch_bounds__(256, 2) flash_kernel()
{
    __shared__ unsigned kbuf[2][64 * KVSTRIDE];
    __shared__ unsigned vbuf[2][64 * KVSTRIDE];

    int bh    = blockIdx.x >> 3;
    int qtile = blockIdx.x & 7;
    int b = bh >> 3, r = bh & 7;

    const float* Q = g_q2 + (size_t)bh * HD * NHW;
    const __nv_bfloat16* Kp = g_kbf + (size_t)bh * NHW * HD;
    const __nv_bfloat16* Vp = g_vbf + (size_t)bh * HD * NHW;

    int t = threadIdx.x;
    int w = t >> 5, lane = t & 31;
    int gid = lane >> 2, tig = lane & 3;
    int i0w = w * 16;
    int i_glob = qtile * 128;
    int ibase = i_glob + i0w + gid;

    unsigned qa[4][4];
    #pragma unroll
    for (int ds = 0; ds < 4; ds++) {
        int d0 = ds * 16 + 2 * tig;
        const float* r0 = Q + (size_t)d0 * NHW + ibase;
        const float* r1 = r0 + NHW;
        const float* r2 = Q + (size_t)(d0 + 8) * NHW + ibase;
        const float* r3 = r2 + NHW;
        qa[ds][0] = packbf(r0[0], r1[0]);
        qa[ds][1] = packbf(r0[8], r1[8]);
        qa[ds][2] = packbf(r2[0], r3[0]);
        qa[ds][3] = packbf(r2[8], r3[8]);
    }

    float acc_o[8][4];
    #pragma unroll
    for (int i = 0; i < 8; i++)
        #pragma unroll
        for (int c = 0; c < 4; c++) acc_o[i][c] = 0.f;
    float row_m0 = -1e30f, row_m1 = -1e30f;
    float row_l0 = 0.f, row_l1 = 0.f;
    const float scale = 0.125f;

    auto load_tiles = [&](int s, int kt) {
        int j0 = kt * 64;
        #pragma unroll
        for (int h = 0; h < 2; h++) {
            int ca = t + h * 256;
            int row = ca >> 3, ch = ca & 7;
            cp16((unsigned)__cvta_generic_to_shared(&kbuf[s][row * KVSTRIDE + ch * 4]),
                 Kp + (size_t)(j0 + row) * HD + ch * 8);
            cp16((unsigned)__cvta_generic_to_shared(&vbuf[s][row * KVSTRIDE + ch * 4]),
                 Vp + (size_t)row * NHW + j0 + ch * 8);
        }
    };

    load_tiles(0, 0);
    asm volatile("cp.async.commit_group;");

    for (int kt = 0; kt < 16; kt++) {
        int s = kt & 1;
        if (kt + 1 < 16) {
            load_tiles(s ^ 1, kt + 1);
            asm volatile("cp.async.commit_group;");
            asm volatile("cp.async.wait_group 1;");
        } else {
            asm volatile("cp.async.wait_group 0;");
        }
        __syncthreads();

        float p[8][4];
        #pragma unroll
        for (int i = 0; i < 8; i++)
            #pragma unroll
            for (int c = 0; c < 4; c++) p[i][c] = 0.f;

        #pragma unroll
        for (int ds = 0; ds < 4; ds++) {
            #pragma unroll
            for (int nf = 0; nf < 8; nf++) {
                unsigned bb[2];
                const unsigned* kr = &kbuf[s][(nf * 8 + gid) * KVSTRIDE + ds * 8 + tig];
                bb[0] = kr[0];
                bb[1] = kr[4];
                mma_bf16(p[nf], qa[ds], bb);
            }
        }

        float tmax0 = -1e30f, tmax1 = -1e30f;
        #pragma unroll
        for (int nf = 0; nf < 8; nf++) {
            tmax0 = fmaxf(tmax0, fmaxf(p[nf][0], p[nf][1]));
            tmax1 = fmaxf(tmax1, fmaxf(p[nf][2], p[nf][3]));
        }
        tmax0 = fmaxf(tmax0, __shfl_xor_sync(~0u, tmax0, 1));
        tmax0 = fmaxf(tmax0, __shfl_xor_sync(~0u, tmax0, 2));
        tmax1 = fmaxf(tmax1, __shfl_xor_sync(~0u, tmax1, 1));
        tmax1 = fmaxf(tmax1, __shfl_xor_sync(~0u, tmax1, 2));

        float nm0 = fmaxf(row_m0, tmax0 * scale);
        float nm1 = fmaxf(row_m1, tmax1 * scale);
        float corr0 = __expf(row_m0 - nm0);
        float corr1 = __expf(row_m1 - nm1);

        float sum0 = 0.f, sum1 = 0.f;
        #pragma unroll
        for (int nf = 0; nf < 8; nf++) {
            p[nf][0] = __expf(p[nf][0] * scale - nm0);
            p[nf][1] = __expf(p[nf][1] * scale - nm0);
            p[nf][2] = __expf(p[nf][2] * scale - nm1);
            p[nf][3] = __expf(p[nf][3] * scale - nm1);
            sum0 += p[nf][0] + p[nf][1];
            sum1 += p[nf][2] + p[nf][3];
        }
        sum0 += __shfl_xor_sync(~0u, sum0, 1);
        sum0 += __shfl_xor_sync(~0u, sum0, 2);
        sum1 += __shfl_xor_sync(~0u, sum1, 1);
        sum1 += __shfl_xor_sync(~0u, sum1, 2);

        row_l0 = row_l0 * corr0 + sum0;
        row_l1 = row_l1 * corr1 + sum1;
        row_m0 = nm0; row_m1 = nm1;

        #pragma unroll
        for (int nf2 = 0; nf2 < 8; nf2++) {
            acc_o[nf2][0] *= corr0; acc_o[nf2][1] *= corr0;
            acc_o[nf2][2] *= corr1; acc_o[nf2][3] *= corr1;
        }

        #pragma unroll
        for (int js = 0; js < 4; js++) {
            unsigned pa[4];
            pa[0] = packbf(p[2 * js][0],     p[2 * js][1]);
            pa[1] = packbf(p[2 * js][2],     p[2 * js][3]);
            pa[2] = packbf(p[2 * js + 1][0], p[2 * js + 1][1]);
            pa[3] = packbf(p[2 * js + 1][2], p[2 * js + 1][3]);
            #pragma unroll
            for (int nf2 = 0; nf2 < 8; nf2++) {
                unsigned bb[2];
                const unsigned* vr = &vbuf[s][(nf2 * 8 + gid) * KVSTRIDE + js * 8 + tig];
                bb[0] = vr[0];
                bb[1] = vr[4];
                mma_bf16(acc_o[nf2], pa, bb);
            }
        }
        __syncthreads();
    }

    // ---- epilogue: O /= l, write packed bf16x2 into g_hbf ----
    float inv0 = 1.f / row_l0, inv1 = 1.f / row_l1;
    unsigned* Hb = g_hbf + ((size_t)b * (NC / 2) + r * (HD / 2)) * NHW;
    int i0 = ibase;
    #pragma unroll
    for (int nf2 = 0; nf2 < 8; nf2++) {
        int u = nf2 * 4 + tig;   // (d0)/2 with d0 = nf2*8 + 2*tig
        Hb[(size_t)u * NHW + i0]     = packbf(acc_o[nf2][0] * inv0, acc_o[nf2][1] * inv0);
        Hb[(size_t)u * NHW + i0 + 8] = packbf(acc_o[nf2][2] * inv1, acc_o[nf2][3] * inv1);
    }
}

// ============================================================
extern "C" void kernel_launch(void* const* d_in, const int* in_sizes, int n_in,
                              void* d_out, int out_size)
{
    const float* x      = (const float*)d_in[0];
    const float* gn_w   = (const float*)d_in[1];
    const float* gn_b   = (const float*)d_in[2];
    const float* qkv_w  = (const float*)d_in[3];
    const float* proj_w = (const float*)d_in[4];
    const float* proj_b = (const float*)d_in[5];
    float* out = (float*)d_out;

    convw_kernel<<<1024, 256>>>(qkv_w, proj_w);
    gn_kernel<<<NB * NG, 256>>>(x, gn_w, gn_b);
    gemm_bf<0><<<dim3(8, 12, NB), 256>>>(nullptr, nullptr);
    permute_kernel<<<NB * NHEADS * 3 * 8, 256>>>();
    flash_kernel<<<NB * NHEADS * 8, 256>>>();
    gemm_bf<1><<<dim3(8, 4, NB), 256>>>(proj_b, out);
}

// round 9
// speedup vs baseline: 8.9305x; 1.0976x over previous
#include <cuda_runtime.h>
#include <cuda_bf16.h>
#include <math.h>

#define NB 16
#define NC 512
#define NHW 1024
#define NHEADS 8
#define HD 64
#define NG 32
#define CPG 16

// ---- scratch ----
__device__ float g_xgn[(size_t)NB * NC * NHW];                  //  33.5 MB fp32 (residual)
__device__ unsigned g_xbf[(size_t)NB * (NC / 2) * NHW];         //  33.5 MB bf16x2 [b][c/2][n] (k-packed)
__device__ unsigned g_qkvbf[(size_t)NB * 3 * NC * (NHW / 2)];   //  50.3 MB bf16x2 [b][o][n/2] (n-packed)
__device__ __nv_bfloat16 g_qbf[(size_t)NB * NHEADS * NHW * HD]; //  16.8 MB bf16 Q [bh][n2][d2]
__device__ __nv_bfloat16 g_kbf[(size_t)NB * NHEADS * NHW * HD]; //  16.8 MB bf16 K [bh][n2][d2]
__device__ __nv_bfloat16 g_vbf[(size_t)NB * NHEADS * HD * NHW]; //  16.8 MB bf16 V [bh][d2][n2]
__device__ unsigned g_hbf[(size_t)NB * (NC / 2) * NHW];         //  33.5 MB bf16x2 packed h (k-packed)
__device__ unsigned g_wqkv[3 * NC * NC / 2];                    //   1.5 MB bf16 qkv_w
__device__ unsigned g_wproj[NC * NC / 2];                       //   0.5 MB bf16 proj_w

// ---- helpers ----
__device__ __forceinline__ void mma_bf16(float* c, const unsigned* a, const unsigned* b) {
    asm volatile(
        "mma.sync.aligned.m16n8k16.row.col.f32.bf16.bf16.f32 "
        "{%0,%1,%2,%3}, {%4,%5,%6,%7}, {%8,%9}, {%0,%1,%2,%3};"
        : "+f"(c[0]), "+f"(c[1]), "+f"(c[2]), "+f"(c[3])
        : "r"(a[0]), "r"(a[1]), "r"(a[2]), "r"(a[3]), "r"(b[0]), "r"(b[1]));
}
// packed bf16x2: low half = lo, high half = hi
__device__ __forceinline__ unsigned packbf(float lo, float hi) {
    unsigned d;
    asm("cvt.rn.bf16x2.f32 %0, %1, %2;" : "=r"(d) : "f"(hi), "f"(lo));
    return d;
}
__device__ __forceinline__ void cp16(unsigned dst, const void* src) {
    asm volatile("cp.async.cg.shared.global [%0], [%1], 16;" :: "r"(dst), "l"(src));
}

// ============================================================
// Weight pre-pack: fp32 -> bf16 [m][k]
// ============================================================
__global__ void __launch_bounds__(256) convw_kernel(const float* __restrict__ qkvw,
                                                    const float* __restrict__ projw)
{
    int i = blockIdx.x * 256 + threadIdx.x;
    const int NQ = 3 * NC * NC / 4;
    const int NP = NC * NC / 4;
    if (i < NQ) {
        float4 v = reinterpret_cast<const float4*>(qkvw)[i];
        reinterpret_cast<uint2*>(g_wqkv)[i] = make_uint2(packbf(v.x, v.y), packbf(v.z, v.w));
    } else if (i < NQ + NP) {
        int j = i - NQ;
        float4 v = reinterpret_cast<const float4*>(projw)[j];
        reinterpret_cast<uint2*>(g_wproj)[j] = make_uint2(packbf(v.x, v.y), packbf(v.z, v.w));
    }
}

// ============================================================
// GroupNorm: fp32 out (residual) + bf16x2 k-packed out (GEMM B)
// ============================================================
__global__ void __launch_bounds__(256) gn_kernel(const float* __restrict__ x,
                                                 const float* __restrict__ w,
                                                 const float* __restrict__ bias)
{
    int b = blockIdx.x >> 5;
    int g = blockIdx.x & 31;
    const float* xp = x + ((size_t)b * NC + g * CPG) * NHW;

    float s = 0.f, s2 = 0.f;
    for (int i = threadIdx.x; i < CPG * NHW; i += 256) {
        float v = xp[i];
        s += v; s2 += v * v;
    }
    __shared__ float r0[8], r1[8];
    #pragma unroll
    for (int o = 16; o; o >>= 1) {
        s  += __shfl_xor_sync(~0u, s,  o);
        s2 += __shfl_xor_sync(~0u, s2, o);
    }
    int wid = threadIdx.x >> 5, lid = threadIdx.x & 31;
    if (lid == 0) { r0[wid] = s; r1[wid] = s2; }
    __syncthreads();
    if (threadIdx.x < 32) {
        s  = (lid < 8) ? r0[lid] : 0.f;
        s2 = (lid < 8) ? r1[lid] : 0.f;
        #pragma unroll
        for (int o = 4; o; o >>= 1) {
            s  += __shfl_xor_sync(~0u, s,  o);
            s2 += __shfl_xor_sync(~0u, s2, o);
        }
        if (lid == 0) { r0[0] = s; r1[0] = s2; }
    }
    __syncthreads();
    const float inv_n = 1.f / (CPG * NHW);
    float mean = r0[0] * inv_n;
    float var  = r1[0] * inv_n - mean * mean;
    float rinv = rsqrtf(var + 1e-5f);

    float* op = g_xgn + ((size_t)b * NC + g * CPG) * NHW;
    unsigned* xb = g_xbf + ((size_t)b * (NC / 2) + g * (CPG / 2)) * NHW;
    for (int i = threadIdx.x; i < (CPG / 2) * NHW; i += 256) {
        int ul = i >> 10, n = i & 1023;
        int c0 = g * CPG + 2 * ul;
        float v0 = (xp[(2 * ul) * NHW + n]     - mean) * rinv * w[c0]     + bias[c0];
        float v1 = (xp[(2 * ul + 1) * NHW + n] - mean) * rinv * w[c0 + 1] + bias[c0 + 1];
        op[(2 * ul) * NHW + n]     = v0;
        op[(2 * ul + 1) * NHW + n] = v1;
        xb[ul * NHW + n] = packbf(v0, v1);
    }
}

// ============================================================
// bf16 GEMM NN, cp.async 2-stage, fp32 accumulate.
// MODE 0: qkv -> g_qkvbf bf16x2 n-packed
// MODE 1: proj -> out fp32 (+bias +residual g_xgn)
// ============================================================
template <int MODE>
__global__ void __launch_bounds__(256, 2) gemm_bf(const float* __restrict__ pbias,
                                                  float* __restrict__ outp)
{
    const unsigned* Aw = MODE ? g_wproj : g_wqkv;

    int b  = blockIdx.z;
    int m0 = blockIdx.y << 7;
    int n0 = blockIdx.x << 7;
    const unsigned* Bw = (MODE ? g_hbf : g_xbf) + (size_t)b * (NC / 2) * NHW;

    __shared__ unsigned As[2][128][20];
    __shared__ unsigned Bs[2][16][136];

    int t = threadIdx.x;
    int w = t >> 5, lane = t & 31;
    int gid = lane >> 2, tig = lane & 3;
    int mw = (w >> 2) * 64;
    int nw = (w & 3) * 32;

    float acc[4][4][4];
    #pragma unroll
    for (int i = 0; i < 4; i++)
        #pragma unroll
        for (int j = 0; j < 4; j++)
            #pragma unroll
            for (int c = 0; c < 4; c++) acc[i][j][c] = 0.f;

    auto load_stage = [&](int s, int kp0) {
        #pragma unroll
        for (int h = 0; h < 2; h++) {
            int ca = t + h * 256;
            int m = ca >> 2, kq = ca & 3;
            cp16((unsigned)__cvta_generic_to_shared(&As[s][m][kq * 4]),
                 Aw + (size_t)(m0 + m) * (NC / 2) + kp0 + kq * 4);
            int kp = ca >> 5, nq = (ca & 31) * 4;
            cp16((unsigned)__cvta_generic_to_shared(&Bs[s][kp][nq]),
                 Bw + (size_t)(kp0 + kp) * NHW + n0 + nq);
        }
    };

    load_stage(0, 0);
    asm volatile("cp.async.commit_group;");

    const int NIT = (NC / 2) / 16;   // 16
    for (int it = 0; it < NIT; it++) {
        int s = it & 1;
        if (it + 1 < NIT) {
            load_stage(s ^ 1, (it + 1) * 16);
            asm volatile("cp.async.commit_group;");
            asm volatile("cp.async.wait_group 1;");
        } else {
            asm volatile("cp.async.wait_group 0;");
        }
        __syncthreads();

        #pragma unroll
        for (int c2 = 0; c2 < 2; c2++) {
            unsigned a[4][4], bb[4][2];
            #pragma unroll
            for (int mf = 0; mf < 4; mf++) {
                int mi = mw + mf * 16 + gid;
                a[mf][0] = As[s][mi][c2 * 8 + tig];
                a[mf][1] = As[s][mi + 8][c2 * 8 + tig];
                a[mf][2] = As[s][mi][c2 * 8 + tig + 4];
                a[mf][3] = As[s][mi + 8][c2 * 8 + tig + 4];
            }
            #pragma unroll
            for (int nf = 0; nf < 4; nf++) {
                int ni = nw + nf * 8 + gid;
                bb[nf][0] = Bs[s][c2 * 8 + tig][ni];
                bb[nf][1] = Bs[s][c2 * 8 + tig + 4][ni];
            }
            #pragma unroll
            for (int mf = 0; mf < 4; mf++)
                #pragma unroll
                for (int nf = 0; nf < 4; nf++)
                    mma_bf16(acc[mf][nf], a[mf], bb[nf]);
        }
        __syncthreads();
    }

    #pragma unroll
    for (int mf = 0; mf < 4; mf++) {
        int gm = m0 + mw + mf * 16 + gid;
        #pragma unroll
        for (int nf = 0; nf < 4; nf++) {
            int gn = n0 + nw + nf * 8 + 2 * tig;
            if (MODE) {
                float2 v01 = make_float2(acc[mf][nf][0], acc[mf][nf][1]);
                float2 v23 = make_float2(acc[mf][nf][2], acc[mf][nf][3]);
                float pb0 = pbias[gm], pb1 = pbias[gm + 8];
                const float* xg0 = &g_xgn[((size_t)b * NC + gm) * NHW + gn];
                const float* xg1 = &g_xgn[((size_t)b * NC + gm + 8) * NHW + gn];
                v01.x += pb0 + xg0[0]; v01.y += pb0 + xg0[1];
                v23.x += pb1 + xg1[0]; v23.y += pb1 + xg1[1];
                *reinterpret_cast<float2*>(&outp[((size_t)b * NC + gm) * NHW + gn]) = v01;
                *reinterpret_cast<float2*>(&outp[((size_t)b * NC + gm + 8) * NHW + gn]) = v23;
            } else {
                g_qkvbf[((size_t)b * 3 * NC + gm) * (NHW / 2) + (gn >> 1)] =
                    packbf(acc[mf][nf][0], acc[mf][nf][1]);
                g_qkvbf[((size_t)b * 3 * NC + gm + 8) * (NHW / 2) + (gn >> 1)] =
                    packbf(acc[mf][nf][2], acc[mf][nf][3]);
            }
        }
    }
}

// ============================================================
// Permute packed qkv -> attention layouts (conflict-mitigated).
// Q,K: bf16 [bh][n2][d2]; V: bf16 [bh][d2][n2].
// scalar(d2, n2=d_lo*128+jj) = plane[h=d2&7][n=jj*8+(d2>>3)]
// smem: s<2 plane h at h*516+np (2-way); s==2 transposed
// plane h at h*528 + (np&7)*66 + (np>>3) (CF reads).
// ============================================================
__global__ void __launch_bounds__(256) permute_kernel()
{
    int blk  = blockIdx.x;
    int d_lo = blk & 7;
    int s    = (blk >> 3) % 3;
    int bh   = blk / 24;
    int b = bh >> 3, r = bh & 7;

    __shared__ unsigned smw[8 * 528];
    int t = threadIdx.x;

    for (int i = t; i < 8 * 512; i += 256) {
        int h = i >> 9, np = i & 511;
        unsigned v = g_qkvbf[((size_t)b * 3 * NC + s * NC + h * 64 + r * 8 + d_lo) * (NHW / 2) + np];
        if (s == 2) smw[h * 528 + (np & 7) * 66 + (np >> 3)] = v;
        else        smw[h * 516 + np] = v;
    }
    __syncthreads();

    if (s < 2) {
        // Q (s==0) / K (s==1): word (n2=d_lo*128+jj, d2pair pr) =
        //   (plane[h0][n], plane[h0+1][n]) with h0=(pr&3)*2, n=jj*8+(pr>>2)
        unsigned* dst = reinterpret_cast<unsigned*>((s == 0 ? g_qbf : g_kbf)
                        + ((size_t)bh * NHW + (size_t)d_lo * 128) * HD);
        for (int i = t; i < 128 * 32; i += 256) {
            int jj = i >> 5, pr = i & 31;
            int n  = jj * 8 + (pr >> 2);
            int h0 = (pr & 3) * 2;
            unsigned w0 = smw[h0 * 516 + (n >> 1)];
            unsigned w1 = smw[h0 * 516 + 516 + (n >> 1)];
            dst[jj * 32 + pr] = __byte_perm(w0, w1, (n & 1) ? 0x7632 : 0x5410);
        }
    } else {
        // V: word (d2, jp) = (plane[h][16jp+c], plane[h][16jp+8+c]),
        //   h=d2&7, c=d2>>3; smem cols (c>>1)*66+jp and (4+(c>>1))*66+jp
        unsigned* dst = reinterpret_cast<unsigned*>(g_vbf + (size_t)bh * HD * NHW)
                        + d_lo * 64;
        for (int i = t; i < 64 * 64; i += 256) {
            int d2 = i >> 6, jp = i & 63;
            int h = d2 & 7, c = d2 >> 3;
            unsigned w1 = smw[h * 528 + (c >> 1) * 66 + jp];
            unsigned w2 = smw[h * 528 + (4 + (c >> 1)) * 66 + jp];
            dst[(size_t)d2 * (NHW / 2) + jp] = __byte_perm(w1, w2, (c & 1) ? 0x7632 : 0x5410);
        }
    }
}

// ============================================================
// Flash attention v6 — bf16 mma, 3-stage cp.async, 1 sync/iter.
// K smem [j][d] rows (36 wd), V smem [d][j] rows (36 wd).
// Q a-frags: direct LDG.32 from [n2][d2] layout.
// Dynamic smem 54KB, 2 CTAs/SM.
// ============================================================
#define KVSTRIDE 36
#define STG_WORDS (2 * 64 * KVSTRIDE)
#define FLASH_SMEM (3 * STG_WORDS * 4)

__global__ void __launch_bounds__(256, 2) flash_kernel()
{
    extern __shared__ unsigned dynsm[];

    int bh    = blockIdx.x >> 3;
    int qtile = blockIdx.x & 7;
    int b = bh >> 3, r = bh & 7;

    const unsigned* Qp = reinterpret_cast<const unsigned*>(g_qbf + (size_t)bh * NHW * HD);
    const __nv_bfloat16* Kp = g_kbf + (size_t)bh * NHW * HD;
    const __nv_bfloat16* Vp = g_vbf + (size_t)bh * HD * NHW;

    int t = threadIdx.x;
    int w = t >> 5, lane = t & 31;
    int gid = lane >> 2, tig = lane & 3;
    int i0w = w * 16;
    int ibase = qtile * 128 + i0w + gid;

    // Q a-frags: word (n2, p) = (Q[2p][n2], Q[2p+1][n2])
    unsigned qa[4][4];
    {
        const unsigned* qr0 = Qp + (size_t)ibase * 32;
        const unsigned* qr8 = qr0 + 8 * 32;
        #pragma unroll
        for (int ds = 0; ds < 4; ds++) {
            qa[ds][0] = qr0[ds * 8 + tig];
            qa[ds][1] = qr8[ds * 8 + tig];
            qa[ds][2] = qr0[ds * 8 + tig + 4];
            qa[ds][3] = qr8[ds * 8 + tig + 4];
        }
    }

    float acc_o[8][4];
    #pragma unroll
    for (int i = 0; i < 8; i++)
        #pragma unroll
        for (int c = 0; c < 4; c++) acc_o[i][c] = 0.f;
    float row_m0 = -1e30f, row_m1 = -1e30f;
    float row_l0 = 0.f, row_l1 = 0.f;
    const float scale = 0.125f;

    auto load_tiles = [&](int st, int kt) {
        unsigned kb = (unsigned)__cvta_generic_to_shared(dynsm + st * STG_WORDS);
        unsigned vb = kb + 64 * KVSTRIDE * 4;
        int j0 = kt * 64;
        #pragma unroll
        for (int h = 0; h < 2; h++) {
            int ca = t + h * 256;
            int row = ca >> 3, ch = ca & 7;
            cp16(kb + (row * KVSTRIDE + ch * 4) * 4, Kp + (size_t)(j0 + row) * HD + ch * 8);
            cp16(vb + (row * KVSTRIDE + ch * 4) * 4, Vp + (size_t)row * NHW + j0 + ch * 8);
        }
    };

    load_tiles(0, 0);
    asm volatile("cp.async.commit_group;");
    load_tiles(1, 1);
    asm volatile("cp.async.commit_group;");

    for (int kt = 0; kt < 16; kt++) {
        int st = kt % 3;
        const unsigned* kbuf = dynsm + st * STG_WORDS;
        const unsigned* vbuf = kbuf + 64 * KVSTRIDE;

        asm volatile("cp.async.wait_group 1;");
        __syncthreads();
        if (kt + 2 < 16) load_tiles((kt + 2) % 3, kt + 2);
        asm volatile("cp.async.commit_group;");

        // ---- S = Q K^T ----
        float p[8][4];
        #pragma unroll
        for (int i = 0; i < 8; i++)
            #pragma unroll
            for (int c = 0; c < 4; c++) p[i][c] = 0.f;

        #pragma unroll
        for (int ds = 0; ds < 4; ds++) {
            #pragma unroll
            for (int nf = 0; nf < 8; nf++) {
                unsigned bb[2];
                const unsigned* kr = &kbuf[(nf * 8 + gid) * KVSTRIDE + ds * 8 + tig];
                bb[0] = kr[0];
                bb[1] = kr[4];
                mma_bf16(p[nf], qa[ds], bb);
            }
        }

        // ---- online softmax ----
        float tmax0 = -1e30f, tmax1 = -1e30f;
        #pragma unroll
        for (int nf = 0; nf < 8; nf++) {
            tmax0 = fmaxf(tmax0, fmaxf(p[nf][0], p[nf][1]));
            tmax1 = fmaxf(tmax1, fmaxf(p[nf][2], p[nf][3]));
        }
        tmax0 = fmaxf(tmax0, __shfl_xor_sync(~0u, tmax0, 1));
        tmax0 = fmaxf(tmax0, __shfl_xor_sync(~0u, tmax0, 2));
        tmax1 = fmaxf(tmax1, __shfl_xor_sync(~0u, tmax1, 1));
        tmax1 = fmaxf(tmax1, __shfl_xor_sync(~0u, tmax1, 2));

        float nm0 = fmaxf(row_m0, tmax0 * scale);
        float nm1 = fmaxf(row_m1, tmax1 * scale);
        float corr0 = __expf(row_m0 - nm0);
        float corr1 = __expf(row_m1 - nm1);

        float sum0 = 0.f, sum1 = 0.f;
        #pragma unroll
        for (int nf = 0; nf < 8; nf++) {
            p[nf][0] = __expf(p[nf][0] * scale - nm0);
            p[nf][1] = __expf(p[nf][1] * scale - nm0);
            p[nf][2] = __expf(p[nf][2] * scale - nm1);
            p[nf][3] = __expf(p[nf][3] * scale - nm1);
            sum0 += p[nf][0] + p[nf][1];
            sum1 += p[nf][2] + p[nf][3];
        }
        sum0 += __shfl_xor_sync(~0u, sum0, 1);
        sum0 += __shfl_xor_sync(~0u, sum0, 2);
        sum1 += __shfl_xor_sync(~0u, sum1, 1);
        sum1 += __shfl_xor_sync(~0u, sum1, 2);

        row_l0 = row_l0 * corr0 + sum0;
        row_l1 = row_l1 * corr1 + sum1;
        row_m0 = nm0; row_m1 = nm1;

        #pragma unroll
        for (int nf2 = 0; nf2 < 8; nf2++) {
            acc_o[nf2][0] *= corr0; acc_o[nf2][1] *= corr0;
            acc_o[nf2][2] *= corr1; acc_o[nf2][3] *= corr1;
        }

        // ---- O += P V^T ----
        #pragma unroll
        for (int js = 0; js < 4; js++) {
            unsigned pa[4];
            pa[0] = packbf(p[2 * js][0],     p[2 * js][1]);
            pa[1] = packbf(p[2 * js][2],     p[2 * js][3]);
            pa[2] = packbf(p[2 * js + 1][0], p[2 * js + 1][1]);
            pa[3] = packbf(p[2 * js + 1][2], p[2 * js + 1][3]);
            #pragma unroll
            for (int nf2 = 0; nf2 < 8; nf2++) {
                unsigned bb[2];
                const unsigned* vr = &vbuf[(nf2 * 8 + gid) * KVSTRIDE + js * 8 + tig];
                bb[0] = vr[0];
                bb[1] = vr[4];
                mma_bf16(acc_o[nf2], pa, bb);
            }
        }
    }

    // ---- epilogue: O /= l, write packed bf16x2 into g_hbf ----
    float inv0 = 1.f / row_l0, inv1 = 1.f / row_l1;
    unsigned* Hb = g_hbf + ((size_t)b * (NC / 2) + r * (HD / 2)) * NHW;
    #pragma unroll
    for (int nf2 = 0; nf2 < 8; nf2++) {
        int u = nf2 * 4 + tig;
        Hb[(size_t)u * NHW + ibase]     = packbf(acc_o[nf2][0] * inv0, acc_o[nf2][1] * inv0);
        Hb[(size_t)u * NHW + ibase + 8] = packbf(acc_o[nf2][2] * inv1, acc_o[nf2][3] * inv1);
    }
}

// ============================================================
extern "C" void kernel_launch(void* const* d_in, const int* in_sizes, int n_in,
                              void* d_out, int out_size)
{
    const float* x      = (const float*)d_in[0];
    const float* gn_w   = (const float*)d_in[1];
    const float* gn_b   = (const float*)d_in[2];
    const float* qkv_w  = (const float*)d_in[3];
    const float* proj_w = (const float*)d_in[4];
    const float* proj_b = (const float*)d_in[5];
    float* out = (float*)d_out;

    cudaFuncSetAttribute(flash_kernel, cudaFuncAttributeMaxDynamicSharedMemorySize, FLASH_SMEM);

    convw_kernel<<<1024, 256>>>(qkv_w, proj_w);
    gn_kernel<<<NB * NG, 256>>>(x, gn_w, gn_b);
    gemm_bf<0><<<dim3(8, 12, NB), 256>>>(nullptr, nullptr);
    permute_kernel<<<NB * NHEADS * 3 * 8, 256>>>();
    flash_kernel<<<NB * NHEADS * 8, 256, FLASH_SMEM>>>();
    gemm_bf<1><<<dim3(8, 4, NB), 256>>>(proj_b, out);
}

// round 12
// speedup vs baseline: 9.2839x; 1.0396x over previous
#include <cuda_runtime.h>
#include <cuda_bf16.h>
#include <math.h>

#define NB 16
#define NC 512
#define NHW 1024
#define NHEADS 8
#define HD 64
#define NG 32
#define CPG 16

// ---- scratch ----
__device__ float g_xgn[(size_t)NB * NC * NHW];                  //  33.5 MB fp32 (residual)
__device__ unsigned g_xbf[(size_t)NB * (NC / 2) * NHW];         //  33.5 MB bf16x2 [b][c/2][n] (k-packed)
__device__ unsigned g_qkvbf[(size_t)NB * 3 * NC * (NHW / 2)];   //  50.3 MB bf16x2 [b][o][n/2] (n-packed)
__device__ __nv_bfloat16 g_qbf[(size_t)NB * NHEADS * NHW * HD]; //  16.8 MB bf16 Q [bh][n2][d2] (frag-interleaved)
__device__ __nv_bfloat16 g_kbf[(size_t)NB * NHEADS * NHW * HD]; //  16.8 MB bf16 K [bh][n2][d2] (frag-interleaved)
__device__ __nv_bfloat16 g_vbf[(size_t)NB * NHEADS * HD * NHW]; //  16.8 MB bf16 V [bh][d2][n2] (frag-interleaved)
__device__ unsigned g_hbf[(size_t)NB * (NC / 2) * NHW];         //  33.5 MB bf16x2 packed h (k-packed)
__device__ unsigned g_wqkv[3 * NC * NC / 2];                    //   1.5 MB bf16 qkv_w [m][k]
__device__ unsigned g_wproj[NC * NC / 2];                       //   0.5 MB bf16 proj_w [m][k]

// fragment-pair interleave within 8-word groups:
// old word g = ds*8 + tig + 4*half  ->  new pos = ds*8 + 2*tig + half
__device__ __host__ __forceinline__ int fperm(int p) {
    return (p & ~7) | ((p & 3) << 1) | ((p >> 2) & 1);
}

// ---- helpers ----
__device__ __forceinline__ void mma_bf16(float* c, const unsigned* a, const unsigned* b) {
    asm volatile(
        "mma.sync.aligned.m16n8k16.row.col.f32.bf16.bf16.f32 "
        "{%0,%1,%2,%3}, {%4,%5,%6,%7}, {%8,%9}, {%0,%1,%2,%3};"
        : "+f"(c[0]), "+f"(c[1]), "+f"(c[2]), "+f"(c[3])
        : "r"(a[0]), "r"(a[1]), "r"(a[2]), "r"(a[3]), "r"(b[0]), "r"(b[1]));
}
__device__ __forceinline__ unsigned packbf(float lo, float hi) {
    unsigned d;
    asm("cvt.rn.bf16x2.f32 %0, %1, %2;" : "=r"(d) : "f"(hi), "f"(lo));
    return d;
}
__device__ __forceinline__ void cp16(unsigned dst, const void* src) {
    asm volatile("cp.async.cg.shared.global [%0], [%1], 16;" :: "r"(dst), "l"(src));
}

// ============================================================
// Weight pre-pack: fp32 -> bf16 [m][k]
// ============================================================
__global__ void __launch_bounds__(256) convw_kernel(const float* __restrict__ qkvw,
                                                    const float* __restrict__ projw)
{
    int i = blockIdx.x * 256 + threadIdx.x;
    const int NQ = 3 * NC * NC / 4;
    const int NP = NC * NC / 4;
    if (i < NQ) {
        float4 v = reinterpret_cast<const float4*>(qkvw)[i];
        reinterpret_cast<uint2*>(g_wqkv)[i] = make_uint2(packbf(v.x, v.y), packbf(v.z, v.w));
    } else if (i < NQ + NP) {
        int j = i - NQ;
        float4 v = reinterpret_cast<const float4*>(projw)[j];
        reinterpret_cast<uint2*>(g_wproj)[j] = make_uint2(packbf(v.x, v.y), packbf(v.z, v.w));
    }
}

// ============================================================
// GroupNorm: fp32 out (residual) + bf16x2 k-packed out (GEMM B)
// ============================================================
__global__ void __launch_bounds__(256) gn_kernel(const float* __restrict__ x,
                                                 const float* __restrict__ w,
                                                 const float* __restrict__ bias)
{
    int b = blockIdx.x >> 5;
    int g = blockIdx.x & 31;
    const float* xp = x + ((size_t)b * NC + g * CPG) * NHW;

    float s = 0.f, s2 = 0.f;
    for (int i = threadIdx.x; i < CPG * NHW; i += 256) {
        float v = xp[i];
        s += v; s2 += v * v;
    }
    __shared__ float r0[8], r1[8];
    #pragma unroll
    for (int o = 16; o; o >>= 1) {
        s  += __shfl_xor_sync(~0u, s,  o);
        s2 += __shfl_xor_sync(~0u, s2, o);
    }
    int wid = threadIdx.x >> 5, lid = threadIdx.x & 31;
    if (lid == 0) { r0[wid] = s; r1[wid] = s2; }
    __syncthreads();
    if (threadIdx.x < 32) {
        s  = (lid < 8) ? r0[lid] : 0.f;
        s2 = (lid < 8) ? r1[lid] : 0.f;
        #pragma unroll
        for (int o = 4; o; o >>= 1) {
            s  += __shfl_xor_sync(~0u, s,  o);
            s2 += __shfl_xor_sync(~0u, s2, o);
        }
        if (lid == 0) { r0[0] = s; r1[0] = s2; }
    }
    __syncthreads();
    const float inv_n = 1.f / (CPG * NHW);
    float mean = r0[0] * inv_n;
    float var  = r1[0] * inv_n - mean * mean;
    float rinv = rsqrtf(var + 1e-5f);

    float* op = g_xgn + ((size_t)b * NC + g * CPG) * NHW;
    unsigned* xb = g_xbf + ((size_t)b * (NC / 2) + g * (CPG / 2)) * NHW;
    for (int i = threadIdx.x; i < (CPG / 2) * NHW; i += 256) {
        int ul = i >> 10, n = i & 1023;
        int c0 = g * CPG + 2 * ul;
        float v0 = (xp[(2 * ul) * NHW + n]     - mean) * rinv * w[c0]     + bias[c0];
        float v1 = (xp[(2 * ul + 1) * NHW + n] - mean) * rinv * w[c0 + 1] + bias[c0 + 1];
        op[(2 * ul) * NHW + n]     = v0;
        op[(2 * ul + 1) * NHW + n] = v1;
        xb[ul * NHW + n] = packbf(v0, v1);
    }
}

// ============================================================
// bf16 GEMM NN, 3-stage cp.async ring, ONE sync per k-iter.
// MODE 0: qkv -> g_qkvbf bf16x2 n-packed
// MODE 1: proj -> out fp32 (+bias +residual g_xgn)
// Stage: A[128][20] words + B[16][136] words = 4736 words.
// ============================================================
#define GSTAGE 4736
#define GEMM_SMEM (3 * GSTAGE * 4)

template <int MODE>
__global__ void __launch_bounds__(256, 2) gemm_bf(const float* __restrict__ pbias,
                                                  float* __restrict__ outp)
{
    extern __shared__ unsigned gsm[];
    unsigned sbase = (unsigned)__cvta_generic_to_shared(gsm);
    const unsigned* Aw = MODE ? g_wproj : g_wqkv;

    int b  = blockIdx.z;
    int m0 = blockIdx.y << 7;
    int n0 = blockIdx.x << 7;
    const unsigned* Bw = (MODE ? g_hbf : g_xbf) + (size_t)b * (NC / 2) * NHW;

    int t = threadIdx.x;
    int w = t >> 5, lane = t & 31;
    int gid = lane >> 2, tig = lane & 3;
    int mw = (w >> 2) * 64;
    int nw = (w & 3) * 32;

    float acc[4][4][4];
    #pragma unroll
    for (int i = 0; i < 4; i++)
        #pragma unroll
        for (int j = 0; j < 4; j++)
            #pragma unroll
            for (int c = 0; c < 4; c++) acc[i][j][c] = 0.f;

    auto load_stage = [&](int s, int kp0) {
        unsigned abase = sbase + s * GSTAGE * 4;
        unsigned bbase = abase + 2560 * 4;
        #pragma unroll
        for (int h = 0; h < 2; h++) {
            int ca = t + h * 256;
            int m = ca >> 2, kq = ca & 3;
            cp16(abase + (m * 20 + kq * 4) * 4,
                 Aw + (size_t)(m0 + m) * (NC / 2) + kp0 + kq * 4);
            int kp = ca >> 5, nq = (ca & 31) * 4;
            cp16(bbase + (kp * 136 + nq) * 4,
                 Bw + (size_t)(kp0 + kp) * NHW + n0 + nq);
        }
    };

    load_stage(0, 0);
    asm volatile("cp.async.commit_group;");
    load_stage(1, 16);
    asm volatile("cp.async.commit_group;");

    const int NIT = (NC / 2) / 16;   // 16
    for (int it = 0; it < NIT; it++) {
        int s = it % 3;
        const unsigned* As = gsm + s * GSTAGE;
        const unsigned* Bs = As + 2560;

        asm volatile("cp.async.wait_group 1;");
        __syncthreads();
        if (it + 2 < NIT) load_stage((it + 2) % 3, (it + 2) * 16);
        asm volatile("cp.async.commit_group;");

        #pragma unroll
        for (int c2 = 0; c2 < 2; c2++) {
            unsigned a[4][4], bb[4][2];
            #pragma unroll
            for (int mf = 0; mf < 4; mf++) {
                int mi = mw + mf * 16 + gid;
                a[mf][0] = As[mi * 20 + c2 * 8 + tig];
                a[mf][1] = As[(mi + 8) * 20 + c2 * 8 + tig];
                a[mf][2] = As[mi * 20 + c2 * 8 + tig + 4];
                a[mf][3] = As[(mi + 8) * 20 + c2 * 8 + tig + 4];
            }
            #pragma unroll
            for (int nf = 0; nf < 4; nf++) {
                int ni = nw + nf * 8 + gid;
                bb[nf][0] = Bs[(c2 * 8 + tig) * 136 + ni];
                bb[nf][1] = Bs[(c2 * 8 + tig + 4) * 136 + ni];
            }
            #pragma unroll
            for (int mf = 0; mf < 4; mf++)
                #pragma unroll
                for (int nf = 0; nf < 4; nf++)
                    mma_bf16(acc[mf][nf], a[mf], bb[nf]);
        }
    }

    #pragma unroll
    for (int mf = 0; mf < 4; mf++) {
        int gm = m0 + mw + mf * 16 + gid;
        #pragma unroll
        for (int nf = 0; nf < 4; nf++) {
            int gn = n0 + nw + nf * 8 + 2 * tig;
            if (MODE) {
                float2 v01 = make_float2(acc[mf][nf][0], acc[mf][nf][1]);
                float2 v23 = make_float2(acc[mf][nf][2], acc[mf][nf][3]);
                float pb0 = pbias[gm], pb1 = pbias[gm + 8];
                const float* xg0 = &g_xgn[((size_t)b * NC + gm) * NHW + gn];
                const float* xg1 = &g_xgn[((size_t)b * NC + gm + 8) * NHW + gn];
                v01.x += pb0 + xg0[0]; v01.y += pb0 + xg0[1];
                v23.x += pb1 + xg1[0]; v23.y += pb1 + xg1[1];
                *reinterpret_cast<float2*>(&outp[((size_t)b * NC + gm) * NHW + gn]) = v01;
                *reinterpret_cast<float2*>(&outp[((size_t)b * NC + gm + 8) * NHW + gn]) = v23;
            } else {
                g_qkvbf[((size_t)b * 3 * NC + gm) * (NHW / 2) + (gn >> 1)] =
                    packbf(acc[mf][nf][0], acc[mf][nf][1]);
                g_qkvbf[((size_t)b * 3 * NC + gm + 8) * (NHW / 2) + (gn >> 1)] =
                    packbf(acc[mf][nf][2], acc[mf][nf][3]);
            }
        }
    }
}

// ============================================================
// Permute packed qkv -> attention layouts, frag-pair interleaved
// so flash b-fragments are adjacent word pairs (LDS.64).
// ============================================================
__global__ void __launch_bounds__(256) permute_kernel()
{
    int blk  = blockIdx.x;
    int d_lo = blk & 7;
    int s    = (blk >> 3) % 3;
    int bh   = blk / 24;
    int b = bh >> 3, r = bh & 7;

    __shared__ unsigned smw[8 * 528];
    int t = threadIdx.x;

    for (int i = t; i < 8 * 512; i += 256) {
        int h = i >> 9, np = i & 511;
        unsigned v = g_qkvbf[((size_t)b * 3 * NC + s * NC + h * 64 + r * 8 + d_lo) * (NHW / 2) + np];
        if (s == 2) smw[h * 528 + (np & 7) * 66 + (np >> 3)] = v;
        else        smw[h * 516 + np] = v;
    }
    __syncthreads();

    if (s < 2) {
        unsigned* dst = reinterpret_cast<unsigned*>((s == 0 ? g_qbf : g_kbf)
                        + ((size_t)bh * NHW + (size_t)d_lo * 128) * HD);
        for (int i = t; i < 128 * 32; i += 256) {
            int jj = i >> 5, pr = i & 31;
            int n  = jj * 8 + (pr >> 2);
            int h0 = (pr & 3) * 2;
            unsigned w0 = smw[h0 * 516 + (n >> 1)];
            unsigned w1 = smw[h0 * 516 + 516 + (n >> 1)];
            dst[jj * 32 + fperm(pr)] = __byte_perm(w0, w1, (n & 1) ? 0x7632 : 0x5410);
        }
    } else {
        unsigned* dst = reinterpret_cast<unsigned*>(g_vbf + (size_t)bh * HD * NHW)
                        + d_lo * 64;
        for (int i = t; i < 64 * 64; i += 256) {
            int d2 = i >> 6, jp = i & 63;
            int h = d2 & 7, c = d2 >> 3;
            unsigned w1 = smw[h * 528 + (c >> 1) * 66 + jp];
            unsigned w2 = smw[h * 528 + (4 + (c >> 1)) * 66 + jp];
            dst[(size_t)d2 * (NHW / 2) + fperm(jp)] = __byte_perm(w1, w2, (c & 1) ? 0x7632 : 0x5410);
        }
    }
}

// ============================================================
// Flash attention v7 — bf16 mma, 3-stage cp.async, LDS.64 b-frags.
// K smem [j][d] rows (40 wd incl pad), V smem [d][j] rows (40 wd).
// Q a-frags direct LDG (interleaved layout: pairs adjacent).
// ============================================================
#define KVSTRIDE 40
#define STG_WORDS (2 * 64 * KVSTRIDE)
#define FLASH_SMEM (3 * STG_WORDS * 4)

__global__ void __launch_bounds__(256, 2) flash_kernel()
{
    extern __shared__ unsigned dynsm[];

    int bh    = blockIdx.x >> 3;
    int qtile = blockIdx.x & 7;
    int b = bh >> 3, r = bh & 7;

    const unsigned* Qp = reinterpret_cast<const unsigned*>(g_qbf + (size_t)bh * NHW * HD);
    const __nv_bfloat16* Kp = g_kbf + (size_t)bh * NHW * HD;
    const __nv_bfloat16* Vp = g_vbf + (size_t)bh * HD * NHW;

    int t = threadIdx.x;
    int w = t >> 5, lane = t & 31;
    int gid = lane >> 2, tig = lane & 3;
    int i0w = w * 16;
    int ibase = qtile * 128 + i0w + gid;

    // Q a-frags (interleaved layout: old word ds*8+tig at pos ds*8+2*tig, +4 at +1)
    unsigned qa[4][4];
    {
        const unsigned* qr0 = Qp + (size_t)ibase * 32;
        const unsigned* qr8 = qr0 + 8 * 32;
        #pragma unroll
        for (int ds = 0; ds < 4; ds++) {
            uint2 u0 = *reinterpret_cast<const uint2*>(qr0 + ds * 8 + 2 * tig);
            uint2 u8 = *reinterpret_cast<const uint2*>(qr8 + ds * 8 + 2 * tig);
            qa[ds][0] = u0.x;
            qa[ds][1] = u8.x;
            qa[ds][2] = u0.y;
            qa[ds][3] = u8.y;
        }
    }

    float acc_o[8][4];
    #pragma unroll
    for (int i = 0; i < 8; i++)
        #pragma unroll
        for (int c = 0; c < 4; c++) acc_o[i][c] = 0.f;
    float row_m0 = -1e30f, row_m1 = -1e30f;
    float row_l0 = 0.f, row_l1 = 0.f;
    const float scale = 0.125f;

    auto load_tiles = [&](int st, int kt) {
        unsigned kb = (unsigned)__cvta_generic_to_shared(dynsm + st * STG_WORDS);
        unsigned vb = kb + 64 * KVSTRIDE * 4;
        int j0 = kt * 64;
        #pragma unroll
        for (int h = 0; h < 2; h++) {
            int ca = t + h * 256;
            int row = ca >> 3, ch = ca & 7;
            cp16(kb + (row * KVSTRIDE + ch * 4) * 4, Kp + (size_t)(j0 + row) * HD + ch * 8);
            cp16(vb + (row * KVSTRIDE + ch * 4) * 4, Vp + (size_t)row * NHW + j0 + ch * 8);
        }
    };

    load_tiles(0, 0);
    asm volatile("cp.async.commit_group;");
    load_tiles(1, 1);
    asm volatile("cp.async.commit_group;");

    for (int kt = 0; kt < 16; kt++) {
        int st = kt % 3;
        const unsigned* kbuf = dynsm + st * STG_WORDS;
        const unsigned* vbuf = kbuf + 64 * KVSTRIDE;

        asm volatile("cp.async.wait_group 1;");
        __syncthreads();
        if (kt + 2 < 16) load_tiles((kt + 2) % 3, kt + 2);
        asm volatile("cp.async.commit_group;");

        // ---- S = Q K^T ----
        float p[8][4];
        #pragma unroll
        for (int i = 0; i < 8; i++)
            #pragma unroll
            for (int c = 0; c < 4; c++) p[i][c] = 0.f;

        #pragma unroll
        for (int ds = 0; ds < 4; ds++) {
            #pragma unroll
            for (int nf = 0; nf < 8; nf++) {
                uint2 kb2 = *reinterpret_cast<const uint2*>(
                    &kbuf[(nf * 8 + gid) * KVSTRIDE + ds * 8 + 2 * tig]);
                unsigned bb[2] = {kb2.x, kb2.y};
                mma_bf16(p[nf], qa[ds], bb);
            }
        }

        // ---- online softmax ----
        float tmax0 = -1e30f, tmax1 = -1e30f;
        #pragma unroll
        for (int nf = 0; nf < 8; nf++) {
            tmax0 = fmaxf(tmax0, fmaxf(p[nf][0], p[nf][1]));
            tmax1 = fmaxf(tmax1, fmaxf(p[nf][2], p[nf][3]));
        }
        tmax0 = fmaxf(tmax0, __shfl_xor_sync(~0u, tmax0, 1));
        tmax0 = fmaxf(tmax0, __shfl_xor_sync(~0u, tmax0, 2));
        tmax1 = fmaxf(tmax1, __shfl_xor_sync(~0u, tmax1, 1));
        tmax1 = fmaxf(tmax1, __shfl_xor_sync(~0u, tmax1, 2));

        float nm0 = fmaxf(row_m0, tmax0 * scale);
        float nm1 = fmaxf(row_m1, tmax1 * scale);
        float corr0 = __expf(row_m0 - nm0);
        float corr1 = __expf(row_m1 - nm1);

        float sum0 = 0.f, sum1 = 0.f;
        #pragma unroll
        for (int nf = 0; nf < 8; nf++) {
            p[nf][0] = __expf(p[nf][0] * scale - nm0);
            p[nf][1] = __expf(p[nf][1] * scale - nm0);
            p[nf][2] = __expf(p[nf][2] * scale - nm1);
            p[nf][3] = __expf(p[nf][3] * scale - nm1);
            sum0 += p[nf][0] + p[nf][1];
            sum1 += p[nf][2] + p[nf][3];
        }
        sum0 += __shfl_xor_sync(~0u, sum0, 1);
        sum0 += __shfl_xor_sync(~0u, sum0, 2);
        sum1 += __shfl_xor_sync(~0u, sum1, 1);
        sum1 += __shfl_xor_sync(~0u, sum1, 2);

        row_l0 = row_l0 * corr0 + sum0;
        row_l1 = row_l1 * corr1 + sum1;
        row_m0 = nm0; row_m1 = nm1;

        #pragma unroll
        for (int nf2 = 0; nf2 < 8; nf2++) {
            acc_o[nf2][0] *= corr0; acc_o[nf2][1] *= corr0;
            acc_o[nf2][2] *= corr1; acc_o[nf2][3] *= corr1;
        }

        // ---- O += P V^T ----
        #pragma unroll
        for (int js = 0; js < 4; js++) {
            unsigned pa[4];
            pa[0] = packbf(p[2 * js][0],     p[2 * js][1]);
            pa[1] = packbf(p[2 * js][2],     p[2 * js][3]);
            pa[2] = packbf(p[2 * js + 1][0], p[2 * js + 1][1]);
            pa[3] = packbf(p[2 * js + 1][2], p[2 * js + 1][3]);
            #pragma unroll
            for (int nf2 = 0; nf2 < 8; nf2++) {
                uint2 vb2 = *reinterpret_cast<const uint2*>(
                    &vbuf[(nf2 * 8 + gid) * KVSTRIDE + js * 8 + 2 * tig]);
                unsigned bb[2] = {vb2.x, vb2.y};
                mma_bf16(acc_o[nf2], pa, bb);
            }
        }
    }

    // ---- epilogue: O /= l, write packed bf16x2 into g_hbf ----
    float inv0 = 1.f / row_l0, inv1 = 1.f / row_l1;
    unsigned* Hb = g_hbf + ((size_t)b * (NC / 2) + r * (HD / 2)) * NHW;
    #pragma unroll
    for (int nf2 = 0; nf2 < 8; nf2++) {
        int u = nf2 * 4 + tig;
        Hb[(size_t)u * NHW + ibase]     = packbf(acc_o[nf2][0] * inv0, acc_o[nf2][1] * inv0);
        Hb[(size_t)u * NHW + ibase + 8] = packbf(acc_o[nf2][2] * inv1, acc_o[nf2][3] * inv1);
    }
}

// ============================================================
extern "C" void kernel_launch(void* const* d_in, const int* in_sizes, int n_in,
                              void* d_out, int out_size)
{
    const float* x      = (const float*)d_in[0];
    const float* gn_w   = (const float*)d_in[1];
    const float* gn_b   = (const float*)d_in[2];
    const float* qkv_w  = (const float*)d_in[3];
    const float* proj_w = (const float*)d_in[4];
    const float* proj_b = (const float*)d_in[5];
    float* out = (float*)d_out;

    cudaFuncSetAttribute(flash_kernel, cudaFuncAttributeMaxDynamicSharedMemorySize, FLASH_SMEM);
    cudaFuncSetAttribute(gemm_bf<0>, cudaFuncAttributeMaxDynamicSharedMemorySize, GEMM_SMEM);
    cudaFuncSetAttribute(gemm_bf<1>, cudaFuncAttributeMaxDynamicSharedMemorySize, GEMM_SMEM);

    convw_kernel<<<1024, 256>>>(qkv_w, proj_w);
    gn_kernel<<<NB * NG, 256>>>(x, gn_w, gn_b);
    gemm_bf<0><<<dim3(8, 12, NB), 256, GEMM_SMEM>>>(nullptr, nullptr);
    permute_kernel<<<NB * NHEADS * 3 * 8, 256>>>();
    flash_kernel<<<NB * NHEADS * 8, 256, FLASH_SMEM>>>();
    gemm_bf<1><<<dim3(8, 4, NB), 256, GEMM_SMEM>>>(proj_b, out);
}

// round 13
// speedup vs baseline: 9.4044x; 1.0130x over previous
#include <cuda_runtime.h>
#include <cuda_bf16.h>
#include <math.h>

#define NB 16
#define NC 512
#define NHW 1024
#define NHEADS 8
#define HD 64
#define NG 32
#define CPG 16

// ---- scratch ----
__device__ float g_xgn[(size_t)NB * NC * NHW];                  //  33.5 MB fp32 (residual)
__device__ unsigned g_xbf[(size_t)NB * (NC / 2) * NHW];         //  33.5 MB bf16x2 [b][c/2][n] (k-packed)
__device__ unsigned g_qkvbf[(size_t)NB * 3 * NC * (NHW / 2)];   //  50.3 MB bf16x2 [b][o][n/2] (n-packed)
__device__ __nv_bfloat16 g_qbf[(size_t)NB * NHEADS * NHW * HD]; //  16.8 MB bf16 Q [bh][n2][d2] (fperm2)
__device__ __nv_bfloat16 g_kbf[(size_t)NB * NHEADS * NHW * HD]; //  16.8 MB bf16 K [bh][n2][d2] (fperm2)
__device__ __nv_bfloat16 g_vbf[(size_t)NB * NHEADS * HD * NHW]; //  16.8 MB bf16 V [bh][d2][n2] (fperm2)
__device__ unsigned g_hbf[(size_t)NB * (NC / 2) * NHW];         //  33.5 MB bf16x2 packed h (k-packed)
__device__ unsigned g_wqkv[3 * NC * NC / 2];                    //   1.5 MB bf16 qkv_w [m][k]
__device__ unsigned g_wproj[NC * NC / 2];                       //   0.5 MB bf16 proj_w [m][k]

// ---- helpers ----
__device__ __forceinline__ void mma_bf16(float* c, const unsigned* a, const unsigned* b) {
    asm volatile(
        "mma.sync.aligned.m16n8k16.row.col.f32.bf16.bf16.f32 "
        "{%0,%1,%2,%3}, {%4,%5,%6,%7}, {%8,%9}, {%0,%1,%2,%3};"
        : "+f"(c[0]), "+f"(c[1]), "+f"(c[2]), "+f"(c[3])
        : "r"(a[0]), "r"(a[1]), "r"(a[2]), "r"(a[3]), "r"(b[0]), "r"(b[1]));
}
__device__ __forceinline__ unsigned packbf(float lo, float hi) {
    unsigned d;
    asm("cvt.rn.bf16x2.f32 %0, %1, %2;" : "=r"(d) : "f"(hi), "f"(lo));
    return d;
}
__device__ __forceinline__ void cp16(unsigned dst, const void* src) {
    asm volatile("cp.async.cg.shared.global [%0], [%1], 16;" :: "r"(dst), "l"(src));
}

// ============================================================
// Weight pre-pack: fp32 -> bf16 [m][k]
// ============================================================
__global__ void __launch_bounds__(256) convw_kernel(const float* __restrict__ qkvw,
                                                    const float* __restrict__ projw)
{
    int i = blockIdx.x * 256 + threadIdx.x;
    const int NQ = 3 * NC * NC / 4;
    const int NP = NC * NC / 4;
    if (i < NQ) {
        float4 v = reinterpret_cast<const float4*>(qkvw)[i];
        reinterpret_cast<uint2*>(g_wqkv)[i] = make_uint2(packbf(v.x, v.y), packbf(v.z, v.w));
    } else if (i < NQ + NP) {
        int j = i - NQ;
        float4 v = reinterpret_cast<const float4*>(projw)[j];
        reinterpret_cast<uint2*>(g_wproj)[j] = make_uint2(packbf(v.x, v.y), packbf(v.z, v.w));
    }
}

// ============================================================
// GroupNorm: fp32 out (residual) + bf16x2 k-packed out — float4 I/O
// ============================================================
__global__ void __launch_bounds__(256) gn_kernel(const float* __restrict__ x,
                                                 const float* __restrict__ w,
                                                 const float* __restrict__ bias)
{
    int b = blockIdx.x >> 5;
    int g = blockIdx.x & 31;
    const float* xp = x + ((size_t)b * NC + g * CPG) * NHW;

    float s = 0.f, s2 = 0.f;
    for (int i = threadIdx.x; i < CPG * NHW / 4; i += 256) {
        float4 v = reinterpret_cast<const float4*>(xp)[i];
        s  += v.x + v.y + v.z + v.w;
        s2 += v.x * v.x + v.y * v.y + v.z * v.z + v.w * v.w;
    }
    __shared__ float r0[8], r1[8];
    #pragma unroll
    for (int o = 16; o; o >>= 1) {
        s  += __shfl_xor_sync(~0u, s,  o);
        s2 += __shfl_xor_sync(~0u, s2, o);
    }
    int wid = threadIdx.x >> 5, lid = threadIdx.x & 31;
    if (lid == 0) { r0[wid] = s; r1[wid] = s2; }
    __syncthreads();
    if (threadIdx.x < 32) {
        s  = (lid < 8) ? r0[lid] : 0.f;
        s2 = (lid < 8) ? r1[lid] : 0.f;
        #pragma unroll
        for (int o = 4; o; o >>= 1) {
            s  += __shfl_xor_sync(~0u, s,  o);
            s2 += __shfl_xor_sync(~0u, s2, o);
        }
        if (lid == 0) { r0[0] = s; r1[0] = s2; }
    }
    __syncthreads();
    const float inv_n = 1.f / (CPG * NHW);
    float mean = r0[0] * inv_n;
    float var  = r1[0] * inv_n - mean * mean;
    float rinv = rsqrtf(var + 1e-5f);

    float* op = g_xgn + ((size_t)b * NC + g * CPG) * NHW;
    unsigned* xb = g_xbf + ((size_t)b * (NC / 2) + g * (CPG / 2)) * NHW;
    for (int i = threadIdx.x; i < (CPG / 2) * (NHW / 4); i += 256) {
        int ul = i >> 8, n4 = (i & 255) * 4;
        int c0 = g * CPG + 2 * ul;
        float w0 = w[c0] * rinv, w1 = w[c0 + 1] * rinv;
        float b0 = bias[c0] - mean * w0, b1 = bias[c0 + 1] - mean * w1;
        float4 xa = *reinterpret_cast<const float4*>(&xp[(2 * ul) * NHW + n4]);
        float4 xc = *reinterpret_cast<const float4*>(&xp[(2 * ul + 1) * NHW + n4]);
        float4 va = make_float4(xa.x * w0 + b0, xa.y * w0 + b0, xa.z * w0 + b0, xa.w * w0 + b0);
        float4 vc = make_float4(xc.x * w1 + b1, xc.y * w1 + b1, xc.z * w1 + b1, xc.w * w1 + b1);
        *reinterpret_cast<float4*>(&op[(2 * ul) * NHW + n4])     = va;
        *reinterpret_cast<float4*>(&op[(2 * ul + 1) * NHW + n4]) = vc;
        uint4 pk = make_uint4(packbf(va.x, vc.x), packbf(va.y, vc.y),
                              packbf(va.z, vc.z), packbf(va.w, vc.w));
        *reinterpret_cast<uint4*>(&xb[ul * NHW + n4]) = pk;
    }
}

// ============================================================
// bf16 GEMM NN, 3-stage cp.async ring, ONE sync per k-iter.
// ============================================================
#define GSTAGE 4736
#define GEMM_SMEM (3 * GSTAGE * 4)

template <int MODE>
__global__ void __launch_bounds__(256, 2) gemm_bf(const float* __restrict__ pbias,
                                                  float* __restrict__ outp)
{
    extern __shared__ unsigned gsm[];
    unsigned sbase = (unsigned)__cvta_generic_to_shared(gsm);
    const unsigned* Aw = MODE ? g_wproj : g_wqkv;

    int b  = blockIdx.z;
    int m0 = blockIdx.y << 7;
    int n0 = blockIdx.x << 7;
    const unsigned* Bw = (MODE ? g_hbf : g_xbf) + (size_t)b * (NC / 2) * NHW;

    int t = threadIdx.x;
    int w = t >> 5, lane = t & 31;
    int gid = lane >> 2, tig = lane & 3;
    int mw = (w >> 2) * 64;
    int nw = (w & 3) * 32;

    float acc[4][4][4];
    #pragma unroll
    for (int i = 0; i < 4; i++)
        #pragma unroll
        for (int j = 0; j < 4; j++)
            #pragma unroll
            for (int c = 0; c < 4; c++) acc[i][j][c] = 0.f;

    auto load_stage = [&](int s, int kp0) {
        unsigned abase = sbase + s * GSTAGE * 4;
        unsigned bbase = abase + 2560 * 4;
        #pragma unroll
        for (int h = 0; h < 2; h++) {
            int ca = t + h * 256;
            int m = ca >> 2, kq = ca & 3;
            cp16(abase + (m * 20 + kq * 4) * 4,
                 Aw + (size_t)(m0 + m) * (NC / 2) + kp0 + kq * 4);
            int kp = ca >> 5, nq = (ca & 31) * 4;
            cp16(bbase + (kp * 136 + nq) * 4,
                 Bw + (size_t)(kp0 + kp) * NHW + n0 + nq);
        }
    };

    load_stage(0, 0);
    asm volatile("cp.async.commit_group;");
    load_stage(1, 16);
    asm volatile("cp.async.commit_group;");

    const int NIT = (NC / 2) / 16;
    for (int it = 0; it < NIT; it++) {
        int s = it % 3;
        const unsigned* As = gsm + s * GSTAGE;
        const unsigned* Bs = As + 2560;

        asm volatile("cp.async.wait_group 1;");
        __syncthreads();
        if (it + 2 < NIT) load_stage((it + 2) % 3, (it + 2) * 16);
        asm volatile("cp.async.commit_group;");

        #pragma unroll
        for (int c2 = 0; c2 < 2; c2++) {
            unsigned a[4][4], bb[4][2];
            #pragma unroll
            for (int mf = 0; mf < 4; mf++) {
                int mi = mw + mf * 16 + gid;
                a[mf][0] = As[mi * 20 + c2 * 8 + tig];
                a[mf][1] = As[(mi + 8) * 20 + c2 * 8 + tig];
                a[mf][2] = As[mi * 20 + c2 * 8 + tig + 4];
                a[mf][3] = As[(mi + 8) * 20 + c2 * 8 + tig + 4];
            }
            #pragma unroll
            for (int nf = 0; nf < 4; nf++) {
                int ni = nw + nf * 8 + gid;
                bb[nf][0] = Bs[(c2 * 8 + tig) * 136 + ni];
                bb[nf][1] = Bs[(c2 * 8 + tig + 4) * 136 + ni];
            }
            #pragma unroll
            for (int mf = 0; mf < 4; mf++)
                #pragma unroll
                for (int nf = 0; nf < 4; nf++)
                    mma_bf16(acc[mf][nf], a[mf], bb[nf]);
        }
    }

    #pragma unroll
    for (int mf = 0; mf < 4; mf++) {
        int gm = m0 + mw + mf * 16 + gid;
        #pragma unroll
        for (int nf = 0; nf < 4; nf++) {
            int gn = n0 + nw + nf * 8 + 2 * tig;
            if (MODE) {
                float2 v01 = make_float2(acc[mf][nf][0], acc[mf][nf][1]);
                float2 v23 = make_float2(acc[mf][nf][2], acc[mf][nf][3]);
                float pb0 = pbias[gm], pb1 = pbias[gm + 8];
                const float* xg0 = &g_xgn[((size_t)b * NC + gm) * NHW + gn];
                const float* xg1 = &g_xgn[((size_t)b * NC + gm + 8) * NHW + gn];
                v01.x += pb0 + xg0[0]; v01.y += pb0 + xg0[1];
                v23.x += pb1 + xg1[0]; v23.y += pb1 + xg1[1];
                *reinterpret_cast<float2*>(&outp[((size_t)b * NC + gm) * NHW + gn]) = v01;
                *reinterpret_cast<float2*>(&outp[((size_t)b * NC + gm + 8) * NHW + gn]) = v23;
            } else {
                g_qkvbf[((size_t)b * 3 * NC + gm) * (NHW / 2) + (gn >> 1)] =
                    packbf(acc[mf][nf][0], acc[mf][nf][1]);
                g_qkvbf[((size_t)b * 3 * NC + gm + 8) * (NHW / 2) + (gn >> 1)] =
                    packbf(acc[mf][nf][2], acc[mf][nf][3]);
            }
        }
    }
}

// ============================================================
// Permute packed qkv -> attention layouts, fperm2-interleaved
// (4 words of a ds-pair contiguous), fully vectorized.
// ============================================================
__global__ void __launch_bounds__(256) permute_kernel()
{
    int blk  = blockIdx.x;
    int d_lo = blk & 7;
    int s    = (blk >> 3) % 3;
    int bh   = blk / 24;
    int b = bh >> 3, r = bh & 7;

    __shared__ unsigned smw[8 * 528];
    int t = threadIdx.x;

    // load phase: uint4 reads
    #pragma unroll
    for (int k = 0; k < 4; k++) {
        int i = t + k * 256;
        int h = i >> 7, np4 = (i & 127) * 4;
        uint4 v = *reinterpret_cast<const uint4*>(
            &g_qkvbf[((size_t)b * 3 * NC + s * NC + h * 64 + r * 8 + d_lo) * (NHW / 2) + np4]);
        if (s == 2) {
            int c0 = np4 & 7, rw = np4 >> 3;
            smw[h * 528 + (c0 + 0) * 66 + rw] = v.x;
            smw[h * 528 + (c0 + 1) * 66 + rw] = v.y;
            smw[h * 528 + (c0 + 2) * 66 + rw] = v.z;
            smw[h * 528 + (c0 + 3) * 66 + rw] = v.w;
        } else {
            *reinterpret_cast<uint4*>(&smw[h * 516 + np4]) = v;
        }
    }
    __syncthreads();

    if (s < 2) {
        // Q/K: uint4 output at (jj, dsp*16 + tig*4). Word c: n = jj*8+4dsp+c,
        // content = pack(plane[2tig][n], plane[2tig+1][n]).
        unsigned* dst = reinterpret_cast<unsigned*>((s == 0 ? g_qbf : g_kbf)
                        + ((size_t)bh * NHW + (size_t)d_lo * 128) * HD);
        #pragma unroll
        for (int k = 0; k < 4; k++) {
            int i = t + k * 256;
            int jj = i >> 3, o4 = i & 7;
            int tg = o4 & 3, dsp = o4 >> 2;
            int h0 = 2 * tg;
            int cb = jj * 4 + 2 * dsp;   // (n base)/2
            uint2 A = *reinterpret_cast<const uint2*>(&smw[h0 * 516 + cb]);
            uint2 B = *reinterpret_cast<const uint2*>(&smw[(h0 + 1) * 516 + cb]);
            uint4 o;
            o.x = __byte_perm(A.x, B.x, 0x5410);
            o.y = __byte_perm(A.x, B.x, 0x7632);
            o.z = __byte_perm(A.y, B.y, 0x5410);
            o.w = __byte_perm(A.y, B.y, 0x7632);
            *reinterpret_cast<uint4*>(&dst[jj * 32 + dsp * 16 + tg * 4]) = o;
        }
    } else {
        // V: uint4 output at (d2, blk32*32 + jsp*16 + tig*4). Word c:
        // jp_old = blk32*32 + (2jsp+(c>>1))*8 + (c&1)*4 + tig.
        unsigned* dst = reinterpret_cast<unsigned*>(g_vbf + (size_t)bh * HD * NHW)
                        + d_lo * 64;
        #pragma unroll
        for (int k = 0; k < 4; k++) {
            int i = t + k * 256;
            int d2 = i >> 4, rest = i & 15;
            int bk = rest >> 3, o4 = rest & 7;
            int tg = o4 & 3, jsp = o4 >> 2;
            int h = d2 & 7, cc = d2 >> 3;
            int col1 = h * 528 + (cc >> 1) * 66;
            int col2 = col1 + 4 * 66;
            unsigned sel = (cc & 1) ? 0x7632 : 0x5410;
            uint4 o;
            #pragma unroll
            for (int c = 0; c < 4; c++) {
                int jp = bk * 32 + (2 * jsp + (c >> 1)) * 8 + (c & 1) * 4 + tg;
                unsigned w1 = smw[col1 + jp];
                unsigned w2 = smw[col2 + jp];
                ((unsigned*)&o)[c] = __byte_perm(w1, w2, sel);
            }
            *reinterpret_cast<uint4*>(&dst[(size_t)d2 * (NHW / 2) + bk * 32 + jsp * 16 + tg * 4]) = o;
        }
    }
}

// ============================================================
// Flash attention v8 — bf16 mma, 3-stage cp.async, LDS.128 b-frags.
// K smem [j][d] rows (48 wd incl pad), V smem [d][j] rows (48 wd).
// One uint4 = b-frags for a ds/js pair (2 mmas).
// ============================================================
#define KVSTRIDE 48
#define STG_WORDS (2 * 64 * KVSTRIDE)
#define FLASH_SMEM (3 * STG_WORDS * 4)

__global__ void __launch_bounds__(256, 2) flash_kernel()
{
    extern __shared__ unsigned dynsm[];

    int bh    = blockIdx.x >> 3;
    int qtile = blockIdx.x & 7;
    int b = bh >> 3, r = bh & 7;

    const unsigned* Qp = reinterpret_cast<const unsigned*>(g_qbf + (size_t)bh * NHW * HD);
    const __nv_bfloat16* Kp = g_kbf + (size_t)bh * NHW * HD;
    const __nv_bfloat16* Vp = g_vbf + (size_t)bh * HD * NHW;

    int t = threadIdx.x;
    int w = t >> 5, lane = t & 31;
    int gid = lane >> 2, tig = lane & 3;
    int i0w = w * 16;
    int ibase = qtile * 128 + i0w + gid;

    // Q a-frags from fperm2 layout: halves adjacent at (ds>>1)*16 + tig*4 + (ds&1)*2
    unsigned qa[4][4];
    {
        const unsigned* qr0 = Qp + (size_t)ibase * 32;
        const unsigned* qr8 = qr0 + 8 * 32;
        #pragma unroll
        for (int ds = 0; ds < 4; ds++) {
            int off = (ds >> 1) * 16 + tig * 4 + (ds & 1) * 2;
            uint2 u0 = *reinterpret_cast<const uint2*>(qr0 + off);
            uint2 u8 = *reinterpret_cast<const uint2*>(qr8 + off);
            qa[ds][0] = u0.x;
            qa[ds][1] = u8.x;
            qa[ds][2] = u0.y;
            qa[ds][3] = u8.y;
        }
    }

    float acc_o[8][4];
    #pragma unroll
    for (int i = 0; i < 8; i++)
        #pragma unroll
        for (int c = 0; c < 4; c++) acc_o[i][c] = 0.f;
    float row_m0 = -1e30f, row_m1 = -1e30f;
    float row_l0 = 0.f, row_l1 = 0.f;
    const float scale = 0.125f;

    auto load_tiles = [&](int st, int kt) {
        unsigned kb = (unsigned)__cvta_generic_to_shared(dynsm + st * STG_WORDS);
        unsigned vb = kb + 64 * KVSTRIDE * 4;
        int j0 = kt * 64;
        #pragma unroll
        for (int h = 0; h < 2; h++) {
            int ca = t + h * 256;
            int row = ca >> 3, ch = ca & 7;
            cp16(kb + (row * KVSTRIDE + ch * 4) * 4, Kp + (size_t)(j0 + row) * HD + ch * 8);
            cp16(vb + (row * KVSTRIDE + ch * 4) * 4, Vp + (size_t)row * NHW + j0 + ch * 8);
        }
    };

    load_tiles(0, 0);
    asm volatile("cp.async.commit_group;");
    load_tiles(1, 1);
    asm volatile("cp.async.commit_group;");

    for (int kt = 0; kt < 16; kt++) {
        int st = kt % 3;
        const unsigned* kbuf = dynsm + st * STG_WORDS;
        const unsigned* vbuf = kbuf + 64 * KVSTRIDE;

        asm volatile("cp.async.wait_group 1;");
        __syncthreads();
        if (kt + 2 < 16) load_tiles((kt + 2) % 3, kt + 2);
        asm volatile("cp.async.commit_group;");

        // ---- S = Q K^T : uint4 -> 2 mmas ----
        float p[8][4];
        #pragma unroll
        for (int i = 0; i < 8; i++)
            #pragma unroll
            for (int c = 0; c < 4; c++) p[i][c] = 0.f;

        #pragma unroll
        for (int dsp = 0; dsp < 2; dsp++) {
            #pragma unroll
            for (int nf = 0; nf < 8; nf++) {
                uint4 k4 = *reinterpret_cast<const uint4*>(
                    &kbuf[(nf * 8 + gid) * KVSTRIDE + dsp * 16 + tig * 4]);
                unsigned b0[2] = {k4.x, k4.y};
                mma_bf16(p[nf], qa[2 * dsp], b0);
                unsigned b1[2] = {k4.z, k4.w};
                mma_bf16(p[nf], qa[2 * dsp + 1], b1);
            }
        }

        // ---- online softmax ----
        float tmax0 = -1e30f, tmax1 = -1e30f;
        #pragma unroll
        for (int nf = 0; nf < 8; nf++) {
            tmax0 = fmaxf(tmax0, fmaxf(p[nf][0], p[nf][1]));
            tmax1 = fmaxf(tmax1, fmaxf(p[nf][2], p[nf][3]));
        }
        tmax0 = fmaxf(tmax0, __shfl_xor_sync(~0u, tmax0, 1));
        tmax0 = fmaxf(tmax0, __shfl_xor_sync(~0u, tmax0, 2));
        tmax1 = fmaxf(tmax1, __shfl_xor_sync(~0u, tmax1, 1));
        tmax1 = fmaxf(tmax1, __shfl_xor_sync(~0u, tmax1, 2));

        float nm0 = fmaxf(row_m0, tmax0 * scale);
        float nm1 = fmaxf(row_m1, tmax1 * scale);
        float corr0 = __expf(row_m0 - nm0);
        float corr1 = __expf(row_m1 - nm1);

        float sum0 = 0.f, sum1 = 0.f;
        #pragma unroll
        for (int nf = 0; nf < 8; nf++) {
            p[nf][0] = __expf(p[nf][0] * scale - nm0);
            p[nf][1] = __expf(p[nf][1] * scale - nm0);
            p[nf][2] = __expf(p[nf][2] * scale - nm1);
            p[nf][3] = __expf(p[nf][3] * scale - nm1);
            sum0 += p[nf][0] + p[nf][1];
            sum1 += p[nf][2] + p[nf][3];
        }
        sum0 += __shfl_xor_sync(~0u, sum0, 1);
        sum0 += __shfl_xor_sync(~0u, sum0, 2);
        sum1 += __shfl_xor_sync(~0u, sum1, 1);
        sum1 += __shfl_xor_sync(~0u, sum1, 2);

        row_l0 = row_l0 * corr0 + sum0;
        row_l1 = row_l1 * corr1 + sum1;
        row_m0 = nm0; row_m1 = nm1;

        #pragma unroll
        for (int nf2 = 0; nf2 < 8; nf2++) {
            acc_o[nf2][0] *= corr0; acc_o[nf2][1] *= corr0;
            acc_o[nf2][2] *= corr1; acc_o[nf2][3] *= corr1;
        }

        // ---- O += P V^T : uint4 -> 2 mmas ----
        #pragma unroll
        for (int jsp = 0; jsp < 2; jsp++) {
            unsigned pa0[4], pa1[4];
            pa0[0] = packbf(p[4 * jsp][0],     p[4 * jsp][1]);
            pa0[1] = packbf(p[4 * jsp][2],     p[4 * jsp][3]);
            pa0[2] = packbf(p[4 * jsp + 1][0], p[4 * jsp + 1][1]);
            pa0[3] = packbf(p[4 * jsp + 1][2], p[4 * jsp + 1][3]);
            pa1[0] = packbf(p[4 * jsp + 2][0], p[4 * jsp + 2][1]);
            pa1[1] = packbf(p[4 * jsp + 2][2], p[4 * jsp + 2][3]);
            pa1[2] = packbf(p[4 * jsp + 3][0], p[4 * jsp + 3][1]);
            pa1[3] = packbf(p[4 * jsp + 3][2], p[4 * jsp + 3][3]);
            #pragma unroll
            for (int nf2 = 0; nf2 < 8; nf2++) {
                uint4 v4 = *reinterpret_cast<const uint4*>(
                    &vbuf[(nf2 * 8 + gid) * KVSTRIDE + jsp * 16 + tig * 4]);
                unsigned b0[2] = {v4.x, v4.y};
                mma_bf16(acc_o[nf2], pa0, b0);
                unsigned b1[2] = {v4.z, v4.w};
                mma_bf16(acc_o[nf2], pa1, b1);
            }
        }
    }

    // ---- epilogue: O /= l, write packed bf16x2 into g_hbf ----
    float inv0 = 1.f / row_l0, inv1 = 1.f / row_l1;
    unsigned* Hb = g_hbf + ((size_t)b * (NC / 2) + r * (HD / 2)) * NHW;
    #pragma unroll
    for (int nf2 = 0; nf2 < 8; nf2++) {
        int u = nf2 * 4 + tig;
        Hb[(size_t)u * NHW + ibase]     = packbf(acc_o[nf2][0] * inv0, acc_o[nf2][1] * inv0);
        Hb[(size_t)u * NHW + ibase + 8] = packbf(acc_o[nf2][2] * inv1, acc_o[nf2][3] * inv1);
    }
}

// ============================================================
extern "C" void kernel_launch(void* const* d_in, const int* in_sizes, int n_in,
                              void* d_out, int out_size)
{
    const float* x      = (const float*)d_in[0];
    const float* gn_w   = (const float*)d_in[1];
    const float* gn_b   = (const float*)d_in[2];
    const float* qkv_w  = (const float*)d_in[3];
    const float* proj_w = (const float*)d_in[4];
    const float* proj_b = (const float*)d_in[5];
    float* out = (float*)d_out;

    cudaFuncSetAttribute(flash_kernel, cudaFuncAttributeMaxDynamicSharedMemorySize, FLASH_SMEM);
    cudaFuncSetAttribute(gemm_bf<0>, cudaFuncAttributeMaxDynamicSharedMemorySize, GEMM_SMEM);
    cudaFuncSetAttribute(gemm_bf<1>, cudaFuncAttributeMaxDynamicSharedMemorySize, GEMM_SMEM);

    convw_kernel<<<1024, 256>>>(qkv_w, proj_w);
    gn_kernel<<<NB * NG, 256>>>(x, gn_w, gn_b);
    gemm_bf<0><<<dim3(8, 12, NB), 256, GEMM_SMEM>>>(nullptr, nullptr);
    permute_kernel<<<NB * NHEADS * 3 * 8, 256>>>();
    flash_kernel<<<NB * NHEADS * 8, 256, FLASH_SMEM>>>();
    gemm_bf<1><<<dim3(8, 4, NB), 256, GEMM_SMEM>>>(proj_b, out);
}

// round 14
// speedup vs baseline: 10.0575x; 1.0694x over previous
#include <cuda_runtime.h>
#include <cuda_bf16.h>
#include <math.h>

#define NB 16
#define NC 512
#define NHW 1024
#define NHEADS 8
#define HD 64
#define NG 32
#define CPG 16

// ---- scratch ----
__device__ unsigned g_xbf[(size_t)NB * (NC / 2) * NHW];         // bf16x2 [b][c/2][n] (k-packed)
__device__ float g_scale[NB * NC];                              // gn affine: x*scale+shift
__device__ float g_shift[NB * NC];
__device__ __nv_bfloat16 g_qbf[(size_t)NB * NHEADS * NHW * HD]; // bf16 Q [bh][n2][d2] (fperm2, pre-scaled 1/8)
__device__ __nv_bfloat16 g_kbf[(size_t)NB * NHEADS * NHW * HD]; // bf16 K [bh][n2][d2] (fperm2)
__device__ __nv_bfloat16 g_vbf[(size_t)NB * NHEADS * HD * NHW]; // bf16 V [bh][d2][n2] (fperm2)
__device__ unsigned g_hbf[(size_t)NB * (NC / 2) * NHW];         // bf16x2 packed h (k-packed)
__device__ unsigned g_wqkv[3 * NC * NC / 2];                    // bf16 qkv_w [m][k]
__device__ unsigned g_wproj[NC * NC / 2];                       // bf16 proj_w [m][k]

// ---- helpers ----
__device__ __forceinline__ void mma_bf16(float* c, const unsigned* a, const unsigned* b) {
    asm volatile(
        "mma.sync.aligned.m16n8k16.row.col.f32.bf16.bf16.f32 "
        "{%0,%1,%2,%3}, {%4,%5,%6,%7}, {%8,%9}, {%0,%1,%2,%3};"
        : "+f"(c[0]), "+f"(c[1]), "+f"(c[2]), "+f"(c[3])
        : "r"(a[0]), "r"(a[1]), "r"(a[2]), "r"(a[3]), "r"(b[0]), "r"(b[1]));
}
__device__ __forceinline__ unsigned packbf(float lo, float hi) {
    unsigned d;
    asm("cvt.rn.bf16x2.f32 %0, %1, %2;" : "=r"(d) : "f"(hi), "f"(lo));
    return d;
}
__device__ __forceinline__ void cp16(unsigned dst, const void* src) {
    asm volatile("cp.async.cg.shared.global [%0], [%1], 16;" :: "r"(dst), "l"(src));
}

// ============================================================
// Weight pre-pack: fp32 -> bf16 [m][k]
// ============================================================
__global__ void __launch_bounds__(256) convw_kernel(const float* __restrict__ qkvw,
                                                    const float* __restrict__ projw)
{
    int i = blockIdx.x * 256 + threadIdx.x;
    const int NQ = 3 * NC * NC / 4;
    const int NP = NC * NC / 4;
    if (i < NQ) {
        float4 v = reinterpret_cast<const float4*>(qkvw)[i];
        reinterpret_cast<uint2*>(g_wqkv)[i] = make_uint2(packbf(v.x, v.y), packbf(v.z, v.w));
    } else if (i < NQ + NP) {
        int j = i - NQ;
        float4 v = reinterpret_cast<const float4*>(projw)[j];
        reinterpret_cast<uint2*>(g_wproj)[j] = make_uint2(packbf(v.x, v.y), packbf(v.z, v.w));
    }
}

// ============================================================
// GroupNorm: bf16x2 k-packed out + per-channel affine (scale,shift).
// No fp32 normalized output — proj recomputes residual from x.
// ============================================================
__global__ void __launch_bounds__(256) gn_kernel(const float* __restrict__ x,
                                                 const float* __restrict__ w,
                                                 const float* __restrict__ bias)
{
    int b = blockIdx.x >> 5;
    int g = blockIdx.x & 31;
    const float* xp = x + ((size_t)b * NC + g * CPG) * NHW;

    float s = 0.f, s2 = 0.f;
    for (int i = threadIdx.x; i < CPG * NHW / 4; i += 256) {
        float4 v = reinterpret_cast<const float4*>(xp)[i];
        s  += v.x + v.y + v.z + v.w;
        s2 += v.x * v.x + v.y * v.y + v.z * v.z + v.w * v.w;
    }
    __shared__ float r0[8], r1[8];
    #pragma unroll
    for (int o = 16; o; o >>= 1) {
        s  += __shfl_xor_sync(~0u, s,  o);
        s2 += __shfl_xor_sync(~0u, s2, o);
    }
    int wid = threadIdx.x >> 5, lid = threadIdx.x & 31;
    if (lid == 0) { r0[wid] = s; r1[wid] = s2; }
    __syncthreads();
    if (threadIdx.x < 32) {
        s  = (lid < 8) ? r0[lid] : 0.f;
        s2 = (lid < 8) ? r1[lid] : 0.f;
        #pragma unroll
        for (int o = 4; o; o >>= 1) {
            s  += __shfl_xor_sync(~0u, s,  o);
            s2 += __shfl_xor_sync(~0u, s2, o);
        }
        if (lid == 0) { r0[0] = s; r1[0] = s2; }
    }
    __syncthreads();
    const float inv_n = 1.f / (CPG * NHW);
    float mean = r0[0] * inv_n;
    float var  = r1[0] * inv_n - mean * mean;
    float rinv = rsqrtf(var + 1e-5f);

    // per-channel affine for this group
    if (threadIdx.x < CPG) {
        int c = g * CPG + threadIdx.x;
        float sc = w[c] * rinv;
        g_scale[b * NC + c] = sc;
        g_shift[b * NC + c] = bias[c] - mean * sc;
    }

    unsigned* xb = g_xbf + ((size_t)b * (NC / 2) + g * (CPG / 2)) * NHW;
    for (int i = threadIdx.x; i < (CPG / 2) * (NHW / 4); i += 256) {
        int ul = i >> 8, n4 = (i & 255) * 4;
        int c0 = g * CPG + 2 * ul;
        float w0 = w[c0] * rinv, w1 = w[c0 + 1] * rinv;
        float b0 = bias[c0] - mean * w0, b1 = bias[c0 + 1] - mean * w1;
        float4 xa = *reinterpret_cast<const float4*>(&xp[(2 * ul) * NHW + n4]);
        float4 xc = *reinterpret_cast<const float4*>(&xp[(2 * ul + 1) * NHW + n4]);
        uint4 pk = make_uint4(packbf(xa.x * w0 + b0, xc.x * w1 + b1),
                              packbf(xa.y * w0 + b0, xc.y * w1 + b1),
                              packbf(xa.z * w0 + b0, xc.z * w1 + b1),
                              packbf(xa.w * w0 + b0, xc.w * w1 + b1));
        *reinterpret_cast<uint4*>(&xb[ul * NHW + n4]) = pk;
    }
}

// ============================================================
// bf16 GEMM NN, 3-stage cp.async ring, ONE sync per k-iter.
// MODE 0: qkv — epilogue writes DIRECTLY into fperm2 Q/K/V layouts
//         (fused permute; tile covers exactly channel pair h0,h0+1).
// MODE 1: proj -> out fp32 (+bias + recomputed gn residual from x)
// ============================================================
#define GSTAGE 4736
#define GEMM_SMEM (3 * GSTAGE * 4)

template <int MODE>
__global__ void __launch_bounds__(256, 2) gemm_bf(const float* __restrict__ pbias,
                                                  const float* __restrict__ xin,
                                                  float* __restrict__ outp)
{
    extern __shared__ unsigned gsm[];
    unsigned sbase = (unsigned)__cvta_generic_to_shared(gsm);
    const unsigned* Aw = MODE ? g_wproj : g_wqkv;

    int b  = blockIdx.z;
    int by = blockIdx.y, bx = blockIdx.x;
    int m0 = by << 7;
    int n0 = bx << 7;
    const unsigned* Bw = (MODE ? g_hbf : g_xbf) + (size_t)b * (NC / 2) * NHW;

    int t = threadIdx.x;
    int w = t >> 5, lane = t & 31;
    int gid = lane >> 2, tig = lane & 3;
    int mw = (w >> 2) * 64;
    int nw = (w & 3) * 32;

    float acc[4][4][4];
    #pragma unroll
    for (int i = 0; i < 4; i++)
        #pragma unroll
        for (int j = 0; j < 4; j++)
            #pragma unroll
            for (int c = 0; c < 4; c++) acc[i][j][c] = 0.f;

    auto load_stage = [&](int s, int kp0) {
        unsigned abase = sbase + s * GSTAGE * 4;
        unsigned bbase = abase + 2560 * 4;
        #pragma unroll
        for (int h = 0; h < 2; h++) {
            int ca = t + h * 256;
            int m = ca >> 2, kq = ca & 3;
            cp16(abase + (m * 20 + kq * 4) * 4,
                 Aw + (size_t)(m0 + m) * (NC / 2) + kp0 + kq * 4);
            int kp = ca >> 5, nq = (ca & 31) * 4;
            cp16(bbase + (kp * 136 + nq) * 4,
                 Bw + (size_t)(kp0 + kp) * NHW + n0 + nq);
        }
    };

    load_stage(0, 0);
    asm volatile("cp.async.commit_group;");
    load_stage(1, 16);
    asm volatile("cp.async.commit_group;");

    const int NIT = (NC / 2) / 16;
    for (int it = 0; it < NIT; it++) {
        int s = it % 3;
        const unsigned* As = gsm + s * GSTAGE;
        const unsigned* Bs = As + 2560;

        asm volatile("cp.async.wait_group 1;");
        __syncthreads();
        if (it + 2 < NIT) load_stage((it + 2) % 3, (it + 2) * 16);
        asm volatile("cp.async.commit_group;");

        #pragma unroll
        for (int c2 = 0; c2 < 2; c2++) {
            unsigned a[4][4], bb[4][2];
            #pragma unroll
            for (int mf = 0; mf < 4; mf++) {
                int mi = mw + mf * 16 + gid;
                a[mf][0] = As[mi * 20 + c2 * 8 + tig];
                a[mf][1] = As[(mi + 8) * 20 + c2 * 8 + tig];
                a[mf][2] = As[mi * 20 + c2 * 8 + tig + 4];
                a[mf][3] = As[(mi + 8) * 20 + c2 * 8 + tig + 4];
            }
            #pragma unroll
            for (int nf = 0; nf < 4; nf++) {
                int ni = nw + nf * 8 + gid;
                bb[nf][0] = Bs[(c2 * 8 + tig) * 136 + ni];
                bb[nf][1] = Bs[(c2 * 8 + tig + 4) * 136 + ni];
            }
            #pragma unroll
            for (int mf = 0; mf < 4; mf++)
                #pragma unroll
                for (int nf = 0; nf < 4; nf++)
                    mma_bf16(acc[mf][nf], a[mf], bb[nf]);
        }
    }

    if (MODE == 1) {
        // proj epilogue: +bias + residual recomputed from x
        #pragma unroll
        for (int mf = 0; mf < 4; mf++) {
            int gm = m0 + mw + mf * 16 + gid;
            float sc0 = g_scale[b * NC + gm],     sh0 = g_shift[b * NC + gm];
            float sc1 = g_scale[b * NC + gm + 8], sh1 = g_shift[b * NC + gm + 8];
            float pb0 = pbias[gm], pb1 = pbias[gm + 8];
            #pragma unroll
            for (int nf = 0; nf < 4; nf++) {
                int gn = n0 + nw + nf * 8 + 2 * tig;
                const float* x0 = &xin[((size_t)b * NC + gm) * NHW + gn];
                const float* x1 = &xin[((size_t)b * NC + gm + 8) * NHW + gn];
                float2 v01 = make_float2(acc[mf][nf][0] + pb0 + x0[0] * sc0 + sh0,
                                         acc[mf][nf][1] + pb0 + x0[1] * sc0 + sh0);
                float2 v23 = make_float2(acc[mf][nf][2] + pb1 + x1[0] * sc1 + sh1,
                                         acc[mf][nf][3] + pb1 + x1[1] * sc1 + sh1);
                *reinterpret_cast<float2*>(&outp[((size_t)b * NC + gm) * NHW + gn]) = v01;
                *reinterpret_cast<float2*>(&outp[((size_t)b * NC + gm + 8) * NHW + gn]) = v23;
            }
        }
        return;
    }

    // ===== MODE 0 fused-permute epilogue =====
    asm volatile("cp.async.wait_group 0;");
    __syncthreads();   // all mainloop smem reads done; safe to reuse gsm

    int s  = by >> 2;      // 0:Q 1:K 2:V
    int tg = by & 3;       // h0 = 2*tg
    float qs = (s == 0) ? 0.125f : 1.f;   // fold softmax scale into Q (exact)

    // stage tile to smem as bf16x2 words [128 mloc][66]
    unsigned* esm = gsm;
    #pragma unroll
    for (int mf = 0; mf < 4; mf++) {
        int r0i = mw + mf * 16 + gid;
        #pragma unroll
        for (int nf = 0; nf < 4; nf++) {
            int col = (nw >> 1) + nf * 4 + tig;
            esm[r0i * 66 + col]       = packbf(acc[mf][nf][0] * qs, acc[mf][nf][1] * qs);
            esm[(r0i + 8) * 66 + col] = packbf(acc[mf][nf][2] * qs, acc[mf][nf][3] * qs);
        }
    }
    __syncthreads();

    if (s < 2) {
        // Q/K: word(bh, n2, dsp*16+tg*4+c) ; per uint4: cols n = jj*8+4dsp+{0..3}
        unsigned* dstbase = reinterpret_cast<unsigned*>(s == 0 ? g_qbf : g_kbf);
        #pragma unroll
        for (int k = 0; k < 8; k++) {
            int i = t + k * 256;
            int r    = i >> 8;
            int d_lo = (i >> 5) & 7;
            int jj   = (i >> 1) & 15;
            int dsp  = i & 1;
            int mloc = r * 8 + d_lo;
            int colb = jj * 4 + 2 * dsp;
            uint2 A = *reinterpret_cast<const uint2*>(&esm[mloc * 66 + colb]);
            uint2 B = *reinterpret_cast<const uint2*>(&esm[(mloc + 64) * 66 + colb]);
            uint4 o;
            o.x = __byte_perm(A.x, B.x, 0x5410);
            o.y = __byte_perm(A.x, B.x, 0x7632);
            o.z = __byte_perm(A.y, B.y, 0x5410);
            o.w = __byte_perm(A.y, B.y, 0x7632);
            size_t n2 = (size_t)d_lo * 128 + bx * 16 + jj;
            size_t wadr = (((size_t)(b * 8 + r) * NHW) + n2) * 32 + dsp * 16 + tg * 4;
            *reinterpret_cast<uint4*>(&dstbase[wadr]) = o;
        }
    } else {
        // V: word(bh, d2=c2*8+h0+hh, p=d_lo*64+8bx+q) at scrambled wpos.
        // STG.64 covers b0=0,1 (q=tigv, tigv+4); c = 2(bx&1)+b0.
        unsigned* dstbase = reinterpret_cast<unsigned*>(g_vbf);
        int wposb = ((bx >> 1) & 1) * 16 + 2 * (bx & 1);
        #pragma unroll
        for (int k = 0; k < 16; k++) {
            int j = t + k * 256;
            int r    = j >> 9;
            int d2i  = (j >> 5) & 15;
            int c2   = d2i >> 1;
            int hh   = d2i & 1;
            int d_lo = (j >> 2) & 7;
            int tgv  = j & 3;
            int d2   = c2 * 8 + 2 * tg + hh;
            int mloc = hh * 64 + r * 8 + d_lo;
            unsigned sel = (c2 & 1) ? 0x7632 : 0x5410;
            int wA0 = 8 * tgv + (c2 >> 1);
            int wA1 = wA0 + 32;                 // q = tgv+4 -> +8*4
            uint2 o;
            o.x = __byte_perm(esm[mloc * 66 + wA0], esm[mloc * 66 + wA0 + 4], sel);
            o.y = __byte_perm(esm[mloc * 66 + wA1], esm[mloc * 66 + wA1 + 4], sel);
            size_t wadr = ((size_t)(b * 8 + r) * HD + d2) * 512
                        + (size_t)(d_lo * 2 + (bx >> 2)) * 32
                        + wposb + tgv * 4;
            *reinterpret_cast<uint2*>(&dstbase[wadr]) = o;
        }
    }
}

// ============================================================
// Flash attention v9 — bf16 mma, 3-stage cp.async, LDS.128 b-frags.
// Q pre-scaled by 1/8 (no scale mults in loop).
// ============================================================
#define KVSTRIDE 48
#define STG_WORDS (2 * 64 * KVSTRIDE)
#define FLASH_SMEM (3 * STG_WORDS * 4)

__global__ void __launch_bounds__(256, 2) flash_kernel()
{
    extern __shared__ unsigned dynsm[];

    int bh    = blockIdx.x >> 3;
    int qtile = blockIdx.x & 7;
    int b = bh >> 3, r = bh & 7;

    const unsigned* Qp = reinterpret_cast<const unsigned*>(g_qbf + (size_t)bh * NHW * HD);
    const __nv_bfloat16* Kp = g_kbf + (size_t)bh * NHW * HD;
    const __nv_bfloat16* Vp = g_vbf + (size_t)bh * HD * NHW;

    int t = threadIdx.x;
    int w = t >> 5, lane = t & 31;
    int gid = lane >> 2, tig = lane & 3;
    int i0w = w * 16;
    int ibase = qtile * 128 + i0w + gid;

    unsigned qa[4][4];
    {
        const unsigned* qr0 = Qp + (size_t)ibase * 32;
        const unsigned* qr8 = qr0 + 8 * 32;
        #pragma unroll
        for (int ds = 0; ds < 4; ds++) {
            int off = (ds >> 1) * 16 + tig * 4 + (ds & 1) * 2;
            uint2 u0 = *reinterpret_cast<const uint2*>(qr0 + off);
            uint2 u8 = *reinterpret_cast<const uint2*>(qr8 + off);
            qa[ds][0] = u0.x;
            qa[ds][1] = u8.x;
            qa[ds][2] = u0.y;
            qa[ds][3] = u8.y;
        }
    }

    float acc_o[8][4];
    #pragma unroll
    for (int i = 0; i < 8; i++)
        #pragma unroll
        for (int c = 0; c < 4; c++) acc_o[i][c] = 0.f;
    float row_m0 = -1e30f, row_m1 = -1e30f;
    float row_l0 = 0.f, row_l1 = 0.f;

    auto load_tiles = [&](int st, int kt) {
        unsigned kb = (unsigned)__cvta_generic_to_shared(dynsm + st * STG_WORDS);
        unsigned vb = kb + 64 * KVSTRIDE * 4;
        int j0 = kt * 64;
        #pragma unroll
        for (int h = 0; h < 2; h++) {
            int ca = t + h * 256;
            int row = ca >> 3, ch = ca & 7;
            cp16(kb + (row * KVSTRIDE + ch * 4) * 4, Kp + (size_t)(j0 + row) * HD + ch * 8);
            cp16(vb + (row * KVSTRIDE + ch * 4) * 4, Vp + (size_t)row * NHW + j0 + ch * 8);
        }
    };

    load_tiles(0, 0);
    asm volatile("cp.async.commit_group;");
    load_tiles(1, 1);
    asm volatile("cp.async.commit_group;");

    for (int kt = 0; kt < 16; kt++) {
        int st = kt % 3;
        const unsigned* kbuf = dynsm + st * STG_WORDS;
        const unsigned* vbuf = kbuf + 64 * KVSTRIDE;

        asm volatile("cp.async.wait_group 1;");
        __syncthreads();
        if (kt + 2 < 16) load_tiles((kt + 2) % 3, kt + 2);
        asm volatile("cp.async.commit_group;");

        // ---- S = Q K^T (Q pre-scaled) ----
        float p[8][4];
        #pragma unroll
        for (int i = 0; i < 8; i++)
            #pragma unroll
            for (int c = 0; c < 4; c++) p[i][c] = 0.f;

        #pragma unroll
        for (int dsp = 0; dsp < 2; dsp++) {
            #pragma unroll
            for (int nf = 0; nf < 8; nf++) {
                uint4 k4 = *reinterpret_cast<const uint4*>(
                    &kbuf[(nf * 8 + gid) * KVSTRIDE + dsp * 16 + tig * 4]);
                unsigned b0[2] = {k4.x, k4.y};
                mma_bf16(p[nf], qa[2 * dsp], b0);
                unsigned b1[2] = {k4.z, k4.w};
                mma_bf16(p[nf], qa[2 * dsp + 1], b1);
            }
        }

        // ---- online softmax (no scale mults) ----
        float tmax0 = -1e30f, tmax1 = -1e30f;
        #pragma unroll
        for (int nf = 0; nf < 8; nf++) {
            tmax0 = fmaxf(tmax0, fmaxf(p[nf][0], p[nf][1]));
            tmax1 = fmaxf(tmax1, fmaxf(p[nf][2], p[nf][3]));
        }
        tmax0 = fmaxf(tmax0, __shfl_xor_sync(~0u, tmax0, 1));
        tmax0 = fmaxf(tmax0, __shfl_xor_sync(~0u, tmax0, 2));
        tmax1 = fmaxf(tmax1, __shfl_xor_sync(~0u, tmax1, 1));
        tmax1 = fmaxf(tmax1, __shfl_xor_sync(~0u, tmax1, 2));

        float nm0 = fmaxf(row_m0, tmax0);
        float nm1 = fmaxf(row_m1, tmax1);
        float corr0 = __expf(row_m0 - nm0);
        float corr1 = __expf(row_m1 - nm1);

        float sum0 = 0.f, sum1 = 0.f;
        #pragma unroll
        for (int nf = 0; nf < 8; nf++) {
            p[nf][0] = __expf(p[nf][0] - nm0);
            p[nf][1] = __expf(p[nf][1] - nm0);
            p[nf][2] = __expf(p[nf][2] - nm1);
            p[nf][3] = __expf(p[nf][3] - nm1);
            sum0 += p[nf][0] + p[nf][1];
            sum1 += p[nf][2] + p[nf][3];
        }
        sum0 += __shfl_xor_sync(~0u, sum0, 1);
        sum0 += __shfl_xor_sync(~0u, sum0, 2);
        sum1 += __shfl_xor_sync(~0u, sum1, 1);
        sum1 += __shfl_xor_sync(~0u, sum1, 2);

        row_l0 = row_l0 * corr0 + sum0;
        row_l1 = row_l1 * corr1 + sum1;
        row_m0 = nm0; row_m1 = nm1;

        #pragma unroll
        for (int nf2 = 0; nf2 < 8; nf2++) {
            acc_o[nf2][0] *= corr0; acc_o[nf2][1] *= corr0;
            acc_o[nf2][2] *= corr1; acc_o[nf2][3] *= corr1;
        }

        // ---- O += P V^T ----
        #pragma unroll
        for (int jsp = 0; jsp < 2; jsp++) {
            unsigned pa0[4], pa1[4];
            pa0[0] = packbf(p[4 * jsp][0],     p[4 * jsp][1]);
            pa0[1] = packbf(p[4 * jsp][2],     p[4 * jsp][3]);
            pa0[2] = packbf(p[4 * jsp + 1][0], p[4 * jsp + 1][1]);
            pa0[3] = packbf(p[4 * jsp + 1][2], p[4 * jsp + 1][3]);
            pa1[0] = packbf(p[4 * jsp + 2][0], p[4 * jsp + 2][1]);
            pa1[1] = packbf(p[4 * jsp + 2][2], p[4 * jsp + 2][3]);
            pa1[2] = packbf(p[4 * jsp + 3][0], p[4 * jsp + 3][1]);
            pa1[3] = packbf(p[4 * jsp + 3][2], p[4 * jsp + 3][3]);
            #pragma unroll
            for (int nf2 = 0; nf2 < 8; nf2++) {
                uint4 v4 = *reinterpret_cast<const uint4*>(
                    &vbuf[(nf2 * 8 + gid) * KVSTRIDE + jsp * 16 + tig * 4]);
                unsigned b0[2] = {v4.x, v4.y};
                mma_bf16(acc_o[nf2], pa0, b0);
                unsigned b1[2] = {v4.z, v4.w};
                mma_bf16(acc_o[nf2], pa1, b1);
            }
        }
    }

    // ---- epilogue: O /= l, write packed bf16x2 into g_hbf ----
    float inv0 = 1.f / row_l0, inv1 = 1.f / row_l1;
    unsigned* Hb = g_hbf + ((size_t)b * (NC / 2) + r * (HD / 2)) * NHW;
    #pragma unroll
    for (int nf2 = 0; nf2 < 8; nf2++) {
        int u = nf2 * 4 + tig;
        Hb[(size_t)u * NHW + ibase]     = packbf(acc_o[nf2][0] * inv0, acc_o[nf2][1] * inv0);
        Hb[(size_t)u * NHW + ibase + 8] = packbf(acc_o[nf2][2] * inv1, acc_o[nf2][3] * inv1);
    }
}

// ============================================================
extern "C" void kernel_launch(void* const* d_in, const int* in_sizes, int n_in,
                              void* d_out, int out_size)
{
    const float* x      = (const float*)d_in[0];
    const float* gn_w   = (const float*)d_in[1];
    const float* gn_b   = (const float*)d_in[2];
    const float* qkv_w  = (const float*)d_in[3];
    const float* proj_w = (const float*)d_in[4];
    const float* proj_b = (const float*)d_in[5];
    float* out = (float*)d_out;

    cudaFuncSetAttribute(flash_kernel, cudaFuncAttributeMaxDynamicSharedMemorySize, FLASH_SMEM);
    cudaFuncSetAttribute(gemm_bf<0>, cudaFuncAttributeMaxDynamicSharedMemorySize, GEMM_SMEM);
    cudaFuncSetAttribute(gemm_bf<1>, cudaFuncAttributeMaxDynamicSharedMemorySize, GEMM_SMEM);

    convw_kernel<<<1024, 256>>>(qkv_w, proj_w);
    gn_kernel<<<NB * NG, 256>>>(x, gn_w, gn_b);
    gemm_bf<0><<<dim3(8, 12, NB), 256, GEMM_SMEM>>>(nullptr, nullptr, nullptr);
    flash_kernel<<<NB * NHEADS * 8, 256, FLASH_SMEM>>>();
    gemm_bf<1><<<dim3(8, 4, NB), 256, GEMM_SMEM>>>(proj_b, x, out);
}

// round 15
// speedup vs baseline: 10.7280x; 1.0667x over previous
#include <cuda_runtime.h>
#include <cuda_bf16.h>
#include <math.h>

#define NB 16
#define NC 512
#define NHW 1024
#define NHEADS 8
#define HD 64
#define NG 32
#define CPG 16

// ---- scratch ----
__device__ unsigned g_xbf[(size_t)NB * (NC / 2) * NHW];         // bf16x2 [b][c/2][n] (k-packed)
__device__ float g_scale[NB * NC];                              // gn affine: x*scale+shift
__device__ float g_shift[NB * NC];
__device__ __nv_bfloat16 g_qbf[(size_t)NB * NHEADS * NHW * HD]; // bf16 Q (fperm2, pre-scaled log2e/8)
__device__ __nv_bfloat16 g_kbf[(size_t)NB * NHEADS * NHW * HD]; // bf16 K (fperm2)
__device__ __nv_bfloat16 g_vbf[(size_t)NB * NHEADS * HD * NHW]; // bf16 V (fperm2)
__device__ unsigned g_hbf[(size_t)NB * (NC / 2) * NHW];         // bf16x2 packed h (k-packed)
__device__ unsigned g_wqkv[3 * NC * NC / 2];                    // bf16 qkv_w (a-frag interleaved)
__device__ unsigned g_wproj[NC * NC / 2];                       // bf16 proj_w (a-frag interleaved)

// ---- helpers ----
__device__ __forceinline__ void mma_bf16(float* c, const unsigned* a, const unsigned* b) {
    asm volatile(
        "mma.sync.aligned.m16n8k16.row.col.f32.bf16.bf16.f32 "
        "{%0,%1,%2,%3}, {%4,%5,%6,%7}, {%8,%9}, {%0,%1,%2,%3};"
        : "+f"(c[0]), "+f"(c[1]), "+f"(c[2]), "+f"(c[3])
        : "r"(a[0]), "r"(a[1]), "r"(a[2]), "r"(a[3]), "r"(b[0]), "r"(b[1]));
}
__device__ __forceinline__ unsigned packbf(float lo, float hi) {
    unsigned d;
    asm("cvt.rn.bf16x2.f32 %0, %1, %2;" : "=r"(d) : "f"(hi), "f"(lo));
    return d;
}
__device__ __forceinline__ void cp16(unsigned dst, const void* src) {
    asm volatile("cp.async.cg.shared.global [%0], [%1], 16;" :: "r"(dst), "l"(src));
}
__device__ __forceinline__ float ex2f(float x) {
    float r;
    asm("ex2.approx.f32 %0, %1;" : "=f"(r) : "f"(x));
    return r;
}

// a-frag interleaved weight address for word (m, kw), kw = k/2
__device__ __forceinline__ int wfaddr(int m, int kw) {
    int mbg = m >> 4, gid = m & 7, r8 = (m >> 3) & 1;
    int kchunk = kw >> 4, kin = kw & 15;
    int c2 = kin >> 3, kk = kin & 7;
    int tg = kk & 3, half = kk >> 2;
    return ((mbg * 16 + kchunk) << 8) + ((c2 * 8 + gid) * 4 + tg) * 4 + r8 + 2 * half;
}

// ============================================================
// Weight pre-pack: fp32 -> bf16, a-fragment interleaved
// ============================================================
__global__ void __launch_bounds__(256) convw_kernel(const float* __restrict__ qkvw,
                                                    const float* __restrict__ projw)
{
    int i = blockIdx.x * 256 + threadIdx.x;
    const int NQ2 = 3 * NC * NC / 2;
    const int NP2 = NC * NC / 2;
    if (i < NQ2) {
        int m = i >> 8, kw = i & 255;
        float2 v = *reinterpret_cast<const float2*>(&qkvw[m * NC + 2 * kw]);
        g_wqkv[wfaddr(m, kw)] = packbf(v.x, v.y);
    } else if (i < NQ2 + NP2) {
        int j = i - NQ2;
        int m = j >> 8, kw = j & 255;
        float2 v = *reinterpret_cast<const float2*>(&projw[m * NC + 2 * kw]);
        g_wproj[wfaddr(m, kw)] = packbf(v.x, v.y);
    }
}

// ============================================================
// GroupNorm: bf16x2 k-packed out + per-channel affine (scale,shift)
// ============================================================
__global__ void __launch_bounds__(256) gn_kernel(const float* __restrict__ x,
                                                 const float* __restrict__ w,
                                                 const float* __restrict__ bias)
{
    int b = blockIdx.x >> 5;
    int g = blockIdx.x & 31;
    const float* xp = x + ((size_t)b * NC + g * CPG) * NHW;

    float s = 0.f, s2 = 0.f;
    for (int i = threadIdx.x; i < CPG * NHW / 4; i += 256) {
        float4 v = reinterpret_cast<const float4*>(xp)[i];
        s  += v.x + v.y + v.z + v.w;
        s2 += v.x * v.x + v.y * v.y + v.z * v.z + v.w * v.w;
    }
    __shared__ float r0[8], r1[8];
    #pragma unroll
    for (int o = 16; o; o >>= 1) {
        s  += __shfl_xor_sync(~0u, s,  o);
        s2 += __shfl_xor_sync(~0u, s2, o);
    }
    int wid = threadIdx.x >> 5, lid = threadIdx.x & 31;
    if (lid == 0) { r0[wid] = s; r1[wid] = s2; }
    __syncthreads();
    if (threadIdx.x < 32) {
        s  = (lid < 8) ? r0[lid] : 0.f;
        s2 = (lid < 8) ? r1[lid] : 0.f;
        #pragma unroll
        for (int o = 4; o; o >>= 1) {
            s  += __shfl_xor_sync(~0u, s,  o);
            s2 += __shfl_xor_sync(~0u, s2, o);
        }
        if (lid == 0) { r0[0] = s; r1[0] = s2; }
    }
    __syncthreads();
    const float inv_n = 1.f / (CPG * NHW);
    float mean = r0[0] * inv_n;
    float var  = r1[0] * inv_n - mean * mean;
    float rinv = rsqrtf(var + 1e-5f);

    if (threadIdx.x < CPG) {
        int c = g * CPG + threadIdx.x;
        float sc = w[c] * rinv;
        g_scale[b * NC + c] = sc;
        g_shift[b * NC + c] = bias[c] - mean * sc;
    }

    unsigned* xb = g_xbf + ((size_t)b * (NC / 2) + g * (CPG / 2)) * NHW;
    for (int i = threadIdx.x; i < (CPG / 2) * (NHW / 4); i += 256) {
        int ul = i >> 8, n4 = (i & 255) * 4;
        int c0 = g * CPG + 2 * ul;
        float w0 = w[c0] * rinv, w1 = w[c0 + 1] * rinv;
        float b0 = bias[c0] - mean * w0, b1 = bias[c0 + 1] - mean * w1;
        float4 xa = *reinterpret_cast<const float4*>(&xp[(2 * ul) * NHW + n4]);
        float4 xc = *reinterpret_cast<const float4*>(&xp[(2 * ul + 1) * NHW + n4]);
        uint4 pk = make_uint4(packbf(xa.x * w0 + b0, xc.x * w1 + b1),
                              packbf(xa.y * w0 + b0, xc.y * w1 + b1),
                              packbf(xa.z * w0 + b0, xc.z * w1 + b1),
                              packbf(xa.w * w0 + b0, xc.w * w1 + b1));
        *reinterpret_cast<uint4*>(&xb[ul * NHW + n4]) = pk;
    }
}

// ============================================================
// bf16 GEMM NN, 3-stage cp.async ring, A-frags via LDS.128.
// Stage: A 2048 words (interleaved) + B 16x136 = 4224 words.
// MODE 0: qkv — fused-permute epilogue into Q/K/V layouts.
// MODE 1: proj -> out fp32 (+bias + recomputed residual)
// ============================================================
#define GSTAGE 4224
#define GEMM_SMEM (3 * GSTAGE * 4)

template <int MODE>
__global__ void __launch_bounds__(256, 2) gemm_bf(const float* __restrict__ pbias,
                                                  const float* __restrict__ xin,
                                                  float* __restrict__ outp)
{
    extern __shared__ unsigned gsm[];
    unsigned sbase = (unsigned)__cvta_generic_to_shared(gsm);
    const unsigned* Aw = MODE ? g_wproj : g_wqkv;

    int b  = blockIdx.z;
    int by = blockIdx.y, bx = blockIdx.x;
    int m0 = by << 7;
    int n0 = bx << 7;
    const unsigned* Bw = (MODE ? g_hbf : g_xbf) + (size_t)b * (NC / 2) * NHW;

    int t = threadIdx.x;
    int w = t >> 5, lane = t & 31;
    int gid = lane >> 2, tig = lane & 3;
    int mw = (w >> 2) * 64;
    int nw = (w & 3) * 32;

    float acc[4][4][4];
    #pragma unroll
    for (int i = 0; i < 4; i++)
        #pragma unroll
        for (int j = 0; j < 4; j++)
            #pragma unroll
            for (int c = 0; c < 4; c++) acc[i][j][c] = 0.f;

    auto load_stage = [&](int s, int kc) {
        unsigned abase = sbase + s * GSTAGE * 4;
        unsigned bbase = abase + 2048 * 4;
        #pragma unroll
        for (int h = 0; h < 2; h++) {
            int ca = t + h * 256;
            // A: interleaved chunk, 8 m-blocks x 256 words, contiguous per block
            cp16(abase + ca * 16,
                 Aw + ((size_t)((m0 >> 4) + (ca >> 6)) * 16 + kc) * 256 + (ca & 63) * 4);
            // B: 16 k-rows x 128 words
            int kp = ca >> 5, nq = (ca & 31) * 4;
            cp16(bbase + (kp * 136 + nq) * 4,
                 Bw + (size_t)(kc * 16 + kp) * NHW + n0 + nq);
        }
    };

    load_stage(0, 0);
    asm volatile("cp.async.commit_group;");
    load_stage(1, 1);
    asm volatile("cp.async.commit_group;");

    const int NIT = (NC / 2) / 16;
    for (int it = 0; it < NIT; it++) {
        int s = it % 3;
        const unsigned* As = gsm + s * GSTAGE;
        const unsigned* Bs = As + 2048;

        asm volatile("cp.async.wait_group 1;");
        __syncthreads();
        if (it + 2 < NIT) load_stage((it + 2) % 3, it + 2);
        asm volatile("cp.async.commit_group;");

        #pragma unroll
        for (int c2 = 0; c2 < 2; c2++) {
            unsigned a[4][4], bb[4][2];
            #pragma unroll
            for (int mf = 0; mf < 4; mf++) {
                int mb = (w >> 2) * 4 + mf;
                uint4 a4 = *reinterpret_cast<const uint4*>(
                    &As[mb * 256 + ((c2 * 8 + gid) * 4 + tig) * 4]);
                a[mf][0] = a4.x; a[mf][1] = a4.y; a[mf][2] = a4.z; a[mf][3] = a4.w;
            }
            #pragma unroll
            for (int nf = 0; nf < 4; nf++) {
                int ni = nw + nf * 8 + gid;
                bb[nf][0] = Bs[(c2 * 8 + tig) * 136 + ni];
                bb[nf][1] = Bs[(c2 * 8 + tig + 4) * 136 + ni];
            }
            #pragma unroll
            for (int mf = 0; mf < 4; mf++)
                #pragma unroll
                for (int nf = 0; nf < 4; nf++)
                    mma_bf16(acc[mf][nf], a[mf], bb[nf]);
        }
    }

    if (MODE == 1) {
        #pragma unroll
        for (int mf = 0; mf < 4; mf++) {
            int gm = m0 + mw + mf * 16 + gid;
            float sc0 = g_scale[b * NC + gm],     sh0 = g_shift[b * NC + gm];
            float sc1 = g_scale[b * NC + gm + 8], sh1 = g_shift[b * NC + gm + 8];
            float pb0 = pbias[gm], pb1 = pbias[gm + 8];
            #pragma unroll
            for (int nf = 0; nf < 4; nf++) {
                int gn = n0 + nw + nf * 8 + 2 * tig;
                const float* x0 = &xin[((size_t)b * NC + gm) * NHW + gn];
                const float* x1 = &xin[((size_t)b * NC + gm + 8) * NHW + gn];
                float2 v01 = make_float2(acc[mf][nf][0] + pb0 + x0[0] * sc0 + sh0,
                                         acc[mf][nf][1] + pb0 + x0[1] * sc0 + sh0);
                float2 v23 = make_float2(acc[mf][nf][2] + pb1 + x1[0] * sc1 + sh1,
                                         acc[mf][nf][3] + pb1 + x1[1] * sc1 + sh1);
                *reinterpret_cast<float2*>(&outp[((size_t)b * NC + gm) * NHW + gn]) = v01;
                *reinterpret_cast<float2*>(&outp[((size_t)b * NC + gm + 8) * NHW + gn]) = v23;
            }
        }
        return;
    }

    // ===== MODE 0 fused-permute epilogue =====
    asm volatile("cp.async.wait_group 0;");
    __syncthreads();

    int s  = by >> 2;      // 0:Q 1:K 2:V
    int tg = by & 3;       // h0 = 2*tg
    float qs = (s == 0) ? 0.125f * 1.4426950408889634f : 1.f;  // fold scale*log2e into Q

    unsigned* esm = gsm;
    #pragma unroll
    for (int mf = 0; mf < 4; mf++) {
        int r0i = mw + mf * 16 + gid;
        #pragma unroll
        for (int nf = 0; nf < 4; nf++) {
            int col = (nw >> 1) + nf * 4 + tig;
            esm[r0i * 66 + col]       = packbf(acc[mf][nf][0] * qs, acc[mf][nf][1] * qs);
            esm[(r0i + 8) * 66 + col] = packbf(acc[mf][nf][2] * qs, acc[mf][nf][3] * qs);
        }
    }
    __syncthreads();

    if (s < 2) {
        unsigned* dstbase = reinterpret_cast<unsigned*>(s == 0 ? g_qbf : g_kbf);
        #pragma unroll
        for (int k = 0; k < 8; k++) {
            int i = t + k * 256;
            int r    = i >> 8;
            int d_lo = (i >> 5) & 7;
            int jj   = (i >> 1) & 15;
            int dsp  = i & 1;
            int mloc = r * 8 + d_lo;
            int colb = jj * 4 + 2 * dsp;
            uint2 A = *reinterpret_cast<const uint2*>(&esm[mloc * 66 + colb]);
            uint2 B = *reinterpret_cast<const uint2*>(&esm[(mloc + 64) * 66 + colb]);
            uint4 o;
            o.x = __byte_perm(A.x, B.x, 0x5410);
            o.y = __byte_perm(A.x, B.x, 0x7632);
            o.z = __byte_perm(A.y, B.y, 0x5410);
            o.w = __byte_perm(A.y, B.y, 0x7632);
            size_t n2 = (size_t)d_lo * 128 + bx * 16 + jj;
            size_t wadr = (((size_t)(b * 8 + r) * NHW) + n2) * 32 + dsp * 16 + tg * 4;
            *reinterpret_cast<uint4*>(&dstbase[wadr]) = o;
        }
    } else {
        unsigned* dstbase = reinterpret_cast<unsigned*>(g_vbf);
        int wposb = ((bx >> 1) & 1) * 16 + 2 * (bx & 1);
        #pragma unroll
        for (int k = 0; k < 16; k++) {
            int j = t + k * 256;
            int r    = j >> 9;
            int d2i  = (j >> 5) & 15;
            int c2   = d2i >> 1;
            int hh   = d2i & 1;
            int d_lo = (j >> 2) & 7;
            int tgv  = j & 3;
            int d2   = c2 * 8 + 2 * tg + hh;
            int mloc = hh * 64 + r * 8 + d_lo;
            unsigned sel = (c2 & 1) ? 0x7632 : 0x5410;
            int wA0 = 8 * tgv + (c2 >> 1);
            int wA1 = wA0 + 32;
            uint2 o;
            o.x = __byte_perm(esm[mloc * 66 + wA0], esm[mloc * 66 + wA0 + 4], sel);
            o.y = __byte_perm(esm[mloc * 66 + wA1], esm[mloc * 66 + wA1 + 4], sel);
            size_t wadr = ((size_t)(b * 8 + r) * HD + d2) * 512
                        + (size_t)(d_lo * 2 + (bx >> 2)) * 32
                        + wposb + tgv * 4;
            *reinterpret_cast<uint2*>(&dstbase[wadr]) = o;
        }
    }
}

// ============================================================
// Flash attention v10 — exp2 softmax (Q pre-scaled log2e/8).
// ============================================================
#define KVSTRIDE 48
#define STG_WORDS (2 * 64 * KVSTRIDE)
#define FLASH_SMEM (3 * STG_WORDS * 4)

__global__ void __launch_bounds__(256, 2) flash_kernel()
{
    extern __shared__ unsigned dynsm[];

    int bh    = blockIdx.x >> 3;
    int qtile = blockIdx.x & 7;
    int b = bh >> 3, r = bh & 7;

    const unsigned* Qp = reinterpret_cast<const unsigned*>(g_qbf + (size_t)bh * NHW * HD);
    const __nv_bfloat16* Kp = g_kbf + (size_t)bh * NHW * HD;
    const __nv_bfloat16* Vp = g_vbf + (size_t)bh * HD * NHW;

    int t = threadIdx.x;
    int w = t >> 5, lane = t & 31;
    int gid = lane >> 2, tig = lane & 3;
    int i0w = w * 16;
    int ibase = qtile * 128 + i0w + gid;

    unsigned qa[4][4];
    {
        const unsigned* qr0 = Qp + (size_t)ibase * 32;
        const unsigned* qr8 = qr0 + 8 * 32;
        #pragma unroll
        for (int ds = 0; ds < 4; ds++) {
            int off = (ds >> 1) * 16 + tig * 4 + (ds & 1) * 2;
            uint2 u0 = *reinterpret_cast<const uint2*>(qr0 + off);
            uint2 u8 = *reinterpret_cast<const uint2*>(qr8 + off);
            qa[ds][0] = u0.x;
            qa[ds][1] = u8.x;
            qa[ds][2] = u0.y;
            qa[ds][3] = u8.y;
        }
    }

    float acc_o[8][4];
    #pragma unroll
    for (int i = 0; i < 8; i++)
        #pragma unroll
        for (int c = 0; c < 4; c++) acc_o[i][c] = 0.f;
    float row_m0 = -1e30f, row_m1 = -1e30f;
    float row_l0 = 0.f, row_l1 = 0.f;

    auto load_tiles = [&](int st, int kt) {
        unsigned kb = (unsigned)__cvta_generic_to_shared(dynsm + st * STG_WORDS);
        unsigned vb = kb + 64 * KVSTRIDE * 4;
        int j0 = kt * 64;
        #pragma unroll
        for (int h = 0; h < 2; h++) {
            int ca = t + h * 256;
            int row = ca >> 3, ch = ca & 7;
            cp16(kb + (row * KVSTRIDE + ch * 4) * 4, Kp + (size_t)(j0 + row) * HD + ch * 8);
            cp16(vb + (row * KVSTRIDE + ch * 4) * 4, Vp + (size_t)row * NHW + j0 + ch * 8);
        }
    };

    load_tiles(0, 0);
    asm volatile("cp.async.commit_group;");
    load_tiles(1, 1);
    asm volatile("cp.async.commit_group;");

    for (int kt = 0; kt < 16; kt++) {
        int st = kt % 3;
        const unsigned* kbuf = dynsm + st * STG_WORDS;
        const unsigned* vbuf = kbuf + 64 * KVSTRIDE;

        asm volatile("cp.async.wait_group 1;");
        __syncthreads();
        if (kt + 2 < 16) load_tiles((kt + 2) % 3, kt + 2);
        asm volatile("cp.async.commit_group;");

        // ---- S = Q K^T (pre-scaled by log2e/8) ----
        float p[8][4];
        #pragma unroll
        for (int i = 0; i < 8; i++)
            #pragma unroll
            for (int c = 0; c < 4; c++) p[i][c] = 0.f;

        #pragma unroll
        for (int dsp = 0; dsp < 2; dsp++) {
            #pragma unroll
            for (int nf = 0; nf < 8; nf++) {
                uint4 k4 = *reinterpret_cast<const uint4*>(
                    &kbuf[(nf * 8 + gid) * KVSTRIDE + dsp * 16 + tig * 4]);
                unsigned b0[2] = {k4.x, k4.y};
                mma_bf16(p[nf], qa[2 * dsp], b0);
                unsigned b1[2] = {k4.z, k4.w};
                mma_bf16(p[nf], qa[2 * dsp + 1], b1);
            }
        }

        // ---- online softmax in base 2 ----
        float tmax0 = -1e30f, tmax1 = -1e30f;
        #pragma unroll
        for (int nf = 0; nf < 8; nf++) {
            tmax0 = fmaxf(tmax0, fmaxf(p[nf][0], p[nf][1]));
            tmax1 = fmaxf(tmax1, fmaxf(p[nf][2], p[nf][3]));
        }
        tmax0 = fmaxf(tmax0, __shfl_xor_sync(~0u, tmax0, 1));
        tmax0 = fmaxf(tmax0, __shfl_xor_sync(~0u, tmax0, 2));
        tmax1 = fmaxf(tmax1, __shfl_xor_sync(~0u, tmax1, 1));
        tmax1 = fmaxf(tmax1, __shfl_xor_sync(~0u, tmax1, 2));

        float nm0 = fmaxf(row_m0, tmax0);
        float nm1 = fmaxf(row_m1, tmax1);
        float corr0 = ex2f(row_m0 - nm0);
        float corr1 = ex2f(row_m1 - nm1);

        float sum0 = 0.f, sum1 = 0.f;
        #pragma unroll
        for (int nf = 0; nf < 8; nf++) {
            p[nf][0] = ex2f(p[nf][0] - nm0);
            p[nf][1] = ex2f(p[nf][1] - nm0);
            p[nf][2] = ex2f(p[nf][2] - nm1);
            p[nf][3] = ex2f(p[nf][3] - nm1);
            sum0 += p[nf][0] + p[nf][1];
            sum1 += p[nf][2] + p[nf][3];
        }
        sum0 += __shfl_xor_sync(~0u, sum0, 1);
        sum0 += __shfl_xor_sync(~0u, sum0, 2);
        sum1 += __shfl_xor_sync(~0u, sum1, 1);
        sum1 += __shfl_xor_sync(~0u, sum1, 2);

        row_l0 = row_l0 * corr0 + sum0;
        row_l1 = row_l1 * corr1 + sum1;
        row_m0 = nm0; row_m1 = nm1;

        #pragma unroll
        for (int nf2 = 0; nf2 < 8; nf2++) {
            acc_o[nf2][0] *= corr0; acc_o[nf2][1] *= corr0;
            acc_o[nf2][2] *= corr1; acc_o[nf2][3] *= corr1;
        }

        // ---- O += P V^T ----
        #pragma unroll
        for (int jsp = 0; jsp < 2; jsp++) {
            unsigned pa0[4], pa1[4];
            pa0[0] = packbf(p[4 * jsp][0],     p[4 * jsp][1]);
            pa0[1] = packbf(p[4 * jsp][2],     p[4 * jsp][3]);
            pa0[2] = packbf(p[4 * jsp + 1][0], p[4 * jsp + 1][1]);
            pa0[3] = packbf(p[4 * jsp + 1][2], p[4 * jsp + 1][3]);
            pa1[0] = packbf(p[4 * jsp + 2][0], p[4 * jsp + 2][1]);
            pa1[1] = packbf(p[4 * jsp + 2][2], p[4 * jsp + 2][3]);
            pa1[2] = packbf(p[4 * jsp + 3][0], p[4 * jsp + 3][1]);
            pa1[3] = packbf(p[4 * jsp + 3][2], p[4 * jsp + 3][3]);
            #pragma unroll
            for (int nf2 = 0; nf2 < 8; nf2++) {
                uint4 v4 = *reinterpret_cast<const uint4*>(
                    &vbuf[(nf2 * 8 + gid) * KVSTRIDE + jsp * 16 + tig * 4]);
                unsigned b0[2] = {v4.x, v4.y};
                mma_bf16(acc_o[nf2], pa0, b0);
                unsigned b1[2] = {v4.z, v4.w};
                mma_bf16(acc_o[nf2], pa1, b1);
            }
        }
    }

    // ---- epilogue ----
    float inv0 = 1.f / row_l0, inv1 = 1.f / row_l1;
    unsigned* Hb = g_hbf + ((size_t)b * (NC / 2) + r * (HD / 2)) * NHW;
    #pragma unroll
    for (int nf2 = 0; nf2 < 8; nf2++) {
        int u = nf2 * 4 + tig;
        Hb[(size_t)u * NHW + ibase]     = packbf(acc_o[nf2][0] * inv0, acc_o[nf2][1] * inv0);
        Hb[(size_t)u * NHW + ibase + 8] = packbf(acc_o[nf2][2] * inv1, acc_o[nf2][3] * inv1);
    }
}

// ============================================================
extern "C" void kernel_launch(void* const* d_in, const int* in_sizes, int n_in,
                              void* d_out, int out_size)
{
    const float* x      = (const float*)d_in[0];
    const float* gn_w   = (const float*)d_in[1];
    const float* gn_b   = (const float*)d_in[2];
    const float* qkv_w  = (const float*)d_in[3];
    const float* proj_w = (const float*)d_in[4];
    const float* proj_b = (const float*)d_in[5];
    float* out = (float*)d_out;

    cudaFuncSetAttribute(flash_kernel, cudaFuncAttributeMaxDynamicSharedMemorySize, FLASH_SMEM);
    cudaFuncSetAttribute(gemm_bf<0>, cudaFuncAttributeMaxDynamicSharedMemorySize, GEMM_SMEM);
    cudaFuncSetAttribute(gemm_bf<1>, cudaFuncAttributeMaxDynamicSharedMemorySize, GEMM_SMEM);

    convw_kernel<<<2048, 256>>>(qkv_w, proj_w);
    gn_kernel<<<NB * NG, 256>>>(x, gn_w, gn_b);
    gemm_bf<0><<<dim3(8, 12, NB), 256, GEMM_SMEM>>>(nullptr, nullptr, nullptr);
    flash_kernel<<<NB * NHEADS * 8, 256, FLASH_SMEM>>>();
    gemm_bf<1><<<dim3(8, 4, NB), 256, GEMM_SMEM>>>(proj_b, x, out);
}

// round 16
// speedup vs baseline: 11.3133x; 1.0546x over previous
#include <cuda_runtime.h>
#include <cuda_fp16.h>
#include <math.h>

#define NB 16
#define NC 512
#define NHW 1024
#define NHEADS 8
#define HD 64
#define NG 32
#define CPG 16

// ---- scratch ----
__device__ unsigned g_xbf[(size_t)NB * (NC / 2) * NHW];   // f16x2 [b][c/2][n] (k-packed)
__device__ float g_scale[NB * NC];
__device__ float g_shift[NB * NC];
__device__ __half g_qbf[(size_t)NB * NHEADS * NHW * HD];  // f16 Q (fperm2, pre-scaled log2e/8)
__device__ __half g_kbf[(size_t)NB * NHEADS * NHW * HD];  // f16 K (fperm2)
__device__ __half g_vbf[(size_t)NB * NHEADS * HD * NHW];  // f16 V (fperm2)
__device__ unsigned g_hbf[(size_t)NB * (NC / 2) * NHW];   // f16x2 packed h (k-packed)
__device__ unsigned g_wqkv[3 * NC * NC / 2];              // f16 qkv_w (a-frag interleaved)
__device__ unsigned g_wproj[NC * NC / 2];                 // f16 proj_w (a-frag interleaved)

// ---- helpers ----
__device__ __forceinline__ void mma_h16(__half2* c, const unsigned* a, const unsigned* b) {
    unsigned* cu = reinterpret_cast<unsigned*>(c);
    asm volatile(
        "mma.sync.aligned.m16n8k16.row.col.f16.f16.f16.f16 "
        "{%0,%1}, {%2,%3,%4,%5}, {%6,%7}, {%0,%1};"
        : "+r"(cu[0]), "+r"(cu[1])
        : "r"(a[0]), "r"(a[1]), "r"(a[2]), "r"(a[3]), "r"(b[0]), "r"(b[1]));
}
__device__ __forceinline__ void mma_hf32(float* c, const unsigned* a, const unsigned* b) {
    asm volatile(
        "mma.sync.aligned.m16n8k16.row.col.f32.f16.f16.f32 "
        "{%0,%1,%2,%3}, {%4,%5,%6,%7}, {%8,%9}, {%0,%1,%2,%3};"
        : "+f"(c[0]), "+f"(c[1]), "+f"(c[2]), "+f"(c[3])
        : "r"(a[0]), "r"(a[1]), "r"(a[2]), "r"(a[3]), "r"(b[0]), "r"(b[1]));
}
__device__ __forceinline__ unsigned packhf(float lo, float hi) {
    __half2 h = __floats2half2_rn(lo, hi);
    return *reinterpret_cast<unsigned*>(&h);
}
__device__ __forceinline__ unsigned h2u(__half2 h) { return *reinterpret_cast<unsigned*>(&h); }
__device__ __forceinline__ __half2 u2h(unsigned u) { return *reinterpret_cast<__half2*>(&u); }
__device__ __forceinline__ __half2 hex2(__half2 x) {
    unsigned r, xi = h2u(x);
    asm("ex2.approx.f16x2 %0, %1;" : "=r"(r) : "r"(xi));
    return u2h(r);
}
__device__ __forceinline__ float ex2f(float x) {
    float r;
    asm("ex2.approx.f32 %0, %1;" : "=f"(r) : "f"(x));
    return r;
}
__device__ __forceinline__ void cp16(unsigned dst, const void* src) {
    asm volatile("cp.async.cg.shared.global [%0], [%1], 16;" :: "r"(dst), "l"(src));
}

// a-frag interleaved weight address for word (m, kw), kw = k/2
__device__ __forceinline__ int wfaddr(int m, int kw) {
    int mbg = m >> 4, gid = m & 7, r8 = (m >> 3) & 1;
    int kchunk = kw >> 4, kin = kw & 15;
    int c2 = kin >> 3, kk = kin & 7;
    int tg = kk & 3, half = kk >> 2;
    return ((mbg * 16 + kchunk) << 8) + ((c2 * 8 + gid) * 4 + tg) * 4 + r8 + 2 * half;
}

// ============================================================
// Weight pre-pack: fp32 -> f16, a-fragment interleaved
// ============================================================
__global__ void __launch_bounds__(256) convw_kernel(const float* __restrict__ qkvw,
                                                    const float* __restrict__ projw)
{
    int i = blockIdx.x * 256 + threadIdx.x;
    const int NQ2 = 3 * NC * NC / 2;
    const int NP2 = NC * NC / 2;
    if (i < NQ2) {
        int m = i >> 8, kw = i & 255;
        float2 v = *reinterpret_cast<const float2*>(&qkvw[m * NC + 2 * kw]);
        g_wqkv[wfaddr(m, kw)] = packhf(v.x, v.y);
    } else if (i < NQ2 + NP2) {
        int j = i - NQ2;
        int m = j >> 8, kw = j & 255;
        float2 v = *reinterpret_cast<const float2*>(&projw[m * NC + 2 * kw]);
        g_wproj[wfaddr(m, kw)] = packhf(v.x, v.y);
    }
}

// ============================================================
// GroupNorm: f16x2 k-packed out + per-channel affine
// ============================================================
__global__ void __launch_bounds__(256) gn_kernel(const float* __restrict__ x,
                                                 const float* __restrict__ w,
                                                 const float* __restrict__ bias)
{
    int b = blockIdx.x >> 5;
    int g = blockIdx.x & 31;
    const float* xp = x + ((size_t)b * NC + g * CPG) * NHW;

    float s = 0.f, s2 = 0.f;
    for (int i = threadIdx.x; i < CPG * NHW / 4; i += 256) {
        float4 v = reinterpret_cast<const float4*>(xp)[i];
        s  += v.x + v.y + v.z + v.w;
        s2 += v.x * v.x + v.y * v.y + v.z * v.z + v.w * v.w;
    }
    __shared__ float r0[8], r1[8];
    #pragma unroll
    for (int o = 16; o; o >>= 1) {
        s  += __shfl_xor_sync(~0u, s,  o);
        s2 += __shfl_xor_sync(~0u, s2, o);
    }
    int wid = threadIdx.x >> 5, lid = threadIdx.x & 31;
    if (lid == 0) { r0[wid] = s; r1[wid] = s2; }
    __syncthreads();
    if (threadIdx.x < 32) {
        s  = (lid < 8) ? r0[lid] : 0.f;
        s2 = (lid < 8) ? r1[lid] : 0.f;
        #pragma unroll
        for (int o = 4; o; o >>= 1) {
            s  += __shfl_xor_sync(~0u, s,  o);
            s2 += __shfl_xor_sync(~0u, s2, o);
        }
        if (lid == 0) { r0[0] = s; r1[0] = s2; }
    }
    __syncthreads();
    const float inv_n = 1.f / (CPG * NHW);
    float mean = r0[0] * inv_n;
    float var  = r1[0] * inv_n - mean * mean;
    float rinv = rsqrtf(var + 1e-5f);

    if (threadIdx.x < CPG) {
        int c = g * CPG + threadIdx.x;
        float sc = w[c] * rinv;
        g_scale[b * NC + c] = sc;
        g_shift[b * NC + c] = bias[c] - mean * sc;
    }

    unsigned* xb = g_xbf + ((size_t)b * (NC / 2) + g * (CPG / 2)) * NHW;
    for (int i = threadIdx.x; i < (CPG / 2) * (NHW / 4); i += 256) {
        int ul = i >> 8, n4 = (i & 255) * 4;
        int c0 = g * CPG + 2 * ul;
        float w0 = w[c0] * rinv, w1 = w[c0 + 1] * rinv;
        float b0 = bias[c0] - mean * w0, b1 = bias[c0 + 1] - mean * w1;
        float4 xa = *reinterpret_cast<const float4*>(&xp[(2 * ul) * NHW + n4]);
        float4 xc = *reinterpret_cast<const float4*>(&xp[(2 * ul + 1) * NHW + n4]);
        uint4 pk = make_uint4(packhf(xa.x * w0 + b0, xc.x * w1 + b1),
                              packhf(xa.y * w0 + b0, xc.y * w1 + b1),
                              packhf(xa.z * w0 + b0, xc.z * w1 + b1),
                              packhf(xa.w * w0 + b0, xc.w * w1 + b1));
        *reinterpret_cast<uint4*>(&xb[ul * NHW + n4]) = pk;
    }
}

// ============================================================
// qkv GEMM: f16 mma with f16 ACCUM (2x rate), 3-stage cp.async,
// fused-permute epilogue into fperm2 Q/K/V layouts.
// ============================================================
#define GSTAGE 4224
#define GEMM_SMEM (3 * GSTAGE * 4)

__global__ void __launch_bounds__(256, 2) qkv_gemm()
{
    extern __shared__ unsigned gsm[];
    unsigned sbase = (unsigned)__cvta_generic_to_shared(gsm);

    int b  = blockIdx.z;
    int by = blockIdx.y, bx = blockIdx.x;
    int m0 = by << 7;
    int n0 = bx << 7;
    const unsigned* Bw = g_xbf + (size_t)b * (NC / 2) * NHW;

    int t = threadIdx.x;
    int w = t >> 5, lane = t & 31;
    int gid = lane >> 2, tig = lane & 3;
    int mw = (w >> 2) * 64;
    int nw = (w & 3) * 32;

    __half2 acc[4][4][2];
    #pragma unroll
    for (int i = 0; i < 4; i++)
        #pragma unroll
        for (int j = 0; j < 4; j++) {
            acc[i][j][0] = __float2half2_rn(0.f);
            acc[i][j][1] = __float2half2_rn(0.f);
        }

    auto load_stage = [&](int s, int kc) {
        unsigned abase = sbase + s * GSTAGE * 4;
        unsigned bbase = abase + 2048 * 4;
        #pragma unroll
        for (int h = 0; h < 2; h++) {
            int ca = t + h * 256;
            cp16(abase + ca * 16,
                 g_wqkv + ((size_t)((m0 >> 4) + (ca >> 6)) * 16 + kc) * 256 + (ca & 63) * 4);
            int kp = ca >> 5, nq = (ca & 31) * 4;
            cp16(bbase + (kp * 136 + nq) * 4,
                 Bw + (size_t)(kc * 16 + kp) * NHW + n0 + nq);
        }
    };

    load_stage(0, 0);
    asm volatile("cp.async.commit_group;");
    load_stage(1, 1);
    asm volatile("cp.async.commit_group;");

    const int NIT = (NC / 2) / 16;
    for (int it = 0; it < NIT; it++) {
        int s = it % 3;
        const unsigned* As = gsm + s * GSTAGE;
        const unsigned* Bs = As + 2048;

        asm volatile("cp.async.wait_group 1;");
        __syncthreads();
        if (it + 2 < NIT) load_stage((it + 2) % 3, it + 2);
        asm volatile("cp.async.commit_group;");

        #pragma unroll
        for (int c2 = 0; c2 < 2; c2++) {
            unsigned a[4][4], bb[4][2];
            #pragma unroll
            for (int mf = 0; mf < 4; mf++) {
                int mb = (w >> 2) * 4 + mf;
                uint4 a4 = *reinterpret_cast<const uint4*>(
                    &As[mb * 256 + ((c2 * 8 + gid) * 4 + tig) * 4]);
                a[mf][0] = a4.x; a[mf][1] = a4.y; a[mf][2] = a4.z; a[mf][3] = a4.w;
            }
            #pragma unroll
            for (int nf = 0; nf < 4; nf++) {
                int ni = nw + nf * 8 + gid;
                bb[nf][0] = Bs[(c2 * 8 + tig) * 136 + ni];
                bb[nf][1] = Bs[(c2 * 8 + tig + 4) * 136 + ni];
            }
            #pragma unroll
            for (int mf = 0; mf < 4; mf++)
                #pragma unroll
                for (int nf = 0; nf < 4; nf++)
                    mma_h16(acc[mf][nf], a[mf], bb[nf]);
        }
    }

    // ===== fused-permute epilogue =====
    asm volatile("cp.async.wait_group 0;");
    __syncthreads();

    int s  = by >> 2;      // 0:Q 1:K 2:V
    int tg = by & 3;       // h0 = 2*tg
    __half2 qsh = __float2half2_rn(s == 0 ? 0.125f * 1.4426950408889634f : 1.f);

    unsigned* esm = gsm;
    #pragma unroll
    for (int mf = 0; mf < 4; mf++) {
        int r0i = mw + mf * 16 + gid;
        #pragma unroll
        for (int nf = 0; nf < 4; nf++) {
            int col = (nw >> 1) + nf * 4 + tig;
            esm[r0i * 66 + col]       = h2u(__hmul2(acc[mf][nf][0], qsh));
            esm[(r0i + 8) * 66 + col] = h2u(__hmul2(acc[mf][nf][1], qsh));
        }
    }
    __syncthreads();

    if (s < 2) {
        unsigned* dstbase = reinterpret_cast<unsigned*>(s == 0 ? g_qbf : g_kbf);
        #pragma unroll
        for (int k = 0; k < 8; k++) {
            int i = t + k * 256;
            int r    = i >> 8;
            int d_lo = (i >> 5) & 7;
            int jj   = (i >> 1) & 15;
            int dsp  = i & 1;
            int mloc = r * 8 + d_lo;
            int colb = jj * 4 + 2 * dsp;
            uint2 A = *reinterpret_cast<const uint2*>(&esm[mloc * 66 + colb]);
            uint2 B = *reinterpret_cast<const uint2*>(&esm[(mloc + 64) * 66 + colb]);
            uint4 o;
            o.x = __byte_perm(A.x, B.x, 0x5410);
            o.y = __byte_perm(A.x, B.x, 0x7632);
            o.z = __byte_perm(A.y, B.y, 0x5410);
            o.w = __byte_perm(A.y, B.y, 0x7632);
            size_t n2 = (size_t)d_lo * 128 + bx * 16 + jj;
            size_t wadr = (((size_t)(b * 8 + r) * NHW) + n2) * 32 + dsp * 16 + tg * 4;
            *reinterpret_cast<uint4*>(&dstbase[wadr]) = o;
        }
    } else {
        unsigned* dstbase = reinterpret_cast<unsigned*>(g_vbf);
        int wposb = ((bx >> 1) & 1) * 16 + 2 * (bx & 1);
        #pragma unroll
        for (int k = 0; k < 16; k++) {
            int j = t + k * 256;
            int r    = j >> 9;
            int d2i  = (j >> 5) & 15;
            int c2   = d2i >> 1;
            int hh   = d2i & 1;
            int d_lo = (j >> 2) & 7;
            int tgv  = j & 3;
            int d2   = c2 * 8 + 2 * tg + hh;
            int mloc = hh * 64 + r * 8 + d_lo;
            unsigned sel = (c2 & 1) ? 0x7632 : 0x5410;
            int wA0 = 8 * tgv + (c2 >> 1);
            int wA1 = wA0 + 32;
            uint2 o;
            o.x = __byte_perm(esm[mloc * 66 + wA0], esm[mloc * 66 + wA0 + 4], sel);
            o.y = __byte_perm(esm[mloc * 66 + wA1], esm[mloc * 66 + wA1 + 4], sel);
            size_t wadr = ((size_t)(b * 8 + r) * HD + d2) * 512
                        + (size_t)(d_lo * 2 + (bx >> 2)) * 32
                        + wposb + tgv * 4;
            *reinterpret_cast<uint2*>(&dstbase[wadr]) = o;
        }
    }
}

// ============================================================
// proj GEMM: f16 inputs, f32 ACCUM (exact output path).
// ============================================================
__global__ void __launch_bounds__(256, 2) proj_gemm(const float* __restrict__ pbias,
                                                    const float* __restrict__ xin,
                                                    float* __restrict__ outp)
{
    extern __shared__ unsigned gsm[];
    unsigned sbase = (unsigned)__cvta_generic_to_shared(gsm);

    int b  = blockIdx.z;
    int m0 = blockIdx.y << 7;
    int n0 = blockIdx.x << 7;
    const unsigned* Bw = g_hbf + (size_t)b * (NC / 2) * NHW;

    int t = threadIdx.x;
    int w = t >> 5, lane = t & 31;
    int gid = lane >> 2, tig = lane & 3;
    int mw = (w >> 2) * 64;
    int nw = (w & 3) * 32;

    float acc[4][4][4];
    #pragma unroll
    for (int i = 0; i < 4; i++)
        #pragma unroll
        for (int j = 0; j < 4; j++)
            #pragma unroll
            for (int c = 0; c < 4; c++) acc[i][j][c] = 0.f;

    auto load_stage = [&](int s, int kc) {
        unsigned abase = sbase + s * GSTAGE * 4;
        unsigned bbase = abase + 2048 * 4;
        #pragma unroll
        for (int h = 0; h < 2; h++) {
            int ca = t + h * 256;
            cp16(abase + ca * 16,
                 g_wproj + ((size_t)((m0 >> 4) + (ca >> 6)) * 16 + kc) * 256 + (ca & 63) * 4);
            int kp = ca >> 5, nq = (ca & 31) * 4;
            cp16(bbase + (kp * 136 + nq) * 4,
                 Bw + (size_t)(kc * 16 + kp) * NHW + n0 + nq);
        }
    };

    load_stage(0, 0);
    asm volatile("cp.async.commit_group;");
    load_stage(1, 1);
    asm volatile("cp.async.commit_group;");

    const int NIT = (NC / 2) / 16;
    for (int it = 0; it < NIT; it++) {
        int s = it % 3;
        const unsigned* As = gsm + s * GSTAGE;
        const unsigned* Bs = As + 2048;

        asm volatile("cp.async.wait_group 1;");
        __syncthreads();
        if (it + 2 < NIT) load_stage((it + 2) % 3, it + 2);
        asm volatile("cp.async.commit_group;");

        #pragma unroll
        for (int c2 = 0; c2 < 2; c2++) {
            unsigned a[4][4], bb[4][2];
            #pragma unroll
            for (int mf = 0; mf < 4; mf++) {
                int mb = (w >> 2) * 4 + mf;
                uint4 a4 = *reinterpret_cast<const uint4*>(
                    &As[mb * 256 + ((c2 * 8 + gid) * 4 + tig) * 4]);
                a[mf][0] = a4.x; a[mf][1] = a4.y; a[mf][2] = a4.z; a[mf][3] = a4.w;
            }
            #pragma unroll
            for (int nf = 0; nf < 4; nf++) {
                int ni = nw + nf * 8 + gid;
                bb[nf][0] = Bs[(c2 * 8 + tig) * 136 + ni];
                bb[nf][1] = Bs[(c2 * 8 + tig + 4) * 136 + ni];
            }
            #pragma unroll
            for (int mf = 0; mf < 4; mf++)
                #pragma unroll
                for (int nf = 0; nf < 4; nf++)
                    mma_hf32(acc[mf][nf], a[mf], bb[nf]);
        }
    }

    #pragma unroll
    for (int mf = 0; mf < 4; mf++) {
        int gm = m0 + mw + mf * 16 + gid;
        float sc0 = g_scale[b * NC + gm],     sh0 = g_shift[b * NC + gm];
        float sc1 = g_scale[b * NC + gm + 8], sh1 = g_shift[b * NC + gm + 8];
        float pb0 = pbias[gm], pb1 = pbias[gm + 8];
        #pragma unroll
        for (int nf = 0; nf < 4; nf++) {
            int gn = n0 + nw + nf * 8 + 2 * tig;
            const float* x0 = &xin[((size_t)b * NC + gm) * NHW + gn];
            const float* x1 = &xin[((size_t)b * NC + gm + 8) * NHW + gn];
            float2 v01 = make_float2(acc[mf][nf][0] + pb0 + x0[0] * sc0 + sh0,
                                     acc[mf][nf][1] + pb0 + x0[1] * sc0 + sh0);
            float2 v23 = make_float2(acc[mf][nf][2] + pb1 + x1[0] * sc1 + sh1,
                                     acc[mf][nf][3] + pb1 + x1[1] * sc1 + sh1);
            *reinterpret_cast<float2*>(&outp[((size_t)b * NC + gm) * NHW + gn]) = v01;
            *reinterpret_cast<float2*>(&outp[((size_t)b * NC + gm + 8) * NHW + gn]) = v23;
        }
    }
}

// ============================================================
// Flash attention v11 — full fp16: f16-acc mma (2x), packed-half2
// softmax, P frags reused directly (zero pack).
// ============================================================
#define KVSTRIDE 48
#define STG_WORDS (2 * 64 * KVSTRIDE)
#define FLASH_SMEM (3 * STG_WORDS * 4)

__global__ void __launch_bounds__(256, 2) flash_kernel()
{
    extern __shared__ unsigned dynsm[];

    int bh    = blockIdx.x >> 3;
    int qtile = blockIdx.x & 7;
    int b = bh >> 3, r = bh & 7;

    const unsigned* Qp = reinterpret_cast<const unsigned*>(g_qbf + (size_t)bh * NHW * HD);
    const __half* Kp = g_kbf + (size_t)bh * NHW * HD;
    const __half* Vp = g_vbf + (size_t)bh * HD * NHW;

    int t = threadIdx.x;
    int w = t >> 5, lane = t & 31;
    int gid = lane >> 2, tig = lane & 3;
    int i0w = w * 16;
    int ibase = qtile * 128 + i0w + gid;

    unsigned qa[4][4];
    {
        const unsigned* qr0 = Qp + (size_t)ibase * 32;
        const unsigned* qr8 = qr0 + 8 * 32;
        #pragma unroll
        for (int ds = 0; ds < 4; ds++) {
            int off = (ds >> 1) * 16 + tig * 4 + (ds & 1) * 2;
            uint2 u0 = *reinterpret_cast<const uint2*>(qr0 + off);
            uint2 u8 = *reinterpret_cast<const uint2*>(qr8 + off);
            qa[ds][0] = u0.x;
            qa[ds][1] = u8.x;
            qa[ds][2] = u0.y;
            qa[ds][3] = u8.y;
        }
    }

    __half2 acc_o[8][2];
    #pragma unroll
    for (int i = 0; i < 8; i++) {
        acc_o[i][0] = __float2half2_rn(0.f);
        acc_o[i][1] = __float2half2_rn(0.f);
    }
    float row_m0 = -1e30f, row_m1 = -1e30f;
    float row_l0 = 0.f, row_l1 = 0.f;

    auto load_tiles = [&](int st, int kt) {
        unsigned kb = (unsigned)__cvta_generic_to_shared(dynsm + st * STG_WORDS);
        unsigned vb = kb + 64 * KVSTRIDE * 4;
        int j0 = kt * 64;
        #pragma unroll
        for (int h = 0; h < 2; h++) {
            int ca = t + h * 256;
            int row = ca >> 3, ch = ca & 7;
            cp16(kb + (row * KVSTRIDE + ch * 4) * 4, Kp + (size_t)(j0 + row) * HD + ch * 8);
            cp16(vb + (row * KVSTRIDE + ch * 4) * 4, Vp + (size_t)row * NHW + j0 + ch * 8);
        }
    };

    load_tiles(0, 0);
    asm volatile("cp.async.commit_group;");
    load_tiles(1, 1);
    asm volatile("cp.async.commit_group;");

    for (int kt = 0; kt < 16; kt++) {
        int st = kt % 3;
        const unsigned* kbuf = dynsm + st * STG_WORDS;
        const unsigned* vbuf = kbuf + 64 * KVSTRIDE;

        asm volatile("cp.async.wait_group 1;");
        __syncthreads();
        if (kt + 2 < 16) load_tiles((kt + 2) % 3, kt + 2);
        asm volatile("cp.async.commit_group;");

        // ---- S = Q K^T (f16 acc) ----
        __half2 p[8][2];
        #pragma unroll
        for (int i = 0; i < 8; i++) {
            p[i][0] = __float2half2_rn(0.f);
            p[i][1] = __float2half2_rn(0.f);
        }

        #pragma unroll
        for (int dsp = 0; dsp < 2; dsp++) {
            #pragma unroll
            for (int nf = 0; nf < 8; nf++) {
                uint4 k4 = *reinterpret_cast<const uint4*>(
                    &kbuf[(nf * 8 + gid) * KVSTRIDE + dsp * 16 + tig * 4]);
                unsigned b0[2] = {k4.x, k4.y};
                mma_h16(p[nf], qa[2 * dsp], b0);
                unsigned b1[2] = {k4.z, k4.w};
                mma_h16(p[nf], qa[2 * dsp + 1], b1);
            }
        }

        // ---- packed-half2 online softmax (base 2) ----
        __half2 m0h = p[0][0], m1h = p[0][1];
        #pragma unroll
        for (int nf = 1; nf < 8; nf++) {
            m0h = __hmax2(m0h, p[nf][0]);
            m1h = __hmax2(m1h, p[nf][1]);
        }
        m0h = __hmax2(m0h, u2h(__shfl_xor_sync(~0u, h2u(m0h), 1)));
        m0h = __hmax2(m0h, u2h(__shfl_xor_sync(~0u, h2u(m0h), 2)));
        m1h = __hmax2(m1h, u2h(__shfl_xor_sync(~0u, h2u(m1h), 1)));
        m1h = __hmax2(m1h, u2h(__shfl_xor_sync(~0u, h2u(m1h), 2)));
        float tmax0 = fmaxf(__low2float(m0h), __high2float(m0h));
        float tmax1 = fmaxf(__low2float(m1h), __high2float(m1h));

        float nm0 = fmaxf(row_m0, tmax0);
        float nm1 = fmaxf(row_m1, tmax1);
        float corr0 = ex2f(row_m0 - nm0);
        float corr1 = ex2f(row_m1 - nm1);

        __half2 nmh0 = __float2half2_rn(nm0);
        __half2 nmh1 = __float2half2_rn(nm1);
        __half2 s0h = __float2half2_rn(0.f), s1h = __float2half2_rn(0.f);
        #pragma unroll
        for (int nf = 0; nf < 8; nf++) {
            p[nf][0] = hex2(__hsub2(p[nf][0], nmh0));
            p[nf][1] = hex2(__hsub2(p[nf][1], nmh1));
            s0h = __hadd2(s0h, p[nf][0]);
            s1h = __hadd2(s1h, p[nf][1]);
        }
        s0h = __hadd2(s0h, u2h(__shfl_xor_sync(~0u, h2u(s0h), 1)));
        s0h = __hadd2(s0h, u2h(__shfl_xor_sync(~0u, h2u(s0h), 2)));
        s1h = __hadd2(s1h, u2h(__shfl_xor_sync(~0u, h2u(s1h), 1)));
        s1h = __hadd2(s1h, u2h(__shfl_xor_sync(~0u, h2u(s1h), 2)));
        float sum0 = __low2float(s0h) + __high2float(s0h);
        float sum1 = __low2float(s1h) + __high2float(s1h);

        row_l0 = row_l0 * corr0 + sum0;
        row_l1 = row_l1 * corr1 + sum1;
        row_m0 = nm0; row_m1 = nm1;

        __half2 c0h = __float2half2_rn(corr0);
        __half2 c1h = __float2half2_rn(corr1);
        #pragma unroll
        for (int nf2 = 0; nf2 < 8; nf2++) {
            acc_o[nf2][0] = __hmul2(acc_o[nf2][0], c0h);
            acc_o[nf2][1] = __hmul2(acc_o[nf2][1], c1h);
        }

        // ---- O += P V^T : P c-frags ARE the f16 a-frags ----
        #pragma unroll
        for (int jsp = 0; jsp < 2; jsp++) {
            const unsigned* pa0 = reinterpret_cast<const unsigned*>(&p[4 * jsp][0]);
            const unsigned* pa1 = reinterpret_cast<const unsigned*>(&p[4 * jsp + 2][0]);
            #pragma unroll
            for (int nf2 = 0; nf2 < 8; nf2++) {
                uint4 v4 = *reinterpret_cast<const uint4*>(
                    &vbuf[(nf2 * 8 + gid) * KVSTRIDE + jsp * 16 + tig * 4]);
                unsigned b0[2] = {v4.x, v4.y};
                mma_h16(acc_o[nf2], pa0, b0);
                unsigned b1[2] = {v4.z, v4.w};
                mma_h16(acc_o[nf2], pa1, b1);
            }
        }
    }

    // ---- epilogue: O /= l, write f16x2 into g_hbf ----
    __half2 i0h = __float2half2_rn(1.f / row_l0);
    __half2 i1h = __float2half2_rn(1.f / row_l1);
    unsigned* Hb = g_hbf + ((size_t)b * (NC / 2) + r * (HD / 2)) * NHW;
    #pragma unroll
    for (int nf2 = 0; nf2 < 8; nf2++) {
        int u = nf2 * 4 + tig;
        Hb[(size_t)u * NHW + ibase]     = h2u(__hmul2(acc_o[nf2][0], i0h));
        Hb[(size_t)u * NHW + ibase + 8] = h2u(__hmul2(acc_o[nf2][1], i1h));
    }
}

// ============================================================
extern "C" void kernel_launch(void* const* d_in, const int* in_sizes, int n_in,
                              void* d_out, int out_size)
{
    const float* x      = (const float*)d_in[0];
    const float* gn_w   = (const float*)d_in[1];
    const float* gn_b   = (const float*)d_in[2];
    const float* qkv_w  = (const float*)d_in[3];
    const float* proj_w = (const float*)d_in[4];
    const float* proj_b = (const float*)d_in[5];
    float* out = (float*)d_out;

    cudaFuncSetAttribute(flash_kernel, cudaFuncAttributeMaxDynamicSharedMemorySize, FLASH_SMEM);
    cudaFuncSetAttribute(qkv_gemm, cudaFuncAttributeMaxDynamicSharedMemorySize, GEMM_SMEM);
    cudaFuncSetAttribute(proj_gemm, cudaFuncAttributeMaxDynamicSharedMemorySize, GEMM_SMEM);

    convw_kernel<<<2048, 256>>>(qkv_w, proj_w);
    gn_kernel<<<NB * NG, 256>>>(x, gn_w, gn_b);
    qkv_gemm<<<dim3(8, 12, NB), 256, GEMM_SMEM>>>();
    flash_kernel<<<NB * NHEADS * 8, 256, FLASH_SMEM>>>();
    proj_gemm<<<dim3(8, 4, NB), 256, GEMM_SMEM>>>(proj_b, x, out);
}

// round 17
// speedup vs baseline: 11.6797x; 1.0324x over previous
#include <cuda_runtime.h>
#include <cuda_fp16.h>
#include <math.h>

#define NB 16
#define NC 512
#define NHW 1024
#define NHEADS 8
#define HD 64
#define NG 32
#define CPG 16

// ---- scratch ----
__device__ unsigned g_xbf[(size_t)NB * (NC / 2) * NHW];   // f16x2 [b][c/2][n] (k-packed)
__device__ float g_scale[NB * NC];
__device__ float g_shift[NB * NC];
__device__ __half g_qbf[(size_t)NB * NHEADS * NHW * HD];  // f16 Q (fperm2, pre-scaled log2e/8)
__device__ __half g_kbf[(size_t)NB * NHEADS * NHW * HD];  // f16 K (fperm2)
__device__ __half g_vbf[(size_t)NB * NHEADS * HD * NHW];  // f16 V (fperm2)
__device__ unsigned g_hbf[(size_t)NB * (NC / 2) * NHW];   // f16x2 packed h (k-packed)
__device__ unsigned g_wqkv[3 * NC * NC / 2];              // f16 qkv_w (a-frag interleaved)
__device__ unsigned g_wproj[NC * NC / 2];                 // f16 proj_w (a-frag interleaved)

// ---- helpers ----
__device__ __forceinline__ void mma_h16(__half2* c, const unsigned* a, const unsigned* b) {
    unsigned* cu = reinterpret_cast<unsigned*>(c);
    asm volatile(
        "mma.sync.aligned.m16n8k16.row.col.f16.f16.f16.f16 "
        "{%0,%1}, {%2,%3,%4,%5}, {%6,%7}, {%0,%1};"
        : "+r"(cu[0]), "+r"(cu[1])
        : "r"(a[0]), "r"(a[1]), "r"(a[2]), "r"(a[3]), "r"(b[0]), "r"(b[1]));
}
__device__ __forceinline__ void mma_hf32(float* c, const unsigned* a, const unsigned* b) {
    asm volatile(
        "mma.sync.aligned.m16n8k16.row.col.f32.f16.f16.f32 "
        "{%0,%1,%2,%3}, {%4,%5,%6,%7}, {%8,%9}, {%0,%1,%2,%3};"
        : "+f"(c[0]), "+f"(c[1]), "+f"(c[2]), "+f"(c[3])
        : "r"(a[0]), "r"(a[1]), "r"(a[2]), "r"(a[3]), "r"(b[0]), "r"(b[1]));
}
__device__ __forceinline__ unsigned packhf(float lo, float hi) {
    __half2 h = __floats2half2_rn(lo, hi);
    return *reinterpret_cast<unsigned*>(&h);
}
__device__ __forceinline__ unsigned h2u(__half2 h) { return *reinterpret_cast<unsigned*>(&h); }
__device__ __forceinline__ __half2 u2h(unsigned u) { return *reinterpret_cast<__half2*>(&u); }
__device__ __forceinline__ __half2 hex2(__half2 x) {
    unsigned r, xi = h2u(x);
    asm("ex2.approx.f16x2 %0, %1;" : "=r"(r) : "r"(xi));
    return u2h(r);
}
__device__ __forceinline__ float ex2f(float x) {
    float r;
    asm("ex2.approx.f32 %0, %1;" : "=f"(r) : "f"(x));
    return r;
}
__device__ __forceinline__ void cp16(unsigned dst, const void* src) {
    asm volatile("cp.async.cg.shared.global [%0], [%1], 16;" :: "r"(dst), "l"(src));
}

// a-frag interleaved weight address for word (m, kw), kw = k/2
__device__ __forceinline__ int wfaddr(int m, int kw) {
    int mbg = m >> 4, gid = m & 7, r8 = (m >> 3) & 1;
    int kchunk = kw >> 4, kin = kw & 15;
    int c2 = kin >> 3, kk = kin & 7;
    int tg = kk & 3, half = kk >> 2;
    return ((mbg * 16 + kchunk) << 8) + ((c2 * 8 + gid) * 4 + tg) * 4 + r8 + 2 * half;
}

// ============================================================
// Weight pre-pack: fp32 -> f16, a-fragment interleaved
// ============================================================
__global__ void __launch_bounds__(256) convw_kernel(const float* __restrict__ qkvw,
                                                    const float* __restrict__ projw)
{
    int i = blockIdx.x * 256 + threadIdx.x;
    const int NQ2 = 3 * NC * NC / 2;
    const int NP2 = NC * NC / 2;
    if (i < NQ2) {
        int m = i >> 8, kw = i & 255;
        float2 v = *reinterpret_cast<const float2*>(&qkvw[m * NC + 2 * kw]);
        g_wqkv[wfaddr(m, kw)] = packhf(v.x, v.y);
    } else if (i < NQ2 + NP2) {
        int j = i - NQ2;
        int m = j >> 8, kw = j & 255;
        float2 v = *reinterpret_cast<const float2*>(&projw[m * NC + 2 * kw]);
        g_wproj[wfaddr(m, kw)] = packhf(v.x, v.y);
    }
}

// ============================================================
// GroupNorm: f16x2 k-packed out + per-channel affine
// ============================================================
__global__ void __launch_bounds__(256) gn_kernel(const float* __restrict__ x,
                                                 const float* __restrict__ w,
                                                 const float* __restrict__ bias)
{
    int b = blockIdx.x >> 5;
    int g = blockIdx.x & 31;
    const float* xp = x + ((size_t)b * NC + g * CPG) * NHW;

    float s = 0.f, s2 = 0.f;
    for (int i = threadIdx.x; i < CPG * NHW / 4; i += 256) {
        float4 v = reinterpret_cast<const float4*>(xp)[i];
        s  += v.x + v.y + v.z + v.w;
        s2 += v.x * v.x + v.y * v.y + v.z * v.z + v.w * v.w;
    }
    __shared__ float r0[8], r1[8];
    #pragma unroll
    for (int o = 16; o; o >>= 1) {
        s  += __shfl_xor_sync(~0u, s,  o);
        s2 += __shfl_xor_sync(~0u, s2, o);
    }
    int wid = threadIdx.x >> 5, lid = threadIdx.x & 31;
    if (lid == 0) { r0[wid] = s; r1[wid] = s2; }
    __syncthreads();
    if (threadIdx.x < 32) {
        s  = (lid < 8) ? r0[lid] : 0.f;
        s2 = (lid < 8) ? r1[lid] : 0.f;
        #pragma unroll
        for (int o = 4; o; o >>= 1) {
            s  += __shfl_xor_sync(~0u, s,  o);
            s2 += __shfl_xor_sync(~0u, s2, o);
        }
        if (lid == 0) { r0[0] = s; r1[0] = s2; }
    }
    __syncthreads();
    const float inv_n = 1.f / (CPG * NHW);
    float mean = r0[0] * inv_n;
    float var  = r1[0] * inv_n - mean * mean;
    float rinv = rsqrtf(var + 1e-5f);

    if (threadIdx.x < CPG) {
        int c = g * CPG + threadIdx.x;
        float sc = w[c] * rinv;
        g_scale[b * NC + c] = sc;
        g_shift[b * NC + c] = bias[c] - mean * sc;
    }

    unsigned* xb = g_xbf + ((size_t)b * (NC / 2) + g * (CPG / 2)) * NHW;
    for (int i = threadIdx.x; i < (CPG / 2) * (NHW / 4); i += 256) {
        int ul = i >> 8, n4 = (i & 255) * 4;
        int c0 = g * CPG + 2 * ul;
        float w0 = w[c0] * rinv, w1 = w[c0 + 1] * rinv;
        float b0 = bias[c0] - mean * w0, b1 = bias[c0 + 1] - mean * w1;
        float4 xa = *reinterpret_cast<const float4*>(&xp[(2 * ul) * NHW + n4]);
        float4 xc = *reinterpret_cast<const float4*>(&xp[(2 * ul + 1) * NHW + n4]);
        uint4 pk = make_uint4(packhf(xa.x * w0 + b0, xc.x * w1 + b1),
                              packhf(xa.y * w0 + b0, xc.y * w1 + b1),
                              packhf(xa.z * w0 + b0, xc.z * w1 + b1),
                              packhf(xa.w * w0 + b0, xc.w * w1 + b1));
        *reinterpret_cast<uint4*>(&xb[ul * NHW + n4]) = pk;
    }
}

// ============================================================
// qkv GEMM: f16 mma f16-acc, 3-stage cp.async, fused-permute epilogue
// ============================================================
#define GSTAGE 4224
#define GEMM_SMEM (3 * GSTAGE * 4)

__global__ void __launch_bounds__(256, 2) qkv_gemm()
{
    extern __shared__ unsigned gsm[];
    unsigned sbase = (unsigned)__cvta_generic_to_shared(gsm);

    int b  = blockIdx.z;
    int by = blockIdx.y, bx = blockIdx.x;
    int m0 = by << 7;
    int n0 = bx << 7;
    const unsigned* Bw = g_xbf + (size_t)b * (NC / 2) * NHW;

    int t = threadIdx.x;
    int w = t >> 5, lane = t & 31;
    int gid = lane >> 2, tig = lane & 3;
    int mw = (w >> 2) * 64;
    int nw = (w & 3) * 32;

    __half2 acc[4][4][2];
    #pragma unroll
    for (int i = 0; i < 4; i++)
        #pragma unroll
        for (int j = 0; j < 4; j++) {
            acc[i][j][0] = __float2half2_rn(0.f);
            acc[i][j][1] = __float2half2_rn(0.f);
        }

    auto load_stage = [&](int s, int kc) {
        unsigned abase = sbase + s * GSTAGE * 4;
        unsigned bbase = abase + 2048 * 4;
        #pragma unroll
        for (int h = 0; h < 2; h++) {
            int ca = t + h * 256;
            cp16(abase + ca * 16,
                 g_wqkv + ((size_t)((m0 >> 4) + (ca >> 6)) * 16 + kc) * 256 + (ca & 63) * 4);
            int kp = ca >> 5, nq = (ca & 31) * 4;
            cp16(bbase + (kp * 136 + nq) * 4,
                 Bw + (size_t)(kc * 16 + kp) * NHW + n0 + nq);
        }
    };

    load_stage(0, 0);
    asm volatile("cp.async.commit_group;");
    load_stage(1, 1);
    asm volatile("cp.async.commit_group;");

    const int NIT = (NC / 2) / 16;
    for (int it = 0; it < NIT; it++) {
        int s = it % 3;
        const unsigned* As = gsm + s * GSTAGE;
        const unsigned* Bs = As + 2048;

        asm volatile("cp.async.wait_group 1;");
        __syncthreads();
        if (it + 2 < NIT) load_stage((it + 2) % 3, it + 2);
        asm volatile("cp.async.commit_group;");

        #pragma unroll
        for (int c2 = 0; c2 < 2; c2++) {
            unsigned a[4][4], bb[4][2];
            #pragma unroll
            for (int mf = 0; mf < 4; mf++) {
                int mb = (w >> 2) * 4 + mf;
                uint4 a4 = *reinterpret_cast<const uint4*>(
                    &As[mb * 256 + ((c2 * 8 + gid) * 4 + tig) * 4]);
                a[mf][0] = a4.x; a[mf][1] = a4.y; a[mf][2] = a4.z; a[mf][3] = a4.w;
            }
            #pragma unroll
            for (int nf = 0; nf < 4; nf++) {
                int ni = nw + nf * 8 + gid;
                bb[nf][0] = Bs[(c2 * 8 + tig) * 136 + ni];
                bb[nf][1] = Bs[(c2 * 8 + tig + 4) * 136 + ni];
            }
            #pragma unroll
            for (int mf = 0; mf < 4; mf++)
                #pragma unroll
                for (int nf = 0; nf < 4; nf++)
                    mma_h16(acc[mf][nf], a[mf], bb[nf]);
        }
    }

    // ===== fused-permute epilogue =====
    asm volatile("cp.async.wait_group 0;");
    __syncthreads();

    int s  = by >> 2;      // 0:Q 1:K 2:V
    int tg = by & 3;       // h0 = 2*tg
    __half2 qsh = __float2half2_rn(s == 0 ? 0.125f * 1.4426950408889634f : 1.f);

    unsigned* esm = gsm;
    #pragma unroll
    for (int mf = 0; mf < 4; mf++) {
        int r0i = mw + mf * 16 + gid;
        #pragma unroll
        for (int nf = 0; nf < 4; nf++) {
            int col = (nw >> 1) + nf * 4 + tig;
            esm[r0i * 66 + col]       = h2u(__hmul2(acc[mf][nf][0], qsh));
            esm[(r0i + 8) * 66 + col] = h2u(__hmul2(acc[mf][nf][1], qsh));
        }
    }
    __syncthreads();

    if (s < 2) {
        unsigned* dstbase = reinterpret_cast<unsigned*>(s == 0 ? g_qbf : g_kbf);
        #pragma unroll
        for (int k = 0; k < 8; k++) {
            int i = t + k * 256;
            int r    = i >> 8;
            int d_lo = (i >> 5) & 7;
            int jj   = (i >> 1) & 15;
            int dsp  = i & 1;
            int mloc = r * 8 + d_lo;
            int colb = jj * 4 + 2 * dsp;
            uint2 A = *reinterpret_cast<const uint2*>(&esm[mloc * 66 + colb]);
            uint2 B = *reinterpret_cast<const uint2*>(&esm[(mloc + 64) * 66 + colb]);
            uint4 o;
            o.x = __byte_perm(A.x, B.x, 0x5410);
            o.y = __byte_perm(A.x, B.x, 0x7632);
            o.z = __byte_perm(A.y, B.y, 0x5410);
            o.w = __byte_perm(A.y, B.y, 0x7632);
            size_t n2 = (size_t)d_lo * 128 + bx * 16 + jj;
            size_t wadr = (((size_t)(b * 8 + r) * NHW) + n2) * 32 + dsp * 16 + tg * 4;
            *reinterpret_cast<uint4*>(&dstbase[wadr]) = o;
        }
    } else {
        unsigned* dstbase = reinterpret_cast<unsigned*>(g_vbf);
        int wposb = ((bx >> 1) & 1) * 16 + 2 * (bx & 1);
        #pragma unroll
        for (int k = 0; k < 16; k++) {
            int j = t + k * 256;
            int r    = j >> 9;
            int d2i  = (j >> 5) & 15;
            int c2   = d2i >> 1;
            int hh   = d2i & 1;
            int d_lo = (j >> 2) & 7;
            int tgv  = j & 3;
            int d2   = c2 * 8 + 2 * tg + hh;
            int mloc = hh * 64 + r * 8 + d_lo;
            unsigned sel = (c2 & 1) ? 0x7632 : 0x5410;
            int wA0 = 8 * tgv + (c2 >> 1);
            int wA1 = wA0 + 32;
            uint2 o;
            o.x = __byte_perm(esm[mloc * 66 + wA0], esm[mloc * 66 + wA0 + 4], sel);
            o.y = __byte_perm(esm[mloc * 66 + wA1], esm[mloc * 66 + wA1 + 4], sel);
            size_t wadr = ((size_t)(b * 8 + r) * HD + d2) * 512
                        + (size_t)(d_lo * 2 + (bx >> 2)) * 32
                        + wposb + tgv * 4;
            *reinterpret_cast<uint2*>(&dstbase[wadr]) = o;
        }
    }
}

// ============================================================
// proj GEMM: f16 inputs, f32 ACCUM (exact output path).
// ============================================================
__global__ void __launch_bounds__(256, 2) proj_gemm(const float* __restrict__ pbias,
                                                    const float* __restrict__ xin,
                                                    float* __restrict__ outp)
{
    extern __shared__ unsigned gsm[];
    unsigned sbase = (unsigned)__cvta_generic_to_shared(gsm);

    int b  = blockIdx.z;
    int m0 = blockIdx.y << 7;
    int n0 = blockIdx.x << 7;
    const unsigned* Bw = g_hbf + (size_t)b * (NC / 2) * NHW;

    int t = threadIdx.x;
    int w = t >> 5, lane = t & 31;
    int gid = lane >> 2, tig = lane & 3;
    int mw = (w >> 2) * 64;
    int nw = (w & 3) * 32;

    float acc[4][4][4];
    #pragma unroll
    for (int i = 0; i < 4; i++)
        #pragma unroll
        for (int j = 0; j < 4; j++)
            #pragma unroll
            for (int c = 0; c < 4; c++) acc[i][j][c] = 0.f;

    auto load_stage = [&](int s, int kc) {
        unsigned abase = sbase + s * GSTAGE * 4;
        unsigned bbase = abase + 2048 * 4;
        #pragma unroll
        for (int h = 0; h < 2; h++) {
            int ca = t + h * 256;
            cp16(abase + ca * 16,
                 g_wproj + ((size_t)((m0 >> 4) + (ca >> 6)) * 16 + kc) * 256 + (ca & 63) * 4);
            int kp = ca >> 5, nq = (ca & 31) * 4;
            cp16(bbase + (kp * 136 + nq) * 4,
                 Bw + (size_t)(kc * 16 + kp) * NHW + n0 + nq);
        }
    };

    load_stage(0, 0);
    asm volatile("cp.async.commit_group;");
    load_stage(1, 1);
    asm volatile("cp.async.commit_group;");

    const int NIT = (NC / 2) / 16;
    for (int it = 0; it < NIT; it++) {
        int s = it % 3;
        const unsigned* As = gsm + s * GSTAGE;
        const unsigned* Bs = As + 2048;

        asm volatile("cp.async.wait_group 1;");
        __syncthreads();
        if (it + 2 < NIT) load_stage((it + 2) % 3, it + 2);
        asm volatile("cp.async.commit_group;");

        #pragma unroll
        for (int c2 = 0; c2 < 2; c2++) {
            unsigned a[4][4], bb[4][2];
            #pragma unroll
            for (int mf = 0; mf < 4; mf++) {
                int mb = (w >> 2) * 4 + mf;
                uint4 a4 = *reinterpret_cast<const uint4*>(
                    &As[mb * 256 + ((c2 * 8 + gid) * 4 + tig) * 4]);
                a[mf][0] = a4.x; a[mf][1] = a4.y; a[mf][2] = a4.z; a[mf][3] = a4.w;
            }
            #pragma unroll
            for (int nf = 0; nf < 4; nf++) {
                int ni = nw + nf * 8 + gid;
                bb[nf][0] = Bs[(c2 * 8 + tig) * 136 + ni];
                bb[nf][1] = Bs[(c2 * 8 + tig + 4) * 136 + ni];
            }
            #pragma unroll
            for (int mf = 0; mf < 4; mf++)
                #pragma unroll
                for (int nf = 0; nf < 4; nf++)
                    mma_hf32(acc[mf][nf], a[mf], bb[nf]);
        }
    }

    #pragma unroll
    for (int mf = 0; mf < 4; mf++) {
        int gm = m0 + mw + mf * 16 + gid;
        float sc0 = g_scale[b * NC + gm],     sh0 = g_shift[b * NC + gm];
        float sc1 = g_scale[b * NC + gm + 8], sh1 = g_shift[b * NC + gm + 8];
        float pb0 = pbias[gm], pb1 = pbias[gm + 8];
        #pragma unroll
        for (int nf = 0; nf < 4; nf++) {
            int gn = n0 + nw + nf * 8 + 2 * tig;
            const float* x0 = &xin[((size_t)b * NC + gm) * NHW + gn];
            const float* x1 = &xin[((size_t)b * NC + gm + 8) * NHW + gn];
            float2 v01 = make_float2(acc[mf][nf][0] + pb0 + x0[0] * sc0 + sh0,
                                     acc[mf][nf][1] + pb0 + x0[1] * sc0 + sh0);
            float2 v23 = make_float2(acc[mf][nf][2] + pb1 + x1[0] * sc1 + sh1,
                                     acc[mf][nf][3] + pb1 + x1[1] * sc1 + sh1);
            *reinterpret_cast<float2*>(&outp[((size_t)b * NC + gm) * NHW + gn]) = v01;
            *reinterpret_cast<float2*>(&outp[((size_t)b * NC + gm + 8) * NHW + gn]) = v23;
        }
    }
}

// ============================================================
// Flash attention v12 — 128 threads, 32 q-rows/warp (2 row groups
// share every K/V b-fragment: LDS halved), 3 CTAs/SM.
// ============================================================
#define KVSTRIDE 48
#define STG_WORDS (2 * 64 * KVSTRIDE)
#define FLASH_SMEM (3 * STG_WORDS * 4)

__global__ void __launch_bounds__(128, 3) flash_kernel()
{
    extern __shared__ unsigned dynsm[];

    int bh    = blockIdx.x >> 3;
    int qtile = blockIdx.x & 7;
    int b = bh >> 3, r = bh & 7;

    const unsigned* Qp = reinterpret_cast<const unsigned*>(g_qbf + (size_t)bh * NHW * HD);
    const __half* Kp = g_kbf + (size_t)bh * NHW * HD;
    const __half* Vp = g_vbf + (size_t)bh * HD * NHW;

    int t = threadIdx.x;
    int w = t >> 5, lane = t & 31;
    int gid = lane >> 2, tig = lane & 3;
    int i0w = w * 32;

    // Q a-frags for 2 row groups
    unsigned qa[2][4][4];
    #pragma unroll
    for (int rg = 0; rg < 2; rg++) {
        int ib = qtile * 128 + i0w + rg * 16 + gid;
        const unsigned* qr0 = Qp + (size_t)ib * 32;
        const unsigned* qr8 = qr0 + 8 * 32;
        #pragma unroll
        for (int ds = 0; ds < 4; ds++) {
            int off = (ds >> 1) * 16 + tig * 4 + (ds & 1) * 2;
            uint2 u0 = *reinterpret_cast<const uint2*>(qr0 + off);
            uint2 u8 = *reinterpret_cast<const uint2*>(qr8 + off);
            qa[rg][ds][0] = u0.x;
            qa[rg][ds][1] = u8.x;
            qa[rg][ds][2] = u0.y;
            qa[rg][ds][3] = u8.y;
        }
    }

    __half2 acc_o[2][8][2];
    #pragma unroll
    for (int rg = 0; rg < 2; rg++)
        #pragma unroll
        for (int i = 0; i < 8; i++) {
            acc_o[rg][i][0] = __float2half2_rn(0.f);
            acc_o[rg][i][1] = __float2half2_rn(0.f);
        }
    float row_m[2][2] = {{-1e30f, -1e30f}, {-1e30f, -1e30f}};
    float row_l[2][2] = {{0.f, 0.f}, {0.f, 0.f}};

    auto load_tiles = [&](int st, int kt) {
        unsigned kb = (unsigned)__cvta_generic_to_shared(dynsm + st * STG_WORDS);
        unsigned vb = kb + 64 * KVSTRIDE * 4;
        int j0 = kt * 64;
        #pragma unroll
        for (int h = 0; h < 4; h++) {
            int ca = t + h * 128;
            int row = ca >> 3, ch = ca & 7;
            cp16(kb + (row * KVSTRIDE + ch * 4) * 4, Kp + (size_t)(j0 + row) * HD + ch * 8);
            cp16(vb + (row * KVSTRIDE + ch * 4) * 4, Vp + (size_t)row * NHW + j0 + ch * 8);
        }
    };

    load_tiles(0, 0);
    asm volatile("cp.async.commit_group;");
    load_tiles(1, 1);
    asm volatile("cp.async.commit_group;");

    for (int kt = 0; kt < 16; kt++) {
        int st = kt % 3;
        const unsigned* kbuf = dynsm + st * STG_WORDS;
        const unsigned* vbuf = kbuf + 64 * KVSTRIDE;

        asm volatile("cp.async.wait_group 1;");
        __syncthreads();
        if (kt + 2 < 16) load_tiles((kt + 2) % 3, kt + 2);
        asm volatile("cp.async.commit_group;");

        // ---- S = Q K^T : one b-frag feeds BOTH row groups ----
        __half2 p[2][8][2];
        #pragma unroll
        for (int rg = 0; rg < 2; rg++)
            #pragma unroll
            for (int i = 0; i < 8; i++) {
                p[rg][i][0] = __float2half2_rn(0.f);
                p[rg][i][1] = __float2half2_rn(0.f);
            }

        #pragma unroll
        for (int dsp = 0; dsp < 2; dsp++) {
            #pragma unroll
            for (int nf = 0; nf < 8; nf++) {
                uint4 k4 = *reinterpret_cast<const uint4*>(
                    &kbuf[(nf * 8 + gid) * KVSTRIDE + dsp * 16 + tig * 4]);
                unsigned b0[2] = {k4.x, k4.y};
                unsigned b1[2] = {k4.z, k4.w};
                #pragma unroll
                for (int rg = 0; rg < 2; rg++) {
                    mma_h16(p[rg][nf], qa[rg][2 * dsp], b0);
                    mma_h16(p[rg][nf], qa[rg][2 * dsp + 1], b1);
                }
            }
        }

        // ---- packed-half2 online softmax (base 2), per row group ----
        #pragma unroll
        for (int rg = 0; rg < 2; rg++) {
            __half2 m0h = p[rg][0][0], m1h = p[rg][0][1];
            #pragma unroll
            for (int nf = 1; nf < 8; nf++) {
                m0h = __hmax2(m0h, p[rg][nf][0]);
                m1h = __hmax2(m1h, p[rg][nf][1]);
            }
            m0h = __hmax2(m0h, u2h(__shfl_xor_sync(~0u, h2u(m0h), 1)));
            m0h = __hmax2(m0h, u2h(__shfl_xor_sync(~0u, h2u(m0h), 2)));
            m1h = __hmax2(m1h, u2h(__shfl_xor_sync(~0u, h2u(m1h), 1)));
            m1h = __hmax2(m1h, u2h(__shfl_xor_sync(~0u, h2u(m1h), 2)));
            float tmax0 = fmaxf(__low2float(m0h), __high2float(m0h));
            float tmax1 = fmaxf(__low2float(m1h), __high2float(m1h));

            float nm0 = fmaxf(row_m[rg][0], tmax0);
            float nm1 = fmaxf(row_m[rg][1], tmax1);
            float corr0 = ex2f(row_m[rg][0] - nm0);
            float corr1 = ex2f(row_m[rg][1] - nm1);

            __half2 nmh0 = __float2half2_rn(nm0);
            __half2 nmh1 = __float2half2_rn(nm1);
            __half2 s0h = __float2half2_rn(0.f), s1h = __float2half2_rn(0.f);
            #pragma unroll
            for (int nf = 0; nf < 8; nf++) {
                p[rg][nf][0] = hex2(__hsub2(p[rg][nf][0], nmh0));
                p[rg][nf][1] = hex2(__hsub2(p[rg][nf][1], nmh1));
                s0h = __hadd2(s0h, p[rg][nf][0]);
                s1h = __hadd2(s1h, p[rg][nf][1]);
            }
            s0h = __hadd2(s0h, u2h(__shfl_xor_sync(~0u, h2u(s0h), 1)));
            s0h = __hadd2(s0h, u2h(__shfl_xor_sync(~0u, h2u(s0h), 2)));
            s1h = __hadd2(s1h, u2h(__shfl_xor_sync(~0u, h2u(s1h), 1)));
            s1h = __hadd2(s1h, u2h(__shfl_xor_sync(~0u, h2u(s1h), 2)));
            row_l[rg][0] = row_l[rg][0] * corr0 + __low2float(s0h) + __high2float(s0h);
            row_l[rg][1] = row_l[rg][1] * corr1 + __low2float(s1h) + __high2float(s1h);
            row_m[rg][0] = nm0; row_m[rg][1] = nm1;

            __half2 c0h = __float2half2_rn(corr0);
            __half2 c1h = __float2half2_rn(corr1);
            #pragma unroll
            for (int nf2 = 0; nf2 < 8; nf2++) {
                acc_o[rg][nf2][0] = __hmul2(acc_o[rg][nf2][0], c0h);
                acc_o[rg][nf2][1] = __hmul2(acc_o[rg][nf2][1], c1h);
            }
        }

        // ---- O += P V^T : one v-frag feeds BOTH row groups ----
        #pragma unroll
        for (int jsp = 0; jsp < 2; jsp++) {
            #pragma unroll
            for (int nf2 = 0; nf2 < 8; nf2++) {
                uint4 v4 = *reinterpret_cast<const uint4*>(
                    &vbuf[(nf2 * 8 + gid) * KVSTRIDE + jsp * 16 + tig * 4]);
                unsigned b0[2] = {v4.x, v4.y};
                unsigned b1[2] = {v4.z, v4.w};
                #pragma unroll
                for (int rg = 0; rg < 2; rg++) {
                    const unsigned* pa0 = reinterpret_cast<const unsigned*>(&p[rg][4 * jsp][0]);
                    const unsigned* pa1 = reinterpret_cast<const unsigned*>(&p[rg][4 * jsp + 2][0]);
                    mma_h16(acc_o[rg][nf2], pa0, b0);
                    mma_h16(acc_o[rg][nf2], pa1, b1);
                }
            }
        }
    }

    // ---- epilogue: O /= l, write f16x2 into g_hbf ----
    unsigned* Hb = g_hbf + ((size_t)b * (NC / 2) + r * (HD / 2)) * NHW;
    #pragma unroll
    for (int rg = 0; rg < 2; rg++) {
        int ib = qtile * 128 + i0w + rg * 16 + gid;
        __half2 i0h = __float2half2_rn(1.f / row_l[rg][0]);
        __half2 i1h = __float2half2_rn(1.f / row_l[rg][1]);
        #pragma unroll
        for (int nf2 = 0; nf2 < 8; nf2++) {
            int u = nf2 * 4 + tig;
            Hb[(size_t)u * NHW + ib]     = h2u(__hmul2(acc_o[rg][nf2][0], i0h));
            Hb[(size_t)u * NHW + ib + 8] = h2u(__hmul2(acc_o[rg][nf2][1], i1h));
        }
    }
}

// ============================================================
extern "C" void kernel_launch(void* const* d_in, const int* in_sizes, int n_in,
                              void* d_out, int out_size)
{
    const float* x      = (const float*)d_in[0];
    const float* gn_w   = (const float*)d_in[1];
    const float* gn_b   = (const float*)d_in[2];
    const float* qkv_w  = (const float*)d_in[3];
    const float* proj_w = (const float*)d_in[4];
    const float* proj_b = (const float*)d_in[5];
    float* out = (float*)d_out;

    cudaFuncSetAttribute(flash_kernel, cudaFuncAttributeMaxDynamicSharedMemorySize, FLASH_SMEM);
    cudaFuncSetAttribute(qkv_gemm, cudaFuncAttributeMaxDynamicSharedMemorySize, GEMM_SMEM);
    cudaFuncSetAttribute(proj_gemm, cudaFuncAttributeMaxDynamicSharedMemorySize, GEMM_SMEM);

    convw_kernel<<<2048, 256>>>(qkv_w, proj_w);
    gn_kernel<<<NB * NG, 256>>>(x, gn_w, gn_b);
    qkv_gemm<<<dim3(8, 12, NB), 256, GEMM_SMEM>>>();
    flash_kernel<<<NB * NHEADS * 8, 128, FLASH_SMEM>>>();
    proj_gemm<<<dim3(8, 4, NB), 256, GEMM_SMEM>>>(proj_b, x, out);
}